// round 7
// baseline (speedup 1.0000x reference)
#include <cuda_runtime.h>
#include <cstdint>
#include <cstddef>

// Problem constants
#define BB 4
#define TT 1024
#define CC 1024
#define HH 16
#define DH 64
#define FF 4096
#define MM (BB*TT)          // 4096 rows

// ---------------- scratch (device globals; no allocation allowed) ----------------
__device__ float g_q  [(size_t)MM*CC];
__device__ float g_vt [(size_t)MM*CC];         // V transposed per batch: [B][C][T]
__device__ float g_ctx[(size_t)MM*CC];
__device__ float g_o  [(size_t)MM*CC];
__device__ float g_x1 [(size_t)MM*CC];
__device__ float g_x2 [(size_t)MM*CC];
__device__ float g_ff [(size_t)MM*FF];         // 64 MB (also holds fused QKV / KV)
__device__ float g_xr [(size_t)MM*CC];         // tf32-rounded x
__device__ float g_er [(size_t)MM*CC];         // tf32-rounded enc
// transposed weights: 8 x [1024x1024] + Wf1^T [4096x1024] + Wf2^T [1024x4096]
__device__ float g_wt [8u*1024u*1024u + 2u*4096u*1024u];

// ============================ small helpers ======================================
__device__ __forceinline__ float to_tf32(float x) {
    uint32_t o;
    asm("cvt.rna.tf32.f32 %0, %1;" : "=r"(o) : "r"(__float_as_uint(x)));
    return __uint_as_float(o);
}
__device__ __forceinline__ void mma_tf32(float* d, const float* a, const float* b) {
    asm volatile(
        "mma.sync.aligned.m16n8k8.row.col.f32.tf32.tf32.f32 "
        "{%0,%1,%2,%3},{%4,%5,%6,%7},{%8,%9},{%0,%1,%2,%3};"
        : "+f"(d[0]), "+f"(d[1]), "+f"(d[2]), "+f"(d[3])
        : "r"(__float_as_uint(a[0])), "r"(__float_as_uint(a[1])),
          "r"(__float_as_uint(a[2])), "r"(__float_as_uint(a[3])),
          "r"(__float_as_uint(b[0])), "r"(__float_as_uint(b[1])));
}
__device__ __forceinline__ uint32_t smem_u32(const void* p) {
    uint32_t a;
    asm("{ .reg .u64 t; cvta.to.shared.u64 t, %1; cvt.u32.u64 %0, t; }" : "=r"(a) : "l"(p));
    return a;
}
__device__ __forceinline__ void cp16(uint32_t dst, const void* src) {
    asm volatile("cp.async.cg.shared.global [%0], [%1], 16;" :: "r"(dst), "l"(src));
}

// =================== tf32 rounding copy (2 tensors, z-batched) ===================
struct Ptr2 { const float* s[2]; float* d[2]; };
__global__ void __launch_bounds__(256)
round2(Ptr2 p)
{
    const float* in = p.s[blockIdx.y];
    float* out = p.d[blockIdx.y];
    const size_t i = ((size_t)blockIdx.x * 256 + threadIdx.x) * 4;
    float4 v = *(const float4*)(in + i);
    v.x = to_tf32(v.x); v.y = to_tf32(v.y); v.z = to_tf32(v.z); v.w = to_tf32(v.w);
    *(float4*)(out + i) = v;
}

// ====================== 32x32 tiled transposes (tf32-rounding) ===================
struct Ptr8 { const float* s[8]; float* d[8]; };

__global__ void __launch_bounds__(256)
transpose8(Ptr8 ps)   // 8 square [CC x CC] weights, z selects matrix
{
    const float* in = ps.s[blockIdx.z];
    float* out = ps.d[blockIdx.z];
    __shared__ float t[32][33];
    const int bx = blockIdx.x * 32, by = blockIdx.y * 32;
    int x = bx + threadIdx.x;
#pragma unroll
    for (int i = 0; i < 32; i += 8)
        t[threadIdx.y + i][threadIdx.x] = in[(size_t)(by + threadIdx.y + i) * CC + x];
    __syncthreads();
    x = by + threadIdx.x;
#pragma unroll
    for (int i = 0; i < 32; i += 8)
        out[(size_t)(bx + threadIdx.y + i) * CC + x] = to_tf32(t[threadIdx.x][threadIdx.y + i]);
}

__global__ void __launch_bounds__(256)
transpose_k(const float* __restrict__ in, float* __restrict__ out, int R, int C)
{
    __shared__ float t[32][33];
    const int bx = blockIdx.x * 32, by = blockIdx.y * 32;
    int x = bx + threadIdx.x;
#pragma unroll
    for (int i = 0; i < 32; i += 8)
        t[threadIdx.y + i][threadIdx.x] = in[(size_t)(by + threadIdx.y + i) * C + x];
    __syncthreads();
    x = by + threadIdx.x;
#pragma unroll
    for (int i = 0; i < 32; i += 8)
        out[(size_t)(bx + threadIdx.y + i) * R + x] = to_tf32(t[threadIdx.x][threadIdx.y + i]);
}

// extract + transpose V block out of a packed [B*T, ldin] buffer -> [B][C][T]
__global__ void __launch_bounds__(256)
transpose_v(const float* __restrict__ in, float* __restrict__ out, int ldin)
{
    in  += (size_t)blockIdx.z * TT * ldin;
    out += (size_t)blockIdx.z * CC * TT;
    __shared__ float t[32][33];
    const int bx = blockIdx.x * 32, by = blockIdx.y * 32;   // bx: C dim, by: T dim
#pragma unroll
    for (int i = 0; i < 32; i += 8)
        t[threadIdx.y + i][threadIdx.x] =
            in[(size_t)(by + threadIdx.y + i) * ldin + bx + threadIdx.x];
    __syncthreads();
#pragma unroll
    for (int i = 0; i < 32; i += 8)
        out[(size_t)(bx + threadIdx.y + i) * TT + by + threadIdx.x] =
            to_tf32(t[threadIdx.x][threadIdx.y + i]);
}

// ================= tf32 mma.sync GEMM: C[M,N] = A[M,K] @ Bt[N,K]^T ===============
// Inputs pre-rounded to tf32 (RNA). 128x128 CTA tile, 4 warps @ 64x64 each
// (WR=WC=2 -> smem traffic 8 MAC/byte), cp.async 3-stage, 2 CTAs/SM.
#define G_LDP 36
#define G_STG (256 * G_LDP)                 // floats per stage (A128 + B128 rows)
#define GSMEM (3 * G_STG * 4)               // 110592 bytes

template<bool BIAS, bool RELU, bool ROUND>
__global__ void __launch_bounds__(128, 2)
gemm_mma(const float* __restrict__ A, const float* __restrict__ Bt,
         const float* __restrict__ bias, float* __restrict__ C,
         int K, int lda, int ldb, int ldc)
{
    extern __shared__ float smf[];
    const int bxn = blockIdx.x * 128, bym = blockIdx.y * 128;
    const int tid = threadIdx.x, wid = tid >> 5, lane = tid & 31;
    const int wr = wid >> 1, wc = wid & 1;      // 2 x 2 warps, 64x64 each
    const int g = lane >> 2, qc = lane & 3;

    // staging: one thread per row (A row tid, B row tid), 32 floats each
    const float* Ag = A  + (size_t)(bym + tid) * lda;
    const float* Bg = Bt + (size_t)(bxn + tid) * ldb;
    const uint32_t adst = smem_u32(smf) + (uint32_t)(tid * G_LDP) * 4;
    const uint32_t bdst = adst + 128 * G_LDP * 4;

    float acc[4][8][4];
#pragma unroll
    for (int i = 0; i < 4; i++)
#pragma unroll
        for (int j = 0; j < 8; j++)
#pragma unroll
            for (int r = 0; r < 4; r++) acc[i][j][r] = 0.f;

    const int nst = K >> 5;

#pragma unroll
    for (int s = 0; s < 2; s++) {
        const float* as = Ag + s * 32;
        const float* bs = Bg + s * 32;
        const uint32_t ad = adst + s * G_STG * 4;
        const uint32_t bd = bdst + s * G_STG * 4;
#pragma unroll
        for (int j = 0; j < 8; j++) {
            cp16(ad + j * 16, as + j * 4);
            cp16(bd + j * 16, bs + j * 4);
        }
        asm volatile("cp.async.commit_group;" ::: "memory");
    }

    int buf = 0, nxt = 2;
    for (int it = 0; it < nst; ++it) {
        asm volatile("cp.async.wait_group 1;" ::: "memory");
        __syncthreads();
        const float* a_s = smf + buf * G_STG + (wr * 64 + g) * G_LDP;
        const float* b_s = smf + buf * G_STG + 128 * G_LDP + (wc * 64 + g) * G_LDP;
#pragma unroll
        for (int ks = 0; ks < 4; ks++) {
            float av_[4][4], bv_[8][2];
#pragma unroll
            for (int mi = 0; mi < 4; mi++) {
                const float* p = a_s + mi * 16 * G_LDP + ks * 8 + qc;
                av_[mi][0] = p[0];
                av_[mi][1] = p[8 * G_LDP];
                av_[mi][2] = p[4];
                av_[mi][3] = p[8 * G_LDP + 4];
            }
#pragma unroll
            for (int ni = 0; ni < 8; ni++) {
                const float* p = b_s + ni * 8 * G_LDP + ks * 8 + qc;
                bv_[ni][0] = p[0];
                bv_[ni][1] = p[4];
            }
#pragma unroll
            for (int mi = 0; mi < 4; mi++)
#pragma unroll
                for (int ni = 0; ni < 8; ni++)
                    mma_tf32(acc[mi][ni], av_[mi], bv_[ni]);
        }
        if (it + 2 < nst) {
            const int kt = it + 2;
            const float* as = Ag + kt * 32;
            const float* bs = Bg + kt * 32;
            const uint32_t ad = adst + nxt * G_STG * 4;
            const uint32_t bd = bdst + nxt * G_STG * 4;
#pragma unroll
            for (int j = 0; j < 8; j++) {
                cp16(ad + j * 16, as + j * 4);
                cp16(bd + j * 16, bs + j * 4);
            }
            asm volatile("cp.async.commit_group;" ::: "memory");
        }
        buf = (buf == 2) ? 0 : buf + 1;
        nxt = (nxt == 2) ? 0 : nxt + 1;
    }

#pragma unroll
    for (int mi = 0; mi < 4; mi++) {
        const int r = bym + wr * 64 + mi * 16 + g;
#pragma unroll
        for (int ni = 0; ni < 8; ni++) {
            const int col = bxn + wc * 64 + ni * 8 + qc * 2;
            float2 bv = make_float2(0.f, 0.f);
            if (BIAS) bv = *(const float2*)(bias + col);
            float2 v0, v1;
            v0.x = acc[mi][ni][0] + bv.x;
            v0.y = acc[mi][ni][1] + bv.y;
            v1.x = acc[mi][ni][2] + bv.x;
            v1.y = acc[mi][ni][3] + bv.y;
            if (RELU) {
                v0.x = fmaxf(v0.x, 0.f); v0.y = fmaxf(v0.y, 0.f);
                v1.x = fmaxf(v1.x, 0.f); v1.y = fmaxf(v1.y, 0.f);
            }
            if (ROUND) {
                v0.x = to_tf32(v0.x); v0.y = to_tf32(v0.y);
                v1.x = to_tf32(v1.x); v1.y = to_tf32(v1.y);
            }
            *(float2*)(C + (size_t)r * ldc + col)       = v0;
            *(float2*)(C + (size_t)(r + 8) * ldc + col) = v1;
        }
    }
}

// ====================== flash attention (tf32 mma, online softmax) ===============
#define FL_SQ  0
#define FL_SK  8704           // floats
#define FL_SV  26112
#define FL_MSK 43008
#define FSMEM  ((43008 + 66) * 4)

template<bool CAUSAL>
__global__ void __launch_bounds__(256, 1)
flash_k(const float* __restrict__ Qg, const float* __restrict__ Kg,
        const float* __restrict__ Vg, const unsigned char* __restrict__ padg,
        float* __restrict__ Og, int ldq, int ldk)
{
    extern __shared__ float sm[];
    const int tid = threadIdx.x, lane = tid & 31, w = tid >> 5;
    const int g = lane >> 2, qc = lane & 3;
    const int qt = blockIdx.x;
    const int z = blockIdx.y, b = z >> 4, h = z & 15;

    const float* Qp = Qg + (size_t)b * TT * ldq + h * 64;
    const float* Kp = Kg + (size_t)b * TT * ldk + h * 64;
    const float* Vp = Vg + ((size_t)b * CC + h * 64) * TT;
    const unsigned char* padp = padg + (size_t)b * TT;
    float* Op = Og + (size_t)b * TT * CC + h * 64;

    const uint32_t sQa = smem_u32(sm);
    const uint32_t sKa = sQa + FL_SK * 4;
    const uint32_t sVa = sQa + FL_SV * 4;
    uint32_t* sMskp = (uint32_t*)(sm + FL_MSK);

    const int nkt = CAUSAL ? qt + 1 : (TT / 128);

    {
        const float* qs = Qp + (size_t)(qt * 128 + (tid >> 1)) * ldq + (tid & 1) * 32;
        uint32_t qd = sQa + (tid >> 1) * 272 + (tid & 1) * 128;
#pragma unroll
        for (int j = 0; j < 8; j++) cp16(qd + j * 16, qs + j * 4);
    }
    auto issue_kv = [&](int kt, int buf) {
        const float* ks = Kp + (size_t)(kt * 128 + (tid >> 1)) * ldk + (tid & 1) * 32;
        uint32_t kd = sKa + buf * 34816u + (tid >> 1) * 272 + (tid & 1) * 128;
#pragma unroll
        for (int j = 0; j < 8; j++) cp16(kd + j * 16, ks + j * 4);
        const float* vs = Vp + (size_t)(tid >> 2) * TT + kt * 128 + (tid & 3) * 32;
        uint32_t vd = sVa + buf * 33792u + (tid >> 2) * 528 + (tid & 3) * 128;
#pragma unroll
        for (int j = 0; j < 8; j++) cp16(vd + j * 16, vs + j * 4);
        if (tid < 32) {
            uint32_t mv = *(const uint32_t*)(padp + (size_t)kt * 128 + tid * 4);
            sMskp[buf * 32 + tid] = mv;
            uint32_t f = __reduce_or_sync(0xffffffffu, mv);
            if (tid == 0) sMskp[64 + buf] = f;
        }
    };
    issue_kv(0, 0);
    asm volatile("cp.async.commit_group;" ::: "memory");

    float m0 = -INFINITY, m1 = -INFINITY, l0 = 0.f, l1 = 0.f;
    float oacc[8][4];
#pragma unroll
    for (int j = 0; j < 8; j++)
#pragma unroll
        for (int r = 0; r < 4; r++) oacc[j][r] = 0.f;

    const int r0 = w * 16 + g, r1 = r0 + 8;
    const int s0l = (lane & ~3) | (qc >> 1), s1l = s0l + 2;
    const bool odd = (qc & 1) != 0;

    for (int kt = 0; kt < nkt; ++kt) {
        const int buf = kt & 1;
        if (kt + 1 < nkt) {
            issue_kv(kt + 1, buf ^ 1);
            asm volatile("cp.async.commit_group;" ::: "memory");
            asm volatile("cp.async.wait_group 1;" ::: "memory");
        } else {
            asm volatile("cp.async.wait_group 0;" ::: "memory");
        }
        __syncthreads();

        float aq[8][4];
        {
            const float* qr = sm + (size_t)(w * 16 + g) * 68;
#pragma unroll
            for (int ks = 0; ks < 8; ks++) {
                aq[ks][0] = qr[ks * 8 + qc];
                aq[ks][1] = qr[8 * 68 + ks * 8 + qc];
                aq[ks][2] = qr[ks * 8 + qc + 4];
                aq[ks][3] = qr[8 * 68 + ks * 8 + qc + 4];
            }
        }
        float sacc[16][4];
#pragma unroll
        for (int ni = 0; ni < 16; ni++)
#pragma unroll
            for (int r = 0; r < 4; r++) sacc[ni][r] = 0.f;
        {
            const float* kb = sm + FL_SK + buf * 8704;
#pragma unroll
            for (int ks = 0; ks < 8; ks++)
#pragma unroll
                for (int ni = 0; ni < 16; ni++) {
                    const float* kr = kb + (ni * 8 + g) * 68 + ks * 8;
                    float bv[2] = { kr[qc], kr[qc + 4] };
                    mma_tf32(sacc[ni], aq[ks], bv);
                }
        }

        const uint32_t pf = sMskp[64 + buf];
        const unsigned char* mb = (const unsigned char*)(sMskp + buf * 32);
        float tm0 = -INFINITY, tm1 = -INFINITY;
#pragma unroll
        for (int ni = 0; ni < 16; ni++) {
            float s0 = sacc[ni][0] * 0.125f, s1 = sacc[ni][1] * 0.125f;
            float s2 = sacc[ni][2] * 0.125f, s3 = sacc[ni][3] * 0.125f;
            const int c0 = ni * 8 + qc * 2;
            if (CAUSAL && kt == qt) {
                if (c0     > r0) s0 = -INFINITY;
                if (c0 + 1 > r0) s1 = -INFINITY;
                if (c0     > r1) s2 = -INFINITY;
                if (c0 + 1 > r1) s3 = -INFINITY;
            }
            if (pf) {
                if (mb[c0])     { s0 = -INFINITY; s2 = -INFINITY; }
                if (mb[c0 + 1]) { s1 = -INFINITY; s3 = -INFINITY; }
            }
            sacc[ni][0] = s0; sacc[ni][1] = s1; sacc[ni][2] = s2; sacc[ni][3] = s3;
            tm0 = fmaxf(tm0, fmaxf(s0, s1));
            tm1 = fmaxf(tm1, fmaxf(s2, s3));
        }
        tm0 = fmaxf(tm0, __shfl_xor_sync(0xffffffffu, tm0, 1));
        tm0 = fmaxf(tm0, __shfl_xor_sync(0xffffffffu, tm0, 2));
        tm1 = fmaxf(tm1, __shfl_xor_sync(0xffffffffu, tm1, 1));
        tm1 = fmaxf(tm1, __shfl_xor_sync(0xffffffffu, tm1, 2));
        const float mn0 = fmaxf(m0, tm0), mn1 = fmaxf(m1, tm1);

        float sum0 = 0.f, sum1 = 0.f;
#pragma unroll
        for (int ni = 0; ni < 16; ni++) {
            float p0 = __expf(sacc[ni][0] - mn0);
            float p1 = __expf(sacc[ni][1] - mn0);
            float p2 = __expf(sacc[ni][2] - mn1);
            float p3 = __expf(sacc[ni][3] - mn1);
            sacc[ni][0] = p0; sacc[ni][1] = p1; sacc[ni][2] = p2; sacc[ni][3] = p3;
            sum0 += p0 + p1; sum1 += p2 + p3;
        }
        sum0 += __shfl_xor_sync(0xffffffffu, sum0, 1);
        sum0 += __shfl_xor_sync(0xffffffffu, sum0, 2);
        sum1 += __shfl_xor_sync(0xffffffffu, sum1, 1);
        sum1 += __shfl_xor_sync(0xffffffffu, sum1, 2);

        const float sc0 = __expf(m0 - mn0), sc1 = __expf(m1 - mn1);
        l0 = l0 * sc0 + sum0;  l1 = l1 * sc1 + sum1;
        m0 = mn0;  m1 = mn1;
#pragma unroll
        for (int nj = 0; nj < 8; nj++) {
            oacc[nj][0] *= sc0; oacc[nj][1] *= sc0;
            oacc[nj][2] *= sc1; oacc[nj][3] *= sc1;
        }

        {
            const float* vb = sm + FL_SV + buf * 8448;
#pragma unroll
            for (int k2 = 0; k2 < 16; k2++) {
                float v00 = __shfl_sync(0xffffffffu, sacc[k2][0], s0l);
                float v01 = __shfl_sync(0xffffffffu, sacc[k2][1], s0l);
                float v20 = __shfl_sync(0xffffffffu, sacc[k2][2], s0l);
                float v21 = __shfl_sync(0xffffffffu, sacc[k2][3], s0l);
                float w00 = __shfl_sync(0xffffffffu, sacc[k2][0], s1l);
                float w01 = __shfl_sync(0xffffffffu, sacc[k2][1], s1l);
                float w20 = __shfl_sync(0xffffffffu, sacc[k2][2], s1l);
                float w21 = __shfl_sync(0xffffffffu, sacc[k2][3], s1l);
                float pa[4];
                pa[0] = to_tf32(odd ? v01 : v00);
                pa[1] = to_tf32(odd ? v21 : v20);
                pa[2] = to_tf32(odd ? w01 : w00);
                pa[3] = to_tf32(odd ? w21 : w20);
#pragma unroll
                for (int nj = 0; nj < 8; nj++) {
                    const float* vr = vb + (nj * 8 + g) * 132 + k2 * 8;
                    float bv[2] = { vr[qc], vr[qc + 4] };
                    mma_tf32(oacc[nj], pa, bv);
                }
            }
        }
        __syncthreads();
    }

    const float inv0 = 1.f / l0, inv1 = 1.f / l1;
    float* orow0 = Op + (size_t)(qt * 128 + r0) * CC;
    float* orow1 = orow0 + 8 * CC;
#pragma unroll
    for (int nj = 0; nj < 8; nj++) {
        *(float2*)(orow0 + nj * 8 + qc * 2) =
            make_float2(to_tf32(oacc[nj][0] * inv0), to_tf32(oacc[nj][1] * inv0));
        *(float2*)(orow1 + nj * 8 + qc * 2) =
            make_float2(to_tf32(oacc[nj][2] * inv1), to_tf32(oacc[nj][3] * inv1));
    }
}

// ============================ layernorm ==========================================
__device__ __forceinline__ float warpSum(float v) {
#pragma unroll
    for (int o = 16; o; o >>= 1) v += __shfl_xor_sync(0xffffffffu, v, o);
    return v;
}

template<bool ROUND>
__global__ void __launch_bounds__(256)
add_ln(const float* __restrict__ X, const float* __restrict__ R,
       const float* __restrict__ g, const float* __restrict__ be,
       float* __restrict__ out)
{
    const size_t row = blockIdx.x;
    const int tid = threadIdx.x;
    const int col = tid * 4;
    float4 xv = *(const float4*)(X + row * CC + col);
    float4 rv = *(const float4*)(R + row * CC + col);
    float4 v;
    v.x = xv.x + rv.x; v.y = xv.y + rv.y; v.z = xv.z + rv.z; v.w = xv.w + rv.w;

    __shared__ float sh1[8], sh2[8];
    float s = (v.x + v.y) + (v.z + v.w);
    float sq = v.x * v.x + v.y * v.y + v.z * v.z + v.w * v.w;
    s = warpSum(s); sq = warpSum(sq);
    if ((tid & 31) == 0) { sh1[tid >> 5] = s; sh2[tid >> 5] = sq; }
    __syncthreads();
    s  = (sh1[0] + sh1[1]) + (sh1[2] + sh1[3]) + (sh1[4] + sh1[5]) + (sh1[6] + sh1[7]);
    sq = (sh2[0] + sh2[1]) + (sh2[2] + sh2[3]) + (sh2[4] + sh2[5]) + (sh2[6] + sh2[7]);
    const float mean = s * (1.0f / CC);
    const float var = sq * (1.0f / CC) - mean * mean;
    const float rstd = rsqrtf(var + 1e-5f);

    float4 gg = *(const float4*)(g + col);
    float4 bb = *(const float4*)(be + col);
    float4 o;
    o.x = (v.x - mean) * rstd * gg.x + bb.x;
    o.y = (v.y - mean) * rstd * gg.y + bb.y;
    o.z = (v.z - mean) * rstd * gg.z + bb.z;
    o.w = (v.w - mean) * rstd * gg.w + bb.w;
    if (ROUND) {
        o.x = to_tf32(o.x); o.y = to_tf32(o.y);
        o.z = to_tf32(o.z); o.w = to_tf32(o.w);
    }
    *(float4*)(out + row * CC + col) = o;
}

// ------------------------------- launcher ---------------------------------------
extern "C" void kernel_launch(void* const* d_in, const int* in_sizes, int n_in,
                              void* d_out, int out_size)
{
    const float* x    = (const float*)d_in[0];
    const float* enc  = (const float*)d_in[1];
    const unsigned char* tmask = (const unsigned char*)d_in[2];
    const unsigned char* smask = (const unsigned char*)d_in[3];
    const float* Wq1 = (const float*)d_in[4];
    const float* Wk1 = (const float*)d_in[5];
    const float* Wv1 = (const float*)d_in[6];
    const float* Wo1 = (const float*)d_in[7];
    const float* ln1g = (const float*)d_in[8];
    const float* ln1b = (const float*)d_in[9];
    const float* Wq2 = (const float*)d_in[10];
    const float* Wk2 = (const float*)d_in[11];
    const float* Wv2 = (const float*)d_in[12];
    const float* Wo2 = (const float*)d_in[13];
    const float* ln2g = (const float*)d_in[14];
    const float* ln2b = (const float*)d_in[15];
    const float* Wf1 = (const float*)d_in[16];
    const float* bf1 = (const float*)d_in[17];
    const float* Wf2 = (const float*)d_in[18];
    const float* bf2 = (const float*)d_in[19];
    const float* ln3g = (const float*)d_in[20];
    const float* ln3b = (const float*)d_in[21];
    float* out = (float*)d_out;

    float *gq, *gvt, *gctx, *go, *gx1, *gx2, *gff, *gxr, *ger, *gwt;
    cudaGetSymbolAddress((void**)&gq,  g_q);
    cudaGetSymbolAddress((void**)&gvt, g_vt);
    cudaGetSymbolAddress((void**)&gctx, g_ctx);
    cudaGetSymbolAddress((void**)&go,  g_o);
    cudaGetSymbolAddress((void**)&gx1, g_x1);
    cudaGetSymbolAddress((void**)&gx2, g_x2);
    cudaGetSymbolAddress((void**)&gff, g_ff);
    cudaGetSymbolAddress((void**)&gxr, g_xr);
    cudaGetSymbolAddress((void**)&ger, g_er);
    cudaGetSymbolAddress((void**)&gwt, g_wt);

    float* tq1 = gwt + 0u * 1048576u;    // tq1,tk1,tv1 contiguous -> [3072,1024]
    float* tk1 = gwt + 1u * 1048576u;
    float* tv1 = gwt + 2u * 1048576u;
    float* to1 = gwt + 3u * 1048576u;
    float* tq2 = gwt + 4u * 1048576u;
    float* tk2 = gwt + 5u * 1048576u;    // tk2,tv2 contiguous -> [2048,1024]
    float* tv2 = gwt + 6u * 1048576u;
    float* to2 = gwt + 7u * 1048576u;
    float* tf1 = gwt + 8u * 1048576u;               // [F, C]
    float* tf2 = gwt + 8u * 1048576u + 4194304u;    // [C, F]

    auto* kProj  = gemm_mma<false, false, false>;   // plain (out -> add_ln / flash)
    auto* kProjR = gemm_mma<false, false, true >;   // rounded out (out -> GEMM A)
    auto* kFfn1  = gemm_mma<true,  true,  true >;   // bias+relu+rounded (-> FFN2 A)
    auto* kFfn2  = gemm_mma<true,  false, false>;
    cudaFuncSetAttribute(kProj,  cudaFuncAttributeMaxDynamicSharedMemorySize, GSMEM);
    cudaFuncSetAttribute(kProjR, cudaFuncAttributeMaxDynamicSharedMemorySize, GSMEM);
    cudaFuncSetAttribute(kFfn1,  cudaFuncAttributeMaxDynamicSharedMemorySize, GSMEM);
    cudaFuncSetAttribute(kFfn2,  cudaFuncAttributeMaxDynamicSharedMemorySize, GSMEM);
    cudaFuncSetAttribute(flash_k<true>,  cudaFuncAttributeMaxDynamicSharedMemorySize, FSMEM);
    cudaFuncSetAttribute(flash_k<false>, cudaFuncAttributeMaxDynamicSharedMemorySize, FSMEM);

    const dim3 blk(256);
    const dim3 gblk(128);                // gemm CTAs are 128 threads now
    const dim3 tblk(32, 8);

    // ---- producer-side tf32 rounding of external GEMM A inputs (1 launch) ----
    Ptr2 p2;
    p2.s[0] = x;   p2.d[0] = gxr;
    p2.s[1] = enc; p2.d[1] = ger;
    round2<<<dim3(MM * CC / 1024, 2), blk>>>(p2);

    // ---- square weight transposes (1 launch); Wf transposes deferred to FFN ----
    Ptr8 p8;
    p8.s[0] = Wq1; p8.d[0] = tq1;  p8.s[1] = Wk1; p8.d[1] = tk1;
    p8.s[2] = Wv1; p8.d[2] = tv1;  p8.s[3] = Wo1; p8.d[3] = to1;
    p8.s[4] = Wq2; p8.d[4] = tq2;  p8.s[5] = Wk2; p8.d[5] = tk2;
    p8.s[6] = Wv2; p8.d[6] = tv2;  p8.s[7] = Wo2; p8.d[7] = to2;
    transpose8<<<dim3(CC/32, CC/32, 8), tblk>>>(p8);

    const dim3 gQKV(3072/128, MM/128);   // (24, 32) fused self QKV
    const dim3 gKV (2048/128, MM/128);   // (16, 32) fused cross KV
    const dim3 gP  (CC/128,   MM/128);   // (8, 32)
    const dim3 gF1 (FF/128,   MM/128);   // (32, 32)
    const dim3 gFl (TT/128, BB*HH);      // (8, 64)
    const dim3 gVt (CC/32, TT/32, BB);
    const int nLn = MM;

    // ---- self-attention (causal) ----
    kProj<<<gQKV, gblk, GSMEM>>>(gxr, tq1, nullptr, gff, CC, CC, CC, 3072);
    transpose_v<<<gVt, tblk>>>(gff + 2048, gvt, 3072);
    flash_k<true><<<gFl, blk, FSMEM>>>(gff, gff + 1024, gvt, tmask, gctx, 3072, 3072);
    kProj<<<gP, gblk, GSMEM>>>(gctx, to1, nullptr, go, CC, CC, CC, CC);
    add_ln<true><<<nLn, blk>>>(x, go, ln1g, ln1b, gx1);

    // ---- cross-attention ----
    kProjR<<<gP,  gblk, GSMEM>>>(gx1, tq2, nullptr, gq, CC, CC, CC, CC);
    kProj <<<gKV, gblk, GSMEM>>>(ger, tk2, nullptr, gff, CC, CC, CC, 2048);
    transpose_v<<<gVt, tblk>>>(gff + 1024, gvt, 2048);
    flash_k<false><<<gFl, blk, FSMEM>>>(gq, gff, gvt, smask, gctx, CC, 2048);
    kProj<<<gP, gblk, GSMEM>>>(gctx, to2, nullptr, go, CC, CC, CC, CC);
    add_ln<true><<<nLn, blk>>>(gx1, go, ln2g, ln2b, gx2);

    // ---- FFN (Wf transposes deferred to here) ----
    transpose_k<<<dim3(FF/32, CC/32), tblk>>>(Wf1, tf1, CC, FF);
    transpose_k<<<dim3(CC/32, FF/32), tblk>>>(Wf2, tf2, FF, CC);
    kFfn1<<<gF1, gblk, GSMEM>>>(gx2, tf1, bf1, gff, CC, CC, CC, FF);
    kFfn2<<<gP,  gblk, GSMEM>>>(gff, tf2, bf2, go, FF, FF, FF, CC);
    add_ln<false><<<nLn, blk>>>(gx2, go, ln3g, ln3b, out);
}

// round 8
// speedup vs baseline: 1.0697x; 1.0697x over previous
#include <cuda_runtime.h>
#include <cstdint>
#include <cstddef>

// Problem constants
#define BB 4
#define TT 1024
#define CC 1024
#define HH 16
#define DH 64
#define FF 4096
#define MM (BB*TT)          // 4096 rows

// ---------------- scratch (device globals; no allocation allowed) ----------------
__device__ float g_q  [(size_t)MM*CC];
__device__ float g_vt [(size_t)MM*CC];         // V transposed per batch: [B][C][T]
__device__ float g_ctx[(size_t)MM*CC];
__device__ float g_o  [(size_t)MM*CC];
__device__ float g_x1 [(size_t)MM*CC];
__device__ float g_x2 [(size_t)MM*CC];
__device__ float g_ff [(size_t)MM*FF];         // 64 MB (also holds fused QKV / KV)
__device__ float g_xr [(size_t)MM*CC];         // tf32-rounded x
__device__ float g_er [(size_t)MM*CC];         // tf32-rounded enc
// transposed weights: 8 x [1024x1024] + Wf1^T [4096x1024] + Wf2^T [1024x4096]
__device__ float g_wt [8u*1024u*1024u + 2u*4096u*1024u];

// ============================ small helpers ======================================
__device__ __forceinline__ float to_tf32(float x) {
    uint32_t o;
    asm("cvt.rna.tf32.f32 %0, %1;" : "=r"(o) : "r"(__float_as_uint(x)));
    return __uint_as_float(o);
}
__device__ __forceinline__ void mma_tf32(float* d, const float* a, const float* b) {
    asm volatile(
        "mma.sync.aligned.m16n8k8.row.col.f32.tf32.tf32.f32 "
        "{%0,%1,%2,%3},{%4,%5,%6,%7},{%8,%9},{%0,%1,%2,%3};"
        : "+f"(d[0]), "+f"(d[1]), "+f"(d[2]), "+f"(d[3])
        : "r"(__float_as_uint(a[0])), "r"(__float_as_uint(a[1])),
          "r"(__float_as_uint(a[2])), "r"(__float_as_uint(a[3])),
          "r"(__float_as_uint(b[0])), "r"(__float_as_uint(b[1])));
}
__device__ __forceinline__ uint32_t smem_u32(const void* p) {
    uint32_t a;
    asm("{ .reg .u64 t; cvta.to.shared.u64 t, %1; cvt.u32.u64 %0, t; }" : "=r"(a) : "l"(p));
    return a;
}
__device__ __forceinline__ void cp16(uint32_t dst, const void* src) {
    asm volatile("cp.async.cg.shared.global [%0], [%1], 16;" :: "r"(dst), "l"(src));
}

// =================== tf32 rounding copy (2 tensors, z-batched) ===================
struct Ptr2 { const float* s[2]; float* d[2]; };
__global__ void __launch_bounds__(256)
round2(Ptr2 p)
{
    const float* in = p.s[blockIdx.y];
    float* out = p.d[blockIdx.y];
    const size_t i = ((size_t)blockIdx.x * 256 + threadIdx.x) * 4;
    float4 v = *(const float4*)(in + i);
    v.x = to_tf32(v.x); v.y = to_tf32(v.y); v.z = to_tf32(v.z); v.w = to_tf32(v.w);
    *(float4*)(out + i) = v;
}

// ====================== 32x32 tiled transposes (tf32-rounding) ===================
struct Ptr8 { const float* s[8]; float* d[8]; };

__global__ void __launch_bounds__(256)
transpose8(Ptr8 ps)   // 8 square [CC x CC] weights, z selects matrix
{
    const float* in = ps.s[blockIdx.z];
    float* out = ps.d[blockIdx.z];
    __shared__ float t[32][33];
    const int bx = blockIdx.x * 32, by = blockIdx.y * 32;
    int x = bx + threadIdx.x;
#pragma unroll
    for (int i = 0; i < 32; i += 8)
        t[threadIdx.y + i][threadIdx.x] = in[(size_t)(by + threadIdx.y + i) * CC + x];
    __syncthreads();
    x = by + threadIdx.x;
#pragma unroll
    for (int i = 0; i < 32; i += 8)
        out[(size_t)(bx + threadIdx.y + i) * CC + x] = to_tf32(t[threadIdx.x][threadIdx.y + i]);
}

__global__ void __launch_bounds__(256)
transpose_k(const float* __restrict__ in, float* __restrict__ out, int R, int C)
{
    __shared__ float t[32][33];
    const int bx = blockIdx.x * 32, by = blockIdx.y * 32;
    int x = bx + threadIdx.x;
#pragma unroll
    for (int i = 0; i < 32; i += 8)
        t[threadIdx.y + i][threadIdx.x] = in[(size_t)(by + threadIdx.y + i) * C + x];
    __syncthreads();
    x = by + threadIdx.x;
#pragma unroll
    for (int i = 0; i < 32; i += 8)
        out[(size_t)(bx + threadIdx.y + i) * R + x] = to_tf32(t[threadIdx.x][threadIdx.y + i]);
}

// extract + transpose V block out of a packed [B*T, ldin] buffer -> [B][C][T]
__global__ void __launch_bounds__(256)
transpose_v(const float* __restrict__ in, float* __restrict__ out, int ldin)
{
    in  += (size_t)blockIdx.z * TT * ldin;
    out += (size_t)blockIdx.z * CC * TT;
    __shared__ float t[32][33];
    const int bx = blockIdx.x * 32, by = blockIdx.y * 32;   // bx: C dim, by: T dim
#pragma unroll
    for (int i = 0; i < 32; i += 8)
        t[threadIdx.y + i][threadIdx.x] =
            in[(size_t)(by + threadIdx.y + i) * ldin + bx + threadIdx.x];
    __syncthreads();
#pragma unroll
    for (int i = 0; i < 32; i += 8)
        out[(size_t)(bx + threadIdx.y + i) * TT + by + threadIdx.x] =
            to_tf32(t[threadIdx.x][threadIdx.y + i]);
}

// ================= tf32 mma.sync GEMM: C[M,N] = A[M,K] @ Bt[N,K]^T ===============
// Inputs pre-rounded to tf32 (RNA). 128x128 CTA tile, 8 warps (2x4, 64x32 each),
// cp.async 3-stage (next-stage issue moved BEFORE compute), 2 CTAs/SM.
#define G_LDP 36
#define G_STG (256 * G_LDP)                 // floats per stage (A128 + B128 rows)
#define GSMEM (3 * G_STG * 4)               // 110592 bytes

template<bool BIAS, bool RELU, bool ROUND>
__global__ void __launch_bounds__(256, 2)
gemm_mma(const float* __restrict__ A, const float* __restrict__ Bt,
         const float* __restrict__ bias, float* __restrict__ C,
         int K, int lda, int ldb, int ldc)
{
    extern __shared__ float smf[];
    const int bxn = blockIdx.x * 128, bym = blockIdx.y * 128;
    const int tid = threadIdx.x, wid = tid >> 5, lane = tid & 31;
    const int wr = wid >> 2, wc = wid & 3;      // 2 x 4 warps, 64x32 each
    const int g = lane >> 2, qc = lane & 3;

    const int row = tid >> 1, colb = (tid & 1) * 16;
    const float* Ag = A  + (size_t)(bym + row) * lda + colb;
    const float* Bg = Bt + (size_t)(bxn + row) * ldb + colb;
    const uint32_t adst = smem_u32(smf) + (uint32_t)(row * G_LDP + colb) * 4;
    const uint32_t bdst = adst + 128 * G_LDP * 4;

    float acc[4][4][4];
#pragma unroll
    for (int i = 0; i < 4; i++)
#pragma unroll
        for (int j = 0; j < 4; j++)
#pragma unroll
            for (int r = 0; r < 4; r++) acc[i][j][r] = 0.f;

    const int nst = K >> 5;

    // prologue: stages 0, 1
#pragma unroll
    for (int s = 0; s < 2; s++) {
        const float* as = Ag + s * 32;
        const float* bs = Bg + s * 32;
        const uint32_t ad = adst + s * G_STG * 4;
        const uint32_t bd = bdst + s * G_STG * 4;
#pragma unroll
        for (int j = 0; j < 4; j++) {
            cp16(ad + j * 16, as + j * 4);
            cp16(bd + j * 16, bs + j * 4);
        }
        asm volatile("cp.async.commit_group;" ::: "memory");
    }

    int buf = 0, nxt = 2;      // nxt = (it+2) % 3
    for (int it = 0; it < nst; ++it) {
        asm volatile("cp.async.wait_group 1;" ::: "memory");
        __syncthreads();

        // issue next stage FIRST — ~2 stages of MMA to hide the loads under
        if (it + 2 < nst) {
            const int kt = it + 2;
            const float* as = Ag + kt * 32;
            const float* bs = Bg + kt * 32;
            const uint32_t ad = adst + nxt * G_STG * 4;
            const uint32_t bd = bdst + nxt * G_STG * 4;
#pragma unroll
            for (int j = 0; j < 4; j++) {
                cp16(ad + j * 16, as + j * 4);
                cp16(bd + j * 16, bs + j * 4);
            }
            asm volatile("cp.async.commit_group;" ::: "memory");
        }

        const float* a_s = smf + buf * G_STG + (wr * 64 + g) * G_LDP;
        const float* b_s = smf + buf * G_STG + 128 * G_LDP + (wc * 32 + g) * G_LDP;
#pragma unroll
        for (int ks = 0; ks < 4; ks++) {
            float av_[4][4], bv_[4][2];
#pragma unroll
            for (int mi = 0; mi < 4; mi++) {
                const float* p = a_s + mi * 16 * G_LDP + ks * 8 + qc;
                av_[mi][0] = p[0];
                av_[mi][1] = p[8 * G_LDP];
                av_[mi][2] = p[4];
                av_[mi][3] = p[8 * G_LDP + 4];
            }
#pragma unroll
            for (int ni = 0; ni < 4; ni++) {
                const float* p = b_s + ni * 8 * G_LDP + ks * 8 + qc;
                bv_[ni][0] = p[0];
                bv_[ni][1] = p[4];
            }
#pragma unroll
            for (int mi = 0; mi < 4; mi++)
#pragma unroll
                for (int ni = 0; ni < 4; ni++)
                    mma_tf32(acc[mi][ni], av_[mi], bv_[ni]);
        }
        buf = (buf == 2) ? 0 : buf + 1;
        nxt = (nxt == 2) ? 0 : nxt + 1;
    }

#pragma unroll
    for (int mi = 0; mi < 4; mi++) {
        const int r = bym + wr * 64 + mi * 16 + g;
#pragma unroll
        for (int ni = 0; ni < 4; ni++) {
            const int col = bxn + wc * 32 + ni * 8 + qc * 2;
            float2 bv = make_float2(0.f, 0.f);
            if (BIAS) bv = *(const float2*)(bias + col);
            float2 v0, v1;
            v0.x = acc[mi][ni][0] + bv.x;
            v0.y = acc[mi][ni][1] + bv.y;
            v1.x = acc[mi][ni][2] + bv.x;
            v1.y = acc[mi][ni][3] + bv.y;
            if (RELU) {
                v0.x = fmaxf(v0.x, 0.f); v0.y = fmaxf(v0.y, 0.f);
                v1.x = fmaxf(v1.x, 0.f); v1.y = fmaxf(v1.y, 0.f);
            }
            if (ROUND) {
                v0.x = to_tf32(v0.x); v0.y = to_tf32(v0.y);
                v1.x = to_tf32(v1.x); v1.y = to_tf32(v1.y);
            }
            *(float2*)(C + (size_t)r * ldc + col)       = v0;
            *(float2*)(C + (size_t)(r + 8) * ldc + col) = v1;
        }
    }
}

// ====================== flash attention (tf32 mma, online softmax) ===============
#define FL_SQ  0
#define FL_SK  8704           // floats
#define FL_SV  26112
#define FL_MSK 43008
#define FSMEM  ((43008 + 66) * 4)

template<bool CAUSAL>
__global__ void __launch_bounds__(256, 1)
flash_k(const float* __restrict__ Qg, const float* __restrict__ Kg,
        const float* __restrict__ Vg, const unsigned char* __restrict__ padg,
        float* __restrict__ Og, int ldq, int ldk)
{
    extern __shared__ float sm[];
    const int tid = threadIdx.x, lane = tid & 31, w = tid >> 5;
    const int g = lane >> 2, qc = lane & 3;
    // causal: longest q-tiles first (better tail packing across waves)
    const int qt = CAUSAL ? ((int)gridDim.x - 1 - (int)blockIdx.x) : (int)blockIdx.x;
    const int z = blockIdx.y, b = z >> 4, h = z & 15;

    const float* Qp = Qg + (size_t)b * TT * ldq + h * 64;
    const float* Kp = Kg + (size_t)b * TT * ldk + h * 64;
    const float* Vp = Vg + ((size_t)b * CC + h * 64) * TT;
    const unsigned char* padp = padg + (size_t)b * TT;
    float* Op = Og + (size_t)b * TT * CC + h * 64;

    const uint32_t sQa = smem_u32(sm);
    const uint32_t sKa = sQa + FL_SK * 4;
    const uint32_t sVa = sQa + FL_SV * 4;
    uint32_t* sMskp = (uint32_t*)(sm + FL_MSK);

    const int nkt = CAUSAL ? qt + 1 : (TT / 128);

    {
        const float* qs = Qp + (size_t)(qt * 128 + (tid >> 1)) * ldq + (tid & 1) * 32;
        uint32_t qd = sQa + (tid >> 1) * 272 + (tid & 1) * 128;
#pragma unroll
        for (int j = 0; j < 8; j++) cp16(qd + j * 16, qs + j * 4);
    }
    auto issue_kv = [&](int kt, int buf) {
        const float* ks = Kp + (size_t)(kt * 128 + (tid >> 1)) * ldk + (tid & 1) * 32;
        uint32_t kd = sKa + buf * 34816u + (tid >> 1) * 272 + (tid & 1) * 128;
#pragma unroll
        for (int j = 0; j < 8; j++) cp16(kd + j * 16, ks + j * 4);
        const float* vs = Vp + (size_t)(tid >> 2) * TT + kt * 128 + (tid & 3) * 32;
        uint32_t vd = sVa + buf * 33792u + (tid >> 2) * 528 + (tid & 3) * 128;
#pragma unroll
        for (int j = 0; j < 8; j++) cp16(vd + j * 16, vs + j * 4);
        if (tid < 32) {
            uint32_t mv = *(const uint32_t*)(padp + (size_t)kt * 128 + tid * 4);
            sMskp[buf * 32 + tid] = mv;
            uint32_t f = __reduce_or_sync(0xffffffffu, mv);
            if (tid == 0) sMskp[64 + buf] = f;
        }
    };
    issue_kv(0, 0);
    asm volatile("cp.async.commit_group;" ::: "memory");

    float m0 = -INFINITY, m1 = -INFINITY, l0 = 0.f, l1 = 0.f;
    float oacc[8][4];
#pragma unroll
    for (int j = 0; j < 8; j++)
#pragma unroll
        for (int r = 0; r < 4; r++) oacc[j][r] = 0.f;

    const int r0 = w * 16 + g, r1 = r0 + 8;
    const int s0l = (lane & ~3) | (qc >> 1), s1l = s0l + 2;
    const bool odd = (qc & 1) != 0;

    for (int kt = 0; kt < nkt; ++kt) {
        const int buf = kt & 1;
        if (kt + 1 < nkt) {
            issue_kv(kt + 1, buf ^ 1);
            asm volatile("cp.async.commit_group;" ::: "memory");
            asm volatile("cp.async.wait_group 1;" ::: "memory");
        } else {
            asm volatile("cp.async.wait_group 0;" ::: "memory");
        }
        __syncthreads();

        float aq[8][4];
        {
            const float* qr = sm + (size_t)(w * 16 + g) * 68;
#pragma unroll
            for (int ks = 0; ks < 8; ks++) {
                aq[ks][0] = qr[ks * 8 + qc];
                aq[ks][1] = qr[8 * 68 + ks * 8 + qc];
                aq[ks][2] = qr[ks * 8 + qc + 4];
                aq[ks][3] = qr[8 * 68 + ks * 8 + qc + 4];
            }
        }
        float sacc[16][4];
#pragma unroll
        for (int ni = 0; ni < 16; ni++)
#pragma unroll
            for (int r = 0; r < 4; r++) sacc[ni][r] = 0.f;
        {
            const float* kb = sm + FL_SK + buf * 8704;
#pragma unroll
            for (int ks = 0; ks < 8; ks++)
#pragma unroll
                for (int ni = 0; ni < 16; ni++) {
                    const float* kr = kb + (ni * 8 + g) * 68 + ks * 8;
                    float bv[2] = { kr[qc], kr[qc + 4] };
                    mma_tf32(sacc[ni], aq[ks], bv);
                }
        }

        const uint32_t pf = sMskp[64 + buf];
        const unsigned char* mb = (const unsigned char*)(sMskp + buf * 32);
        float tm0 = -INFINITY, tm1 = -INFINITY;
#pragma unroll
        for (int ni = 0; ni < 16; ni++) {
            float s0 = sacc[ni][0] * 0.125f, s1 = sacc[ni][1] * 0.125f;
            float s2 = sacc[ni][2] * 0.125f, s3 = sacc[ni][3] * 0.125f;
            const int c0 = ni * 8 + qc * 2;
            if (CAUSAL && kt == qt) {
                if (c0     > r0) s0 = -INFINITY;
                if (c0 + 1 > r0) s1 = -INFINITY;
                if (c0     > r1) s2 = -INFINITY;
                if (c0 + 1 > r1) s3 = -INFINITY;
            }
            if (pf) {
                if (mb[c0])     { s0 = -INFINITY; s2 = -INFINITY; }
                if (mb[c0 + 1]) { s1 = -INFINITY; s3 = -INFINITY; }
            }
            sacc[ni][0] = s0; sacc[ni][1] = s1; sacc[ni][2] = s2; sacc[ni][3] = s3;
            tm0 = fmaxf(tm0, fmaxf(s0, s1));
            tm1 = fmaxf(tm1, fmaxf(s2, s3));
        }
        tm0 = fmaxf(tm0, __shfl_xor_sync(0xffffffffu, tm0, 1));
        tm0 = fmaxf(tm0, __shfl_xor_sync(0xffffffffu, tm0, 2));
        tm1 = fmaxf(tm1, __shfl_xor_sync(0xffffffffu, tm1, 1));
        tm1 = fmaxf(tm1, __shfl_xor_sync(0xffffffffu, tm1, 2));
        const float mn0 = fmaxf(m0, tm0), mn1 = fmaxf(m1, tm1);

        float sum0 = 0.f, sum1 = 0.f;
#pragma unroll
        for (int ni = 0; ni < 16; ni++) {
            float p0 = __expf(sacc[ni][0] - mn0);
            float p1 = __expf(sacc[ni][1] - mn0);
            float p2 = __expf(sacc[ni][2] - mn1);
            float p3 = __expf(sacc[ni][3] - mn1);
            sacc[ni][0] = p0; sacc[ni][1] = p1; sacc[ni][2] = p2; sacc[ni][3] = p3;
            sum0 += p0 + p1; sum1 += p2 + p3;
        }
        sum0 += __shfl_xor_sync(0xffffffffu, sum0, 1);
        sum0 += __shfl_xor_sync(0xffffffffu, sum0, 2);
        sum1 += __shfl_xor_sync(0xffffffffu, sum1, 1);
        sum1 += __shfl_xor_sync(0xffffffffu, sum1, 2);

        const float sc0 = __expf(m0 - mn0), sc1 = __expf(m1 - mn1);
        l0 = l0 * sc0 + sum0;  l1 = l1 * sc1 + sum1;
        m0 = mn0;  m1 = mn1;
#pragma unroll
        for (int nj = 0; nj < 8; nj++) {
            oacc[nj][0] *= sc0; oacc[nj][1] *= sc0;
            oacc[nj][2] *= sc1; oacc[nj][3] *= sc1;
        }

        {
            const float* vb = sm + FL_SV + buf * 8448;
#pragma unroll
            for (int k2 = 0; k2 < 16; k2++) {
                float v00 = __shfl_sync(0xffffffffu, sacc[k2][0], s0l);
                float v01 = __shfl_sync(0xffffffffu, sacc[k2][1], s0l);
                float v20 = __shfl_sync(0xffffffffu, sacc[k2][2], s0l);
                float v21 = __shfl_sync(0xffffffffu, sacc[k2][3], s0l);
                float w00 = __shfl_sync(0xffffffffu, sacc[k2][0], s1l);
                float w01 = __shfl_sync(0xffffffffu, sacc[k2][1], s1l);
                float w20 = __shfl_sync(0xffffffffu, sacc[k2][2], s1l);
                float w21 = __shfl_sync(0xffffffffu, sacc[k2][3], s1l);
                float pa[4];
                pa[0] = to_tf32(odd ? v01 : v00);
                pa[1] = to_tf32(odd ? v21 : v20);
                pa[2] = to_tf32(odd ? w01 : w00);
                pa[3] = to_tf32(odd ? w21 : w20);
#pragma unroll
                for (int nj = 0; nj < 8; nj++) {
                    const float* vr = vb + (nj * 8 + g) * 132 + k2 * 8;
                    float bv[2] = { vr[qc], vr[qc + 4] };
                    mma_tf32(oacc[nj], pa, bv);
                }
            }
        }
        __syncthreads();
    }

    const float inv0 = 1.f / l0, inv1 = 1.f / l1;
    float* orow0 = Op + (size_t)(qt * 128 + r0) * CC;
    float* orow1 = orow0 + 8 * CC;
#pragma unroll
    for (int nj = 0; nj < 8; nj++) {
        *(float2*)(orow0 + nj * 8 + qc * 2) =
            make_float2(to_tf32(oacc[nj][0] * inv0), to_tf32(oacc[nj][1] * inv0));
        *(float2*)(orow1 + nj * 8 + qc * 2) =
            make_float2(to_tf32(oacc[nj][2] * inv1), to_tf32(oacc[nj][3] * inv1));
    }
}

// ============================ layernorm ==========================================
__device__ __forceinline__ float warpSum(float v) {
#pragma unroll
    for (int o = 16; o; o >>= 1) v += __shfl_xor_sync(0xffffffffu, v, o);
    return v;
}

template<bool ROUND>
__global__ void __launch_bounds__(256)
add_ln(const float* __restrict__ X, const float* __restrict__ R,
       const float* __restrict__ g, const float* __restrict__ be,
       float* __restrict__ out)
{
    const size_t row = blockIdx.x;
    const int tid = threadIdx.x;
    const int col = tid * 4;
    float4 xv = *(const float4*)(X + row * CC + col);
    float4 rv = *(const float4*)(R + row * CC + col);
    float4 v;
    v.x = xv.x + rv.x; v.y = xv.y + rv.y; v.z = xv.z + rv.z; v.w = xv.w + rv.w;

    __shared__ float sh1[8], sh2[8];
    float s = (v.x + v.y) + (v.z + v.w);
    float sq = v.x * v.x + v.y * v.y + v.z * v.z + v.w * v.w;
    s = warpSum(s); sq = warpSum(sq);
    if ((tid & 31) == 0) { sh1[tid >> 5] = s; sh2[tid >> 5] = sq; }
    __syncthreads();
    s  = (sh1[0] + sh1[1]) + (sh1[2] + sh1[3]) + (sh1[4] + sh1[5]) + (sh1[6] + sh1[7]);
    sq = (sh2[0] + sh2[1]) + (sh2[2] + sh2[3]) + (sh2[4] + sh2[5]) + (sh2[6] + sh2[7]);
    const float mean = s * (1.0f / CC);
    const float var = sq * (1.0f / CC) - mean * mean;
    const float rstd = rsqrtf(var + 1e-5f);

    float4 gg = *(const float4*)(g + col);
    float4 bb = *(const float4*)(be + col);
    float4 o;
    o.x = (v.x - mean) * rstd * gg.x + bb.x;
    o.y = (v.y - mean) * rstd * gg.y + bb.y;
    o.z = (v.z - mean) * rstd * gg.z + bb.z;
    o.w = (v.w - mean) * rstd * gg.w + bb.w;
    if (ROUND) {
        o.x = to_tf32(o.x); o.y = to_tf32(o.y);
        o.z = to_tf32(o.z); o.w = to_tf32(o.w);
    }
    *(float4*)(out + row * CC + col) = o;
}

// ------------------------------- launcher ---------------------------------------
extern "C" void kernel_launch(void* const* d_in, const int* in_sizes, int n_in,
                              void* d_out, int out_size)
{
    const float* x    = (const float*)d_in[0];
    const float* enc  = (const float*)d_in[1];
    const unsigned char* tmask = (const unsigned char*)d_in[2];
    const unsigned char* smask = (const unsigned char*)d_in[3];
    const float* Wq1 = (const float*)d_in[4];
    const float* Wk1 = (const float*)d_in[5];
    const float* Wv1 = (const float*)d_in[6];
    const float* Wo1 = (const float*)d_in[7];
    const float* ln1g = (const float*)d_in[8];
    const float* ln1b = (const float*)d_in[9];
    const float* Wq2 = (const float*)d_in[10];
    const float* Wk2 = (const float*)d_in[11];
    const float* Wv2 = (const float*)d_in[12];
    const float* Wo2 = (const float*)d_in[13];
    const float* ln2g = (const float*)d_in[14];
    const float* ln2b = (const float*)d_in[15];
    const float* Wf1 = (const float*)d_in[16];
    const float* bf1 = (const float*)d_in[17];
    const float* Wf2 = (const float*)d_in[18];
    const float* bf2 = (const float*)d_in[19];
    const float* ln3g = (const float*)d_in[20];
    const float* ln3b = (const float*)d_in[21];
    float* out = (float*)d_out;

    float *gq, *gvt, *gctx, *go, *gx1, *gx2, *gff, *gxr, *ger, *gwt;
    cudaGetSymbolAddress((void**)&gq,  g_q);
    cudaGetSymbolAddress((void**)&gvt, g_vt);
    cudaGetSymbolAddress((void**)&gctx, g_ctx);
    cudaGetSymbolAddress((void**)&go,  g_o);
    cudaGetSymbolAddress((void**)&gx1, g_x1);
    cudaGetSymbolAddress((void**)&gx2, g_x2);
    cudaGetSymbolAddress((void**)&gff, g_ff);
    cudaGetSymbolAddress((void**)&gxr, g_xr);
    cudaGetSymbolAddress((void**)&ger, g_er);
    cudaGetSymbolAddress((void**)&gwt, g_wt);

    float* tq1 = gwt + 0u * 1048576u;    // tq1,tk1,tv1 contiguous -> [3072,1024]
    float* tk1 = gwt + 1u * 1048576u;
    float* tv1 = gwt + 2u * 1048576u;
    float* to1 = gwt + 3u * 1048576u;
    float* tq2 = gwt + 4u * 1048576u;
    float* tk2 = gwt + 5u * 1048576u;    // tk2,tv2 contiguous -> [2048,1024]
    float* tv2 = gwt + 6u * 1048576u;
    float* to2 = gwt + 7u * 1048576u;
    float* tf1 = gwt + 8u * 1048576u;               // [F, C]
    float* tf2 = gwt + 8u * 1048576u + 4194304u;    // [C, F]

    auto* kProj  = gemm_mma<false, false, false>;   // plain (out -> add_ln / flash)
    auto* kProjR = gemm_mma<false, false, true >;   // rounded out (out -> GEMM A)
    auto* kFfn1  = gemm_mma<true,  true,  true >;   // bias+relu+rounded (-> FFN2 A)
    auto* kFfn2  = gemm_mma<true,  false, false>;
    cudaFuncSetAttribute(kProj,  cudaFuncAttributeMaxDynamicSharedMemorySize, GSMEM);
    cudaFuncSetAttribute(kProjR, cudaFuncAttributeMaxDynamicSharedMemorySize, GSMEM);
    cudaFuncSetAttribute(kFfn1,  cudaFuncAttributeMaxDynamicSharedMemorySize, GSMEM);
    cudaFuncSetAttribute(kFfn2,  cudaFuncAttributeMaxDynamicSharedMemorySize, GSMEM);
    cudaFuncSetAttribute(flash_k<true>,  cudaFuncAttributeMaxDynamicSharedMemorySize, FSMEM);
    cudaFuncSetAttribute(flash_k<false>, cudaFuncAttributeMaxDynamicSharedMemorySize, FSMEM);

    const dim3 blk(256);
    const dim3 tblk(32, 8);

    // ---- producer-side tf32 rounding of external GEMM A inputs (1 launch) ----
    Ptr2 p2;
    p2.s[0] = x;   p2.d[0] = gxr;
    p2.s[1] = enc; p2.d[1] = ger;
    round2<<<dim3(MM * CC / 1024, 2), blk>>>(p2);

    // ---- weight transposes (K-major, tf32-rounded B operands) ----
    Ptr8 p8;
    p8.s[0] = Wq1; p8.d[0] = tq1;  p8.s[1] = Wk1; p8.d[1] = tk1;
    p8.s[2] = Wv1; p8.d[2] = tv1;  p8.s[3] = Wo1; p8.d[3] = to1;
    p8.s[4] = Wq2; p8.d[4] = tq2;  p8.s[5] = Wk2; p8.d[5] = tk2;
    p8.s[6] = Wv2; p8.d[6] = tv2;  p8.s[7] = Wo2; p8.d[7] = to2;
    transpose8<<<dim3(CC/32, CC/32, 8), tblk>>>(p8);
    transpose_k<<<dim3(FF/32, CC/32), tblk>>>(Wf1, tf1, CC, FF);
    transpose_k<<<dim3(CC/32, FF/32), tblk>>>(Wf2, tf2, FF, CC);

    const dim3 gQKV(3072/128, MM/128);   // (24, 32) fused self QKV
    const dim3 gKV (2048/128, MM/128);   // (16, 32) fused cross KV
    const dim3 gP  (CC/128,   MM/128);   // (8, 32)
    const dim3 gF1 (FF/128,   MM/128);   // (32, 32)
    const dim3 gFl (TT/128, BB*HH);      // (8, 64)
    const dim3 gVt (CC/32, TT/32, BB);
    const int nLn = MM;

    // ---- self-attention (causal) ----
    kProj<<<gQKV, blk, GSMEM>>>(gxr, tq1, nullptr, gff, CC, CC, CC, 3072);
    transpose_v<<<gVt, tblk>>>(gff + 2048, gvt, 3072);
    flash_k<true><<<gFl, blk, FSMEM>>>(gff, gff + 1024, gvt, tmask, gctx, 3072, 3072);
    kProj<<<gP, blk, GSMEM>>>(gctx, to1, nullptr, go, CC, CC, CC, CC);
    add_ln<true><<<nLn, blk>>>(x, go, ln1g, ln1b, gx1);

    // ---- cross-attention ----
    kProjR<<<gP,  blk, GSMEM>>>(gx1, tq2, nullptr, gq, CC, CC, CC, CC);
    kProj <<<gKV, blk, GSMEM>>>(ger, tk2, nullptr, gff, CC, CC, CC, 2048);
    transpose_v<<<gVt, tblk>>>(gff + 1024, gvt, 2048);
    flash_k<false><<<gFl, blk, FSMEM>>>(gq, gff, gvt, smask, gctx, CC, 2048);
    kProj<<<gP, blk, GSMEM>>>(gctx, to2, nullptr, go, CC, CC, CC, CC);
    add_ln<true><<<nLn, blk>>>(gx1, go, ln2g, ln2b, gx2);

    // ---- FFN ----
    kFfn1<<<gF1, blk, GSMEM>>>(gx2, tf1, bf1, gff, CC, CC, CC, FF);
    kFfn2<<<gP,  blk, GSMEM>>>(gff, tf2, bf2, go, FF, FF, FF, CC);
    add_ln<false><<<nLn, blk>>>(gx2, go, ln3g, ln3b, out);
}

// round 9
// speedup vs baseline: 1.7300x; 1.6173x over previous
#include <cuda_runtime.h>
#include <cuda_fp16.h>
#include <cstdint>
#include <cstddef>

// Problem constants
#define BB 4
#define TT 1024
#define CC 1024
#define HH 16
#define DH 64
#define FF 4096
#define MM (BB*TT)          // 4096 rows

// ---------------- scratch (device globals; no allocation allowed) ----------------
__device__ float  g_q  [(size_t)MM*CC];        // cross-attn Q (fp32, flash input)
__device__ float  g_vt [(size_t)MM*CC];        // V transposed per batch: [B][C][T]
__device__ float  g_o  [(size_t)MM*CC];        // GEMM fp32 outputs (pre-LN)
__device__ float  g_x1 [(size_t)MM*CC];
__device__ float  g_x2 [(size_t)MM*CC];
__device__ float  g_ff [(size_t)MM*FF];        // fp32 QKV / KV outputs (flash input)
__device__ __half g_xh [(size_t)MM*CC];        // half GEMM-A operands
__device__ __half g_eh [(size_t)MM*CC];
__device__ __half g_ctxh[(size_t)MM*CC];
__device__ __half g_x1h[(size_t)MM*CC];
__device__ __half g_x2h[(size_t)MM*CC];
__device__ __half g_ffh[(size_t)MM*FF];
__device__ __half g_wth[8u*1024u*1024u + 2u*4096u*1024u];   // half weights (K-major)

// ============================ small helpers ======================================
__device__ __forceinline__ float to_tf32(float x) {
    uint32_t o;
    asm("cvt.rna.tf32.f32 %0, %1;" : "=r"(o) : "r"(__float_as_uint(x)));
    return __uint_as_float(o);
}
__device__ __forceinline__ void mma_tf32(float* d, const float* a, const float* b) {
    asm volatile(
        "mma.sync.aligned.m16n8k8.row.col.f32.tf32.tf32.f32 "
        "{%0,%1,%2,%3},{%4,%5,%6,%7},{%8,%9},{%0,%1,%2,%3};"
        : "+f"(d[0]), "+f"(d[1]), "+f"(d[2]), "+f"(d[3])
        : "r"(__float_as_uint(a[0])), "r"(__float_as_uint(a[1])),
          "r"(__float_as_uint(a[2])), "r"(__float_as_uint(a[3])),
          "r"(__float_as_uint(b[0])), "r"(__float_as_uint(b[1])));
}
__device__ __forceinline__ void mma_f16(float* d, const uint32_t* a, const uint32_t* b) {
    asm volatile(
        "mma.sync.aligned.m16n8k16.row.col.f32.f16.f16.f32 "
        "{%0,%1,%2,%3},{%4,%5,%6,%7},{%8,%9},{%0,%1,%2,%3};"
        : "+f"(d[0]), "+f"(d[1]), "+f"(d[2]), "+f"(d[3])
        : "r"(a[0]), "r"(a[1]), "r"(a[2]), "r"(a[3]),
          "r"(b[0]), "r"(b[1]));
}
__device__ __forceinline__ uint32_t smem_u32(const void* p) {
    uint32_t a;
    asm("{ .reg .u64 t; cvta.to.shared.u64 t, %1; cvt.u32.u64 %0, t; }" : "=r"(a) : "l"(p));
    return a;
}
__device__ __forceinline__ void cp16(uint32_t dst, const void* src) {
    asm volatile("cp.async.cg.shared.global [%0], [%1], 16;" :: "r"(dst), "l"(src));
}

// =================== fp16 conversion copy (2 tensors, z-batched) =================
struct Ptr2h { const float* s[2]; __half* d[2]; };
__global__ void __launch_bounds__(256)
round2h(Ptr2h p)
{
    const float* in = p.s[blockIdx.y];
    __half* out = p.d[blockIdx.y];
    const size_t i = ((size_t)blockIdx.x * 256 + threadIdx.x) * 4;
    float4 v = *(const float4*)(in + i);
    __half2 h0 = __floats2half2_rn(v.x, v.y);
    __half2 h1 = __floats2half2_rn(v.z, v.w);
    *(__half2*)(out + i)     = h0;
    *(__half2*)(out + i + 2) = h1;
}

// ====================== 32x32 tiled transposes (fp16 out) ========================
struct Ptr8h { const float* s[8]; __half* d[8]; };

__global__ void __launch_bounds__(256)
transpose8h(Ptr8h ps)   // 8 square [CC x CC] weights, z selects matrix
{
    const float* in = ps.s[blockIdx.z];
    __half* out = ps.d[blockIdx.z];
    __shared__ float t[32][33];
    const int bx = blockIdx.x * 32, by = blockIdx.y * 32;
    int x = bx + threadIdx.x;
#pragma unroll
    for (int i = 0; i < 32; i += 8)
        t[threadIdx.y + i][threadIdx.x] = in[(size_t)(by + threadIdx.y + i) * CC + x];
    __syncthreads();
    x = by + threadIdx.x;
#pragma unroll
    for (int i = 0; i < 32; i += 8)
        out[(size_t)(bx + threadIdx.y + i) * CC + x] = __float2half_rn(t[threadIdx.x][threadIdx.y + i]);
}

__global__ void __launch_bounds__(256)
transpose_kh(const float* __restrict__ in, __half* __restrict__ out, int R, int C)
{
    __shared__ float t[32][33];
    const int bx = blockIdx.x * 32, by = blockIdx.y * 32;
    int x = bx + threadIdx.x;
#pragma unroll
    for (int i = 0; i < 32; i += 8)
        t[threadIdx.y + i][threadIdx.x] = in[(size_t)(by + threadIdx.y + i) * C + x];
    __syncthreads();
    x = by + threadIdx.x;
#pragma unroll
    for (int i = 0; i < 32; i += 8)
        out[(size_t)(bx + threadIdx.y + i) * R + x] = __float2half_rn(t[threadIdx.x][threadIdx.y + i]);
}

// extract + transpose V block out of a packed [B*T, ldin] fp32 buffer -> [B][C][T]
__global__ void __launch_bounds__(256)
transpose_v(const float* __restrict__ in, float* __restrict__ out, int ldin)
{
    in  += (size_t)blockIdx.z * TT * ldin;
    out += (size_t)blockIdx.z * CC * TT;
    __shared__ float t[32][33];
    const int bx = blockIdx.x * 32, by = blockIdx.y * 32;   // bx: C dim, by: T dim
#pragma unroll
    for (int i = 0; i < 32; i += 8)
        t[threadIdx.y + i][threadIdx.x] =
            in[(size_t)(by + threadIdx.y + i) * ldin + bx + threadIdx.x];
    __syncthreads();
#pragma unroll
    for (int i = 0; i < 32; i += 8)
        out[(size_t)(bx + threadIdx.y + i) * TT + by + threadIdx.x] =
            to_tf32(t[threadIdx.x][threadIdx.y + i]);
}

// ================= fp16 mma.sync GEMM: C[M,N] = A[M,K] @ Bt[N,K]^T ===============
// A,Bt half (K contiguous). 128x128 CTA tile, 8 warps (2x4, 64x32), K-stage 64,
// cp.async 3-stage (R6 ordering: compute then issue), 2 CTAs/SM, fp32 accum.
#define G_LDPH 72                            // halfs per row (64 data + 8 pad)
#define G_STGH (256 * G_LDPH)                // halfs per stage (A128 + B128 rows)
#define GSMEM  (3 * G_STGH * 2)              // 110592 bytes

template<bool BIAS, bool RELU, bool HOUT>
__global__ void __launch_bounds__(256, 2)
gemm_mma(const __half* __restrict__ A, const __half* __restrict__ Bt,
         const float* __restrict__ bias, void* __restrict__ Cv,
         int K, int lda, int ldb, int ldc)
{
    extern __shared__ __half smh[];
    const int bxn = blockIdx.x * 128, bym = blockIdx.y * 128;
    const int tid = threadIdx.x, wid = tid >> 5, lane = tid & 31;
    const int wr = wid >> 2, wc = wid & 3;      // 2 x 4 warps, 64x32 each
    const int g = lane >> 2, qc = lane & 3;

    const int row = tid >> 1, colb = (tid & 1) * 32;   // halfs
    const __half* Ag = A  + (size_t)(bym + row) * lda + colb;
    const __half* Bg = Bt + (size_t)(bxn + row) * ldb + colb;
    const uint32_t adst = smem_u32(smh) + (uint32_t)(row * G_LDPH + colb) * 2;
    const uint32_t bdst = adst + 128 * G_LDPH * 2;

    float acc[4][4][4];
#pragma unroll
    for (int i = 0; i < 4; i++)
#pragma unroll
        for (int j = 0; j < 4; j++)
#pragma unroll
            for (int r = 0; r < 4; r++) acc[i][j][r] = 0.f;

    const int nst = K >> 6;                    // K-stage = 64 halfs

    // prologue: stages 0, 1
#pragma unroll
    for (int s = 0; s < 2; s++) {
        const __half* as = Ag + s * 64;
        const __half* bs = Bg + s * 64;
        const uint32_t ad = adst + s * G_STGH * 2;
        const uint32_t bd = bdst + s * G_STGH * 2;
#pragma unroll
        for (int j = 0; j < 4; j++) {
            cp16(ad + j * 16, as + j * 8);
            cp16(bd + j * 16, bs + j * 8);
        }
        asm volatile("cp.async.commit_group;" ::: "memory");
    }

    int buf = 0, nxt = 2;      // nxt = (it+2) % 3
    for (int it = 0; it < nst; ++it) {
        asm volatile("cp.async.wait_group 1;" ::: "memory");
        __syncthreads();
        const __half* a_s = smh + (size_t)buf * G_STGH + (wr * 64 + g) * G_LDPH;
        const __half* b_s = smh + (size_t)buf * G_STGH + 128 * G_LDPH + (wc * 32 + g) * G_LDPH;
#pragma unroll
        for (int ks = 0; ks < 4; ks++) {       // 4 x k16
            uint32_t av_[4][4], bv_[4][2];
#pragma unroll
            for (int mi = 0; mi < 4; mi++) {
                const __half* p = a_s + mi * 16 * G_LDPH + ks * 16 + qc * 2;
                av_[mi][0] = *(const uint32_t*)(p);
                av_[mi][1] = *(const uint32_t*)(p + 8 * G_LDPH);
                av_[mi][2] = *(const uint32_t*)(p + 8);
                av_[mi][3] = *(const uint32_t*)(p + 8 * G_LDPH + 8);
            }
#pragma unroll
            for (int ni = 0; ni < 4; ni++) {
                const __half* p = b_s + ni * 8 * G_LDPH + ks * 16 + qc * 2;
                bv_[ni][0] = *(const uint32_t*)(p);
                bv_[ni][1] = *(const uint32_t*)(p + 8);
            }
#pragma unroll
            for (int mi = 0; mi < 4; mi++)
#pragma unroll
                for (int ni = 0; ni < 4; ni++)
                    mma_f16(acc[mi][ni], av_[mi], bv_[ni]);
        }
        if (it + 2 < nst) {
            const int kt = it + 2;
            const __half* as = Ag + kt * 64;
            const __half* bs = Bg + kt * 64;
            const uint32_t ad = adst + nxt * G_STGH * 2;
            const uint32_t bd = bdst + nxt * G_STGH * 2;
#pragma unroll
            for (int j = 0; j < 4; j++) {
                cp16(ad + j * 16, as + j * 8);
                cp16(bd + j * 16, bs + j * 8);
            }
            asm volatile("cp.async.commit_group;" ::: "memory");
        }
        buf = (buf == 2) ? 0 : buf + 1;
        nxt = (nxt == 2) ? 0 : nxt + 1;
    }

#pragma unroll
    for (int mi = 0; mi < 4; mi++) {
        const int r = bym + wr * 64 + mi * 16 + g;
#pragma unroll
        for (int ni = 0; ni < 4; ni++) {
            const int col = bxn + wc * 32 + ni * 8 + qc * 2;
            float2 bv = make_float2(0.f, 0.f);
            if (BIAS) bv = *(const float2*)(bias + col);
            float2 v0, v1;
            v0.x = acc[mi][ni][0] + bv.x;
            v0.y = acc[mi][ni][1] + bv.y;
            v1.x = acc[mi][ni][2] + bv.x;
            v1.y = acc[mi][ni][3] + bv.y;
            if (RELU) {
                v0.x = fmaxf(v0.x, 0.f); v0.y = fmaxf(v0.y, 0.f);
                v1.x = fmaxf(v1.x, 0.f); v1.y = fmaxf(v1.y, 0.f);
            }
            if (HOUT) {
                __half* C = (__half*)Cv;
                *(__half2*)(C + (size_t)r * ldc + col)       = __floats2half2_rn(v0.x, v0.y);
                *(__half2*)(C + (size_t)(r + 8) * ldc + col) = __floats2half2_rn(v1.x, v1.y);
            } else {
                float* C = (float*)Cv;
                *(float2*)(C + (size_t)r * ldc + col)       = v0;
                *(float2*)(C + (size_t)(r + 8) * ldc + col) = v1;
            }
        }
    }
}

// ====================== flash attention (tf32 mma, online softmax) ===============
// Q/K/V fp32 in; output half (consumed as fp16-GEMM A operand).
#define FL_SQ  0
#define FL_SK  8704           // floats
#define FL_SV  26112
#define FL_MSK 43008
#define FSMEM  ((43008 + 66) * 4)

template<bool CAUSAL>
__global__ void __launch_bounds__(256, 1)
flash_k(const float* __restrict__ Qg, const float* __restrict__ Kg,
        const float* __restrict__ Vg, const unsigned char* __restrict__ padg,
        __half* __restrict__ Og, int ldq, int ldk)
{
    extern __shared__ float sm[];
    const int tid = threadIdx.x, lane = tid & 31, w = tid >> 5;
    const int g = lane >> 2, qc = lane & 3;
    const int qt = blockIdx.x;
    const int z = blockIdx.y, b = z >> 4, h = z & 15;

    const float* Qp = Qg + (size_t)b * TT * ldq + h * 64;
    const float* Kp = Kg + (size_t)b * TT * ldk + h * 64;
    const float* Vp = Vg + ((size_t)b * CC + h * 64) * TT;
    const unsigned char* padp = padg + (size_t)b * TT;
    __half* Op = Og + (size_t)b * TT * CC + h * 64;

    const uint32_t sQa = smem_u32(sm);
    const uint32_t sKa = sQa + FL_SK * 4;
    const uint32_t sVa = sQa + FL_SV * 4;
    uint32_t* sMskp = (uint32_t*)(sm + FL_MSK);

    const int nkt = CAUSAL ? qt + 1 : (TT / 128);

    {
        const float* qs = Qp + (size_t)(qt * 128 + (tid >> 1)) * ldq + (tid & 1) * 32;
        uint32_t qd = sQa + (tid >> 1) * 272 + (tid & 1) * 128;
#pragma unroll
        for (int j = 0; j < 8; j++) cp16(qd + j * 16, qs + j * 4);
    }
    auto issue_kv = [&](int kt, int buf) {
        const float* ks = Kp + (size_t)(kt * 128 + (tid >> 1)) * ldk + (tid & 1) * 32;
        uint32_t kd = sKa + buf * 34816u + (tid >> 1) * 272 + (tid & 1) * 128;
#pragma unroll
        for (int j = 0; j < 8; j++) cp16(kd + j * 16, ks + j * 4);
        const float* vs = Vp + (size_t)(tid >> 2) * TT + kt * 128 + (tid & 3) * 32;
        uint32_t vd = sVa + buf * 33792u + (tid >> 2) * 528 + (tid & 3) * 128;
#pragma unroll
        for (int j = 0; j < 8; j++) cp16(vd + j * 16, vs + j * 4);
        if (tid < 32) {
            uint32_t mv = *(const uint32_t*)(padp + (size_t)kt * 128 + tid * 4);
            sMskp[buf * 32 + tid] = mv;
            uint32_t f = __reduce_or_sync(0xffffffffu, mv);
            if (tid == 0) sMskp[64 + buf] = f;
        }
    };
    issue_kv(0, 0);
    asm volatile("cp.async.commit_group;" ::: "memory");

    float m0 = -INFINITY, m1 = -INFINITY, l0 = 0.f, l1 = 0.f;
    float oacc[8][4];
#pragma unroll
    for (int j = 0; j < 8; j++)
#pragma unroll
        for (int r = 0; r < 4; r++) oacc[j][r] = 0.f;

    const int r0 = w * 16 + g, r1 = r0 + 8;
    const int s0l = (lane & ~3) | (qc >> 1), s1l = s0l + 2;
    const bool odd = (qc & 1) != 0;

    for (int kt = 0; kt < nkt; ++kt) {
        const int buf = kt & 1;
        if (kt + 1 < nkt) {
            issue_kv(kt + 1, buf ^ 1);
            asm volatile("cp.async.commit_group;" ::: "memory");
            asm volatile("cp.async.wait_group 1;" ::: "memory");
        } else {
            asm volatile("cp.async.wait_group 0;" ::: "memory");
        }
        __syncthreads();

        float aq[8][4];
        {
            const float* qr = sm + (size_t)(w * 16 + g) * 68;
#pragma unroll
            for (int ks = 0; ks < 8; ks++) {
                aq[ks][0] = qr[ks * 8 + qc];
                aq[ks][1] = qr[8 * 68 + ks * 8 + qc];
                aq[ks][2] = qr[ks * 8 + qc + 4];
                aq[ks][3] = qr[8 * 68 + ks * 8 + qc + 4];
            }
        }
        float sacc[16][4];
#pragma unroll
        for (int ni = 0; ni < 16; ni++)
#pragma unroll
            for (int r = 0; r < 4; r++) sacc[ni][r] = 0.f;
        {
            const float* kb = sm + FL_SK + buf * 8704;
#pragma unroll
            for (int ks = 0; ks < 8; ks++)
#pragma unroll
                for (int ni = 0; ni < 16; ni++) {
                    const float* kr = kb + (ni * 8 + g) * 68 + ks * 8;
                    float bv[2] = { kr[qc], kr[qc + 4] };
                    mma_tf32(sacc[ni], aq[ks], bv);
                }
        }

        const uint32_t pf = sMskp[64 + buf];
        const unsigned char* mb = (const unsigned char*)(sMskp + buf * 32);
        float tm0 = -INFINITY, tm1 = -INFINITY;
#pragma unroll
        for (int ni = 0; ni < 16; ni++) {
            float s0 = sacc[ni][0] * 0.125f, s1 = sacc[ni][1] * 0.125f;
            float s2 = sacc[ni][2] * 0.125f, s3 = sacc[ni][3] * 0.125f;
            const int c0 = ni * 8 + qc * 2;
            if (CAUSAL && kt == qt) {
                if (c0     > r0) s0 = -INFINITY;
                if (c0 + 1 > r0) s1 = -INFINITY;
                if (c0     > r1) s2 = -INFINITY;
                if (c0 + 1 > r1) s3 = -INFINITY;
            }
            if (pf) {
                if (mb[c0])     { s0 = -INFINITY; s2 = -INFINITY; }
                if (mb[c0 + 1]) { s1 = -INFINITY; s3 = -INFINITY; }
            }
            sacc[ni][0] = s0; sacc[ni][1] = s1; sacc[ni][2] = s2; sacc[ni][3] = s3;
            tm0 = fmaxf(tm0, fmaxf(s0, s1));
            tm1 = fmaxf(tm1, fmaxf(s2, s3));
        }
        tm0 = fmaxf(tm0, __shfl_xor_sync(0xffffffffu, tm0, 1));
        tm0 = fmaxf(tm0, __shfl_xor_sync(0xffffffffu, tm0, 2));
        tm1 = fmaxf(tm1, __shfl_xor_sync(0xffffffffu, tm1, 1));
        tm1 = fmaxf(tm1, __shfl_xor_sync(0xffffffffu, tm1, 2));
        const float mn0 = fmaxf(m0, tm0), mn1 = fmaxf(m1, tm1);

        float sum0 = 0.f, sum1 = 0.f;
#pragma unroll
        for (int ni = 0; ni < 16; ni++) {
            float p0 = __expf(sacc[ni][0] - mn0);
            float p1 = __expf(sacc[ni][1] - mn0);
            float p2 = __expf(sacc[ni][2] - mn1);
            float p3 = __expf(sacc[ni][3] - mn1);
            sacc[ni][0] = p0; sacc[ni][1] = p1; sacc[ni][2] = p2; sacc[ni][3] = p3;
            sum0 += p0 + p1; sum1 += p2 + p3;
        }
        sum0 += __shfl_xor_sync(0xffffffffu, sum0, 1);
        sum0 += __shfl_xor_sync(0xffffffffu, sum0, 2);
        sum1 += __shfl_xor_sync(0xffffffffu, sum1, 1);
        sum1 += __shfl_xor_sync(0xffffffffu, sum1, 2);

        const float sc0 = __expf(m0 - mn0), sc1 = __expf(m1 - mn1);
        l0 = l0 * sc0 + sum0;  l1 = l1 * sc1 + sum1;
        m0 = mn0;  m1 = mn1;
#pragma unroll
        for (int nj = 0; nj < 8; nj++) {
            oacc[nj][0] *= sc0; oacc[nj][1] *= sc0;
            oacc[nj][2] *= sc1; oacc[nj][3] *= sc1;
        }

        {
            const float* vb = sm + FL_SV + buf * 8448;
#pragma unroll
            for (int k2 = 0; k2 < 16; k2++) {
                float v00 = __shfl_sync(0xffffffffu, sacc[k2][0], s0l);
                float v01 = __shfl_sync(0xffffffffu, sacc[k2][1], s0l);
                float v20 = __shfl_sync(0xffffffffu, sacc[k2][2], s0l);
                float v21 = __shfl_sync(0xffffffffu, sacc[k2][3], s0l);
                float w00 = __shfl_sync(0xffffffffu, sacc[k2][0], s1l);
                float w01 = __shfl_sync(0xffffffffu, sacc[k2][1], s1l);
                float w20 = __shfl_sync(0xffffffffu, sacc[k2][2], s1l);
                float w21 = __shfl_sync(0xffffffffu, sacc[k2][3], s1l);
                float pa[4];
                pa[0] = to_tf32(odd ? v01 : v00);
                pa[1] = to_tf32(odd ? v21 : v20);
                pa[2] = to_tf32(odd ? w01 : w00);
                pa[3] = to_tf32(odd ? w21 : w20);
#pragma unroll
                for (int nj = 0; nj < 8; nj++) {
                    const float* vr = vb + (nj * 8 + g) * 132 + k2 * 8;
                    float bv[2] = { vr[qc], vr[qc + 4] };
                    mma_tf32(oacc[nj], pa, bv);
                }
            }
        }
        __syncthreads();
    }

    const float inv0 = 1.f / l0, inv1 = 1.f / l1;
    __half* orow0 = Op + (size_t)(qt * 128 + r0) * CC;
    __half* orow1 = orow0 + 8 * CC;
#pragma unroll
    for (int nj = 0; nj < 8; nj++) {
        *(__half2*)(orow0 + nj * 8 + qc * 2) =
            __floats2half2_rn(oacc[nj][0] * inv0, oacc[nj][1] * inv0);
        *(__half2*)(orow1 + nj * 8 + qc * 2) =
            __floats2half2_rn(oacc[nj][2] * inv1, oacc[nj][3] * inv1);
    }
}

// ============================ layernorm ==========================================
__device__ __forceinline__ float warpSum(float v) {
#pragma unroll
    for (int o = 16; o; o >>= 1) v += __shfl_xor_sync(0xffffffffu, v, o);
    return v;
}

template<bool DUALH>
__global__ void __launch_bounds__(256)
add_ln(const float* __restrict__ X, const float* __restrict__ R,
       const float* __restrict__ g, const float* __restrict__ be,
       float* __restrict__ out, __half* __restrict__ outh)
{
    const size_t row = blockIdx.x;
    const int tid = threadIdx.x;
    const int col = tid * 4;
    float4 xv = *(const float4*)(X + row * CC + col);
    float4 rv = *(const float4*)(R + row * CC + col);
    float4 v;
    v.x = xv.x + rv.x; v.y = xv.y + rv.y; v.z = xv.z + rv.z; v.w = xv.w + rv.w;

    __shared__ float sh1[8], sh2[8];
    float s = (v.x + v.y) + (v.z + v.w);
    float sq = v.x * v.x + v.y * v.y + v.z * v.z + v.w * v.w;
    s = warpSum(s); sq = warpSum(sq);
    if ((tid & 31) == 0) { sh1[tid >> 5] = s; sh2[tid >> 5] = sq; }
    __syncthreads();
    s  = (sh1[0] + sh1[1]) + (sh1[2] + sh1[3]) + (sh1[4] + sh1[5]) + (sh1[6] + sh1[7]);
    sq = (sh2[0] + sh2[1]) + (sh2[2] + sh2[3]) + (sh2[4] + sh2[5]) + (sh2[6] + sh2[7]);
    const float mean = s * (1.0f / CC);
    const float var = sq * (1.0f / CC) - mean * mean;
    const float rstd = rsqrtf(var + 1e-5f);

    float4 gg = *(const float4*)(g + col);
    float4 bb = *(const float4*)(be + col);
    float4 o;
    o.x = (v.x - mean) * rstd * gg.x + bb.x;
    o.y = (v.y - mean) * rstd * gg.y + bb.y;
    o.z = (v.z - mean) * rstd * gg.z + bb.z;
    o.w = (v.w - mean) * rstd * gg.w + bb.w;
    *(float4*)(out + row * CC + col) = o;
    if (DUALH) {
        *(__half2*)(outh + row * CC + col)     = __floats2half2_rn(o.x, o.y);
        *(__half2*)(outh + row * CC + col + 2) = __floats2half2_rn(o.z, o.w);
    }
}

// ------------------------------- launcher ---------------------------------------
extern "C" void kernel_launch(void* const* d_in, const int* in_sizes, int n_in,
                              void* d_out, int out_size)
{
    const float* x    = (const float*)d_in[0];
    const float* enc  = (const float*)d_in[1];
    const unsigned char* tmask = (const unsigned char*)d_in[2];
    const unsigned char* smask = (const unsigned char*)d_in[3];
    const float* Wq1 = (const float*)d_in[4];
    const float* Wk1 = (const float*)d_in[5];
    const float* Wv1 = (const float*)d_in[6];
    const float* Wo1 = (const float*)d_in[7];
    const float* ln1g = (const float*)d_in[8];
    const float* ln1b = (const float*)d_in[9];
    const float* Wq2 = (const float*)d_in[10];
    const float* Wk2 = (const float*)d_in[11];
    const float* Wv2 = (const float*)d_in[12];
    const float* Wo2 = (const float*)d_in[13];
    const float* ln2g = (const float*)d_in[14];
    const float* ln2b = (const float*)d_in[15];
    const float* Wf1 = (const float*)d_in[16];
    const float* bf1 = (const float*)d_in[17];
    const float* Wf2 = (const float*)d_in[18];
    const float* bf2 = (const float*)d_in[19];
    const float* ln3g = (const float*)d_in[20];
    const float* ln3b = (const float*)d_in[21];
    float* out = (float*)d_out;

    float *gq, *gvt, *go, *gx1, *gx2, *gff;
    __half *gxh, *geh, *gctxh, *gx1h, *gx2h, *gffh, *gwth;
    cudaGetSymbolAddress((void**)&gq,  g_q);
    cudaGetSymbolAddress((void**)&gvt, g_vt);
    cudaGetSymbolAddress((void**)&go,  g_o);
    cudaGetSymbolAddress((void**)&gx1, g_x1);
    cudaGetSymbolAddress((void**)&gx2, g_x2);
    cudaGetSymbolAddress((void**)&gff, g_ff);
    cudaGetSymbolAddress((void**)&gxh, g_xh);
    cudaGetSymbolAddress((void**)&geh, g_eh);
    cudaGetSymbolAddress((void**)&gctxh, g_ctxh);
    cudaGetSymbolAddress((void**)&gx1h, g_x1h);
    cudaGetSymbolAddress((void**)&gx2h, g_x2h);
    cudaGetSymbolAddress((void**)&gffh, g_ffh);
    cudaGetSymbolAddress((void**)&gwth, g_wth);

    __half* tq1 = gwth + 0u * 1048576u;   // tq1,tk1,tv1 contiguous -> [3072,1024]
    __half* tk1 = gwth + 1u * 1048576u;
    __half* tv1 = gwth + 2u * 1048576u;
    __half* to1 = gwth + 3u * 1048576u;
    __half* tq2 = gwth + 4u * 1048576u;
    __half* tk2 = gwth + 5u * 1048576u;   // tk2,tv2 contiguous -> [2048,1024]
    __half* tv2 = gwth + 6u * 1048576u;
    __half* to2 = gwth + 7u * 1048576u;
    __half* tf1 = gwth + 8u * 1048576u;              // [F, C]
    __half* tf2 = gwth + 8u * 1048576u + 4194304u;   // [C, F]

    auto* kProj  = gemm_mma<false, false, false>;   // fp32 out (flash / add_ln)
    auto* kProjH = gemm_mma<false, false, true >;   // half out
    auto* kFfn1  = gemm_mma<true,  true,  true >;   // bias+relu, half out
    auto* kFfn2  = gemm_mma<true,  false, false>;
    cudaFuncSetAttribute(kProj,  cudaFuncAttributeMaxDynamicSharedMemorySize, GSMEM);
    cudaFuncSetAttribute(kProjH, cudaFuncAttributeMaxDynamicSharedMemorySize, GSMEM);
    cudaFuncSetAttribute(kFfn1,  cudaFuncAttributeMaxDynamicSharedMemorySize, GSMEM);
    cudaFuncSetAttribute(kFfn2,  cudaFuncAttributeMaxDynamicSharedMemorySize, GSMEM);
    cudaFuncSetAttribute(flash_k<true>,  cudaFuncAttributeMaxDynamicSharedMemorySize, FSMEM);
    cudaFuncSetAttribute(flash_k<false>, cudaFuncAttributeMaxDynamicSharedMemorySize, FSMEM);

    const dim3 blk(256);
    const dim3 tblk(32, 8);

    // ---- fp16 conversion of external GEMM-A inputs (1 launch) ----
    Ptr2h p2;
    p2.s[0] = x;   p2.d[0] = gxh;
    p2.s[1] = enc; p2.d[1] = geh;
    round2h<<<dim3(MM * CC / 1024, 2), blk>>>(p2);

    // ---- weight transposes (K-major, fp16 B operands) ----
    Ptr8h p8;
    p8.s[0] = Wq1; p8.d[0] = tq1;  p8.s[1] = Wk1; p8.d[1] = tk1;
    p8.s[2] = Wv1; p8.d[2] = tv1;  p8.s[3] = Wo1; p8.d[3] = to1;
    p8.s[4] = Wq2; p8.d[4] = tq2;  p8.s[5] = Wk2; p8.d[5] = tk2;
    p8.s[6] = Wv2; p8.d[6] = tv2;  p8.s[7] = Wo2; p8.d[7] = to2;
    transpose8h<<<dim3(CC/32, CC/32, 8), tblk>>>(p8);
    transpose_kh<<<dim3(FF/32, CC/32), tblk>>>(Wf1, tf1, CC, FF);
    transpose_kh<<<dim3(CC/32, FF/32), tblk>>>(Wf2, tf2, FF, CC);

    const dim3 gQKV(3072/128, MM/128);   // (24, 32) fused self QKV
    const dim3 gKV (2048/128, MM/128);   // (16, 32) fused cross KV
    const dim3 gP  (CC/128,   MM/128);   // (8, 32)
    const dim3 gF1 (FF/128,   MM/128);   // (32, 32)
    const dim3 gFl (TT/128, BB*HH);      // (8, 64)
    const dim3 gVt (CC/32, TT/32, BB);
    const int nLn = MM;

    // ---- self-attention (causal) ----
    kProj<<<gQKV, blk, GSMEM>>>(gxh, tq1, nullptr, gff, CC, CC, CC, 3072);
    transpose_v<<<gVt, tblk>>>(gff + 2048, gvt, 3072);
    flash_k<true><<<gFl, blk, FSMEM>>>(gff, gff + 1024, gvt, tmask, gctxh, 3072, 3072);
    kProj<<<gP, blk, GSMEM>>>(gctxh, to1, nullptr, go, CC, CC, CC, CC);
    add_ln<true><<<nLn, blk>>>(x, go, ln1g, ln1b, gx1, gx1h);

    // ---- cross-attention ----
    kProj<<<gP,  blk, GSMEM>>>(gx1h, tq2, nullptr, gq, CC, CC, CC, CC);
    kProj<<<gKV, blk, GSMEM>>>(geh, tk2, nullptr, gff, CC, CC, CC, 2048);
    transpose_v<<<gVt, tblk>>>(gff + 1024, gvt, 2048);
    flash_k<false><<<gFl, blk, FSMEM>>>(gq, gff, gvt, smask, gctxh, CC, 2048);
    kProj<<<gP, blk, GSMEM>>>(gctxh, to2, nullptr, go, CC, CC, CC, CC);
    add_ln<true><<<nLn, blk>>>(gx1, go, ln2g, ln2b, gx2, gx2h);

    // ---- FFN ----
    kFfn1<<<gF1, blk, GSMEM>>>(gx2h, tf1, bf1, gffh, CC, CC, CC, FF);
    kFfn2<<<gP,  blk, GSMEM>>>(gffh, tf2, bf2, go, FF, FF, FF, CC);
    add_ln<false><<<nLn, blk>>>(gx2, go, ln3g, ln3b, out, nullptr);
}

// round 10
// speedup vs baseline: 2.0166x; 1.1656x over previous
#include <cuda_runtime.h>
#include <cuda_fp16.h>
#include <cstdint>
#include <cstddef>

// Problem constants
#define BB 4
#define TT 1024
#define CC 1024
#define HH 16
#define DH 64
#define FF 4096
#define MM (BB*TT)          // 4096 rows

// ---------------- scratch (device globals; no allocation allowed) ----------------
__device__ float  g_o  [(size_t)MM*CC];        // GEMM fp32 outputs (pre-LN)
__device__ float  g_x1 [(size_t)MM*CC];
__device__ float  g_x2 [(size_t)MM*CC];
__device__ __half g_xh [(size_t)MM*CC];        // half GEMM-A operands
__device__ __half g_eh [(size_t)MM*CC];
__device__ __half g_qh [(size_t)MM*CC];        // cross-attn Q (half, flash input)
__device__ __half g_vth[(size_t)MM*CC];        // V^T per batch: [B][C][T] half
__device__ __half g_ctxh[(size_t)MM*CC];
__device__ __half g_x1h[(size_t)MM*CC];
__device__ __half g_x2h[(size_t)MM*CC];
__device__ __half g_ffh[(size_t)MM*FF];        // QKV / KV / FFN1 half outputs
__device__ __half g_wth[8u*1024u*1024u + 2u*4096u*1024u];   // half weights (K-major)

// ============================ small helpers ======================================
__device__ __forceinline__ void mma_f16(float* d, const uint32_t* a, const uint32_t* b) {
    asm volatile(
        "mma.sync.aligned.m16n8k16.row.col.f32.f16.f16.f32 "
        "{%0,%1,%2,%3},{%4,%5,%6,%7},{%8,%9},{%0,%1,%2,%3};"
        : "+f"(d[0]), "+f"(d[1]), "+f"(d[2]), "+f"(d[3])
        : "r"(a[0]), "r"(a[1]), "r"(a[2]), "r"(a[3]),
          "r"(b[0]), "r"(b[1]));
}
__device__ __forceinline__ uint32_t smem_u32(const void* p) {
    uint32_t a;
    asm("{ .reg .u64 t; cvta.to.shared.u64 t, %1; cvt.u32.u64 %0, t; }" : "=r"(a) : "l"(p));
    return a;
}
__device__ __forceinline__ void cp16(uint32_t dst, const void* src) {
    asm volatile("cp.async.cg.shared.global [%0], [%1], 16;" :: "r"(dst), "l"(src));
}
__device__ __forceinline__ uint32_t packh2(float a, float b) {
    __half2 h = __floats2half2_rn(a, b);
    return *(uint32_t*)&h;
}

// =================== fp16 conversion copy (2 tensors, z-batched) =================
struct Ptr2h { const float* s[2]; __half* d[2]; };
__global__ void __launch_bounds__(256)
round2h(Ptr2h p)
{
    const float* in = p.s[blockIdx.y];
    __half* out = p.d[blockIdx.y];
    const size_t i = ((size_t)blockIdx.x * 256 + threadIdx.x) * 4;
    float4 v = *(const float4*)(in + i);
    *(__half2*)(out + i)     = __floats2half2_rn(v.x, v.y);
    *(__half2*)(out + i + 2) = __floats2half2_rn(v.z, v.w);
}

// ====================== 32x32 tiled transposes (fp16 out) ========================
struct Ptr8h { const float* s[8]; __half* d[8]; };

__global__ void __launch_bounds__(256)
transpose8h(Ptr8h ps)   // 8 square [CC x CC] weights, z selects matrix
{
    const float* in = ps.s[blockIdx.z];
    __half* out = ps.d[blockIdx.z];
    __shared__ float t[32][33];
    const int bx = blockIdx.x * 32, by = blockIdx.y * 32;
    int x = bx + threadIdx.x;
#pragma unroll
    for (int i = 0; i < 32; i += 8)
        t[threadIdx.y + i][threadIdx.x] = in[(size_t)(by + threadIdx.y + i) * CC + x];
    __syncthreads();
    x = by + threadIdx.x;
#pragma unroll
    for (int i = 0; i < 32; i += 8)
        out[(size_t)(bx + threadIdx.y + i) * CC + x] = __float2half_rn(t[threadIdx.x][threadIdx.y + i]);
}

__global__ void __launch_bounds__(256)
transpose_kh(const float* __restrict__ in, __half* __restrict__ out, int R, int C)
{
    __shared__ float t[32][33];
    const int bx = blockIdx.x * 32, by = blockIdx.y * 32;
    int x = bx + threadIdx.x;
#pragma unroll
    for (int i = 0; i < 32; i += 8)
        t[threadIdx.y + i][threadIdx.x] = in[(size_t)(by + threadIdx.y + i) * C + x];
    __syncthreads();
    x = by + threadIdx.x;
#pragma unroll
    for (int i = 0; i < 32; i += 8)
        out[(size_t)(bx + threadIdx.y + i) * R + x] = __float2half_rn(t[threadIdx.x][threadIdx.y + i]);
}

// extract + transpose V block out of a packed [B*T, ldin] half buffer -> [B][C][T]
__global__ void __launch_bounds__(256)
transpose_vh(const __half* __restrict__ in, __half* __restrict__ out, int ldin)
{
    in  += (size_t)blockIdx.z * TT * ldin;
    out += (size_t)blockIdx.z * CC * TT;
    __shared__ __half t[32][40];
    const int bx = blockIdx.x * 32, by = blockIdx.y * 32;   // bx: C dim, by: T dim
#pragma unroll
    for (int i = 0; i < 32; i += 8)
        t[threadIdx.y + i][threadIdx.x] =
            in[(size_t)(by + threadIdx.y + i) * ldin + bx + threadIdx.x];
    __syncthreads();
#pragma unroll
    for (int i = 0; i < 32; i += 8)
        out[(size_t)(bx + threadIdx.y + i) * TT + by + threadIdx.x] =
            t[threadIdx.x][threadIdx.y + i];
}

// ================= fp16 mma.sync GEMM: C[M,N] = A[M,K] @ Bt[N,K]^T ===============
// (unchanged from R9 — passing, 1114us config)
#define G_LDPH 72                            // halfs per row (64 data + 8 pad)
#define G_STGH (256 * G_LDPH)                // halfs per stage (A128 + B128 rows)
#define GSMEM  (3 * G_STGH * 2)              // 110592 bytes

template<bool BIAS, bool RELU, bool HOUT>
__global__ void __launch_bounds__(256, 2)
gemm_mma(const __half* __restrict__ A, const __half* __restrict__ Bt,
         const float* __restrict__ bias, void* __restrict__ Cv,
         int K, int lda, int ldb, int ldc)
{
    extern __shared__ __half smh[];
    const int bxn = blockIdx.x * 128, bym = blockIdx.y * 128;
    const int tid = threadIdx.x, wid = tid >> 5, lane = tid & 31;
    const int wr = wid >> 2, wc = wid & 3;      // 2 x 4 warps, 64x32 each
    const int g = lane >> 2, qc = lane & 3;

    const int row = tid >> 1, colb = (tid & 1) * 32;   // halfs
    const __half* Ag = A  + (size_t)(bym + row) * lda + colb;
    const __half* Bg = Bt + (size_t)(bxn + row) * ldb + colb;
    const uint32_t adst = smem_u32(smh) + (uint32_t)(row * G_LDPH + colb) * 2;
    const uint32_t bdst = adst + 128 * G_LDPH * 2;

    float acc[4][4][4];
#pragma unroll
    for (int i = 0; i < 4; i++)
#pragma unroll
        for (int j = 0; j < 4; j++)
#pragma unroll
            for (int r = 0; r < 4; r++) acc[i][j][r] = 0.f;

    const int nst = K >> 6;                    // K-stage = 64 halfs

#pragma unroll
    for (int s = 0; s < 2; s++) {
        const __half* as = Ag + s * 64;
        const __half* bs = Bg + s * 64;
        const uint32_t ad = adst + s * G_STGH * 2;
        const uint32_t bd = bdst + s * G_STGH * 2;
#pragma unroll
        for (int j = 0; j < 4; j++) {
            cp16(ad + j * 16, as + j * 8);
            cp16(bd + j * 16, bs + j * 8);
        }
        asm volatile("cp.async.commit_group;" ::: "memory");
    }

    int buf = 0, nxt = 2;      // nxt = (it+2) % 3
    for (int it = 0; it < nst; ++it) {
        asm volatile("cp.async.wait_group 1;" ::: "memory");
        __syncthreads();
        const __half* a_s = smh + (size_t)buf * G_STGH + (wr * 64 + g) * G_LDPH;
        const __half* b_s = smh + (size_t)buf * G_STGH + 128 * G_LDPH + (wc * 32 + g) * G_LDPH;
#pragma unroll
        for (int ks = 0; ks < 4; ks++) {       // 4 x k16
            uint32_t av_[4][4], bv_[4][2];
#pragma unroll
            for (int mi = 0; mi < 4; mi++) {
                const __half* p = a_s + mi * 16 * G_LDPH + ks * 16 + qc * 2;
                av_[mi][0] = *(const uint32_t*)(p);
                av_[mi][1] = *(const uint32_t*)(p + 8 * G_LDPH);
                av_[mi][2] = *(const uint32_t*)(p + 8);
                av_[mi][3] = *(const uint32_t*)(p + 8 * G_LDPH + 8);
            }
#pragma unroll
            for (int ni = 0; ni < 4; ni++) {
                const __half* p = b_s + ni * 8 * G_LDPH + ks * 16 + qc * 2;
                bv_[ni][0] = *(const uint32_t*)(p);
                bv_[ni][1] = *(const uint32_t*)(p + 8);
            }
#pragma unroll
            for (int mi = 0; mi < 4; mi++)
#pragma unroll
                for (int ni = 0; ni < 4; ni++)
                    mma_f16(acc[mi][ni], av_[mi], bv_[ni]);
        }
        if (it + 2 < nst) {
            const int kt = it + 2;
            const __half* as = Ag + kt * 64;
            const __half* bs = Bg + kt * 64;
            const uint32_t ad = adst + nxt * G_STGH * 2;
            const uint32_t bd = bdst + nxt * G_STGH * 2;
#pragma unroll
            for (int j = 0; j < 4; j++) {
                cp16(ad + j * 16, as + j * 8);
                cp16(bd + j * 16, bs + j * 8);
            }
            asm volatile("cp.async.commit_group;" ::: "memory");
        }
        buf = (buf == 2) ? 0 : buf + 1;
        nxt = (nxt == 2) ? 0 : nxt + 1;
    }

#pragma unroll
    for (int mi = 0; mi < 4; mi++) {
        const int r = bym + wr * 64 + mi * 16 + g;
#pragma unroll
        for (int ni = 0; ni < 4; ni++) {
            const int col = bxn + wc * 32 + ni * 8 + qc * 2;
            float2 bv = make_float2(0.f, 0.f);
            if (BIAS) bv = *(const float2*)(bias + col);
            float2 v0, v1;
            v0.x = acc[mi][ni][0] + bv.x;
            v0.y = acc[mi][ni][1] + bv.y;
            v1.x = acc[mi][ni][2] + bv.x;
            v1.y = acc[mi][ni][3] + bv.y;
            if (RELU) {
                v0.x = fmaxf(v0.x, 0.f); v0.y = fmaxf(v0.y, 0.f);
                v1.x = fmaxf(v1.x, 0.f); v1.y = fmaxf(v1.y, 0.f);
            }
            if (HOUT) {
                __half* C = (__half*)Cv;
                *(__half2*)(C + (size_t)r * ldc + col)       = __floats2half2_rn(v0.x, v0.y);
                *(__half2*)(C + (size_t)(r + 8) * ldc + col) = __floats2half2_rn(v1.x, v1.y);
            } else {
                float* C = (float*)Cv;
                *(float2*)(C + (size_t)r * ldc + col)       = v0;
                *(float2*)(C + (size_t)(r + 8) * ldc + col) = v1;
            }
        }
    }
}

// ====================== flash attention (fp16 mma, online softmax) ===============
// Q/K/V half in, half out. S-fragment -> P A-fragment is a register-local repack
// (no shuffles). K-chunk = k16.
// smem (bytes): Q 18432 | K 2x18432 | V 2x17408 | masks 264
#define FLB_K  18432
#define FLB_V  55296
#define FLB_M  90112
#define FSMEM  (90112 + 264)

template<bool CAUSAL>
__global__ void __launch_bounds__(256, 1)
flash_k(const __half* __restrict__ Qg, const __half* __restrict__ Kg,
        const __half* __restrict__ Vg, const unsigned char* __restrict__ padg,
        __half* __restrict__ Og, int ldq, int ldk)
{
    extern __shared__ __half smh[];
    const int tid = threadIdx.x, lane = tid & 31, w = tid >> 5;
    const int g = lane >> 2, qc = lane & 3;
    const int qt = blockIdx.x;
    const int z = blockIdx.y, b = z >> 4, h = z & 15;

    const __half* Qp = Qg + (size_t)b * TT * ldq + h * 64;
    const __half* Kp = Kg + (size_t)b * TT * ldk + h * 64;
    const __half* Vp = Vg + ((size_t)b * CC + h * 64) * TT;
    const unsigned char* padp = padg + (size_t)b * TT;
    __half* Op = Og + (size_t)b * TT * CC + h * 64;

    const uint32_t sQa = smem_u32(smh);
    const uint32_t sKa = sQa + FLB_K;
    const uint32_t sVa = sQa + FLB_V;
    uint32_t* sMskp = (uint32_t*)((char*)smh + FLB_M);

    const int nkt = CAUSAL ? qt + 1 : (TT / 128);

    {   // Q tile: 128 rows x 64 halfs, rows padded to 72 halfs (144 B)
        const __half* qs = Qp + (size_t)(qt * 128 + (tid >> 1)) * ldq + (tid & 1) * 32;
        uint32_t qd = sQa + (tid >> 1) * 144 + (tid & 1) * 64;
#pragma unroll
        for (int j = 0; j < 4; j++) cp16(qd + j * 16, qs + j * 8);
    }
    auto issue_kv = [&](int kt, int buf) {
        const __half* ks = Kp + (size_t)(kt * 128 + (tid >> 1)) * ldk + (tid & 1) * 32;
        uint32_t kd = sKa + buf * 18432u + (tid >> 1) * 144 + (tid & 1) * 64;
#pragma unroll
        for (int j = 0; j < 4; j++) cp16(kd + j * 16, ks + j * 8);
        const __half* vs = Vp + (size_t)(tid >> 2) * TT + kt * 128 + (tid & 3) * 32;
        uint32_t vd = sVa + buf * 17408u + (tid >> 2) * 272 + (tid & 3) * 64;
#pragma unroll
        for (int j = 0; j < 4; j++) cp16(vd + j * 16, vs + j * 8);
        if (tid < 32) {
            uint32_t mv = *(const uint32_t*)(padp + (size_t)kt * 128 + tid * 4);
            sMskp[buf * 32 + tid] = mv;
            uint32_t f = __reduce_or_sync(0xffffffffu, mv);
            if (tid == 0) sMskp[64 + buf] = f;
        }
    };
    issue_kv(0, 0);
    asm volatile("cp.async.commit_group;" ::: "memory");

    float m0 = -INFINITY, m1 = -INFINITY, l0 = 0.f, l1 = 0.f;
    float oacc[8][4];
#pragma unroll
    for (int j = 0; j < 8; j++)
#pragma unroll
        for (int r = 0; r < 4; r++) oacc[j][r] = 0.f;

    const int r0 = w * 16 + g, r1 = r0 + 8;

    for (int kt = 0; kt < nkt; ++kt) {
        const int buf = kt & 1;
        if (kt + 1 < nkt) {
            issue_kv(kt + 1, buf ^ 1);
            asm volatile("cp.async.commit_group;" ::: "memory");
            asm volatile("cp.async.wait_group 1;" ::: "memory");
        } else {
            asm volatile("cp.async.wait_group 0;" ::: "memory");
        }
        __syncthreads();

        // ---- S = Q @ K^T (warp: 16 x 128), fp16 k16 ----
        uint32_t aq[4][4];
        {
            const __half* qr = smh + (size_t)(w * 16 + g) * 72;
#pragma unroll
            for (int ks = 0; ks < 4; ks++) {
                const __half* p = qr + ks * 16 + qc * 2;
                aq[ks][0] = *(const uint32_t*)(p);
                aq[ks][1] = *(const uint32_t*)(p + 8 * 72);
                aq[ks][2] = *(const uint32_t*)(p + 8);
                aq[ks][3] = *(const uint32_t*)(p + 8 * 72 + 8);
            }
        }
        float sacc[16][4];
#pragma unroll
        for (int ni = 0; ni < 16; ni++)
#pragma unroll
            for (int r = 0; r < 4; r++) sacc[ni][r] = 0.f;
        {
            const __half* kb = smh + (FLB_K / 2) + buf * 9216;
#pragma unroll
            for (int ks = 0; ks < 4; ks++)
#pragma unroll
                for (int ni = 0; ni < 16; ni++) {
                    const __half* kr = kb + (ni * 8 + g) * 72 + ks * 16 + qc * 2;
                    uint32_t bv[2] = { *(const uint32_t*)(kr), *(const uint32_t*)(kr + 8) };
                    mma_f16(sacc[ni], aq[ks], bv);
                }
        }

        // ---- scale + masks + row stats ----
        const uint32_t pf = sMskp[64 + buf];
        const unsigned char* mb = (const unsigned char*)(sMskp + buf * 32);
        float tm0 = -INFINITY, tm1 = -INFINITY;
#pragma unroll
        for (int ni = 0; ni < 16; ni++) {
            float s0 = sacc[ni][0] * 0.125f, s1 = sacc[ni][1] * 0.125f;
            float s2 = sacc[ni][2] * 0.125f, s3 = sacc[ni][3] * 0.125f;
            const int c0 = ni * 8 + qc * 2;
            if (CAUSAL && kt == qt) {
                if (c0     > r0) s0 = -INFINITY;
                if (c0 + 1 > r0) s1 = -INFINITY;
                if (c0     > r1) s2 = -INFINITY;
                if (c0 + 1 > r1) s3 = -INFINITY;
            }
            if (pf) {
                if (mb[c0])     { s0 = -INFINITY; s2 = -INFINITY; }
                if (mb[c0 + 1]) { s1 = -INFINITY; s3 = -INFINITY; }
            }
            sacc[ni][0] = s0; sacc[ni][1] = s1; sacc[ni][2] = s2; sacc[ni][3] = s3;
            tm0 = fmaxf(tm0, fmaxf(s0, s1));
            tm1 = fmaxf(tm1, fmaxf(s2, s3));
        }
        tm0 = fmaxf(tm0, __shfl_xor_sync(0xffffffffu, tm0, 1));
        tm0 = fmaxf(tm0, __shfl_xor_sync(0xffffffffu, tm0, 2));
        tm1 = fmaxf(tm1, __shfl_xor_sync(0xffffffffu, tm1, 1));
        tm1 = fmaxf(tm1, __shfl_xor_sync(0xffffffffu, tm1, 2));
        const float mn0 = fmaxf(m0, tm0), mn1 = fmaxf(m1, tm1);

        float sum0 = 0.f, sum1 = 0.f;
#pragma unroll
        for (int ni = 0; ni < 16; ni++) {
            float p0 = __expf(sacc[ni][0] - mn0);
            float p1 = __expf(sacc[ni][1] - mn0);
            float p2 = __expf(sacc[ni][2] - mn1);
            float p3 = __expf(sacc[ni][3] - mn1);
            sacc[ni][0] = p0; sacc[ni][1] = p1; sacc[ni][2] = p2; sacc[ni][3] = p3;
            sum0 += p0 + p1; sum1 += p2 + p3;
        }
        sum0 += __shfl_xor_sync(0xffffffffu, sum0, 1);
        sum0 += __shfl_xor_sync(0xffffffffu, sum0, 2);
        sum1 += __shfl_xor_sync(0xffffffffu, sum1, 1);
        sum1 += __shfl_xor_sync(0xffffffffu, sum1, 2);

        const float sc0 = __expf(m0 - mn0), sc1 = __expf(m1 - mn1);
        l0 = l0 * sc0 + sum0;  l1 = l1 * sc1 + sum1;
        m0 = mn0;  m1 = mn1;
#pragma unroll
        for (int nj = 0; nj < 8; nj++) {
            oacc[nj][0] *= sc0; oacc[nj][1] *= sc0;
            oacc[nj][2] *= sc1; oacc[nj][3] *= sc1;
        }

        // ---- O += P @ V: S C-fragment repacks DIRECTLY into P A-fragment ----
        {
            const __half* vb = smh + (FLB_V / 2) + buf * 8704;
#pragma unroll
            for (int k2 = 0; k2 < 8; k2++) {
                uint32_t pa[4];
                pa[0] = packh2(sacc[2 * k2][0],     sacc[2 * k2][1]);
                pa[1] = packh2(sacc[2 * k2][2],     sacc[2 * k2][3]);
                pa[2] = packh2(sacc[2 * k2 + 1][0], sacc[2 * k2 + 1][1]);
                pa[3] = packh2(sacc[2 * k2 + 1][2], sacc[2 * k2 + 1][3]);
#pragma unroll
                for (int nj = 0; nj < 8; nj++) {
                    const __half* vr = vb + (nj * 8 + g) * 136 + k2 * 16 + qc * 2;
                    uint32_t bv[2] = { *(const uint32_t*)(vr), *(const uint32_t*)(vr + 8) };
                    mma_f16(oacc[nj], pa, bv);
                }
            }
        }
        __syncthreads();
    }

    const float inv0 = 1.f / l0, inv1 = 1.f / l1;
    __half* orow0 = Op + (size_t)(qt * 128 + r0) * CC;
    __half* orow1 = orow0 + 8 * CC;
#pragma unroll
    for (int nj = 0; nj < 8; nj++) {
        *(__half2*)(orow0 + nj * 8 + qc * 2) =
            __floats2half2_rn(oacc[nj][0] * inv0, oacc[nj][1] * inv0);
        *(__half2*)(orow1 + nj * 8 + qc * 2) =
            __floats2half2_rn(oacc[nj][2] * inv1, oacc[nj][3] * inv1);
    }
}

// ============================ layernorm ==========================================
__device__ __forceinline__ float warpSum(float v) {
#pragma unroll
    for (int o = 16; o; o >>= 1) v += __shfl_xor_sync(0xffffffffu, v, o);
    return v;
}

template<bool DUALH>
__global__ void __launch_bounds__(256)
add_ln(const float* __restrict__ X, const float* __restrict__ R,
       const float* __restrict__ g, const float* __restrict__ be,
       float* __restrict__ out, __half* __restrict__ outh)
{
    const size_t row = blockIdx.x;
    const int tid = threadIdx.x;
    const int col = tid * 4;
    float4 xv = *(const float4*)(X + row * CC + col);
    float4 rv = *(const float4*)(R + row * CC + col);
    float4 v;
    v.x = xv.x + rv.x; v.y = xv.y + rv.y; v.z = xv.z + rv.z; v.w = xv.w + rv.w;

    __shared__ float sh1[8], sh2[8];
    float s = (v.x + v.y) + (v.z + v.w);
    float sq = v.x * v.x + v.y * v.y + v.z * v.z + v.w * v.w;
    s = warpSum(s); sq = warpSum(sq);
    if ((tid & 31) == 0) { sh1[tid >> 5] = s; sh2[tid >> 5] = sq; }
    __syncthreads();
    s  = (sh1[0] + sh1[1]) + (sh1[2] + sh1[3]) + (sh1[4] + sh1[5]) + (sh1[6] + sh1[7]);
    sq = (sh2[0] + sh2[1]) + (sh2[2] + sh2[3]) + (sh2[4] + sh2[5]) + (sh2[6] + sh2[7]);
    const float mean = s * (1.0f / CC);
    const float var = sq * (1.0f / CC) - mean * mean;
    const float rstd = rsqrtf(var + 1e-5f);

    float4 gg = *(const float4*)(g + col);
    float4 bb = *(const float4*)(be + col);
    float4 o;
    o.x = (v.x - mean) * rstd * gg.x + bb.x;
    o.y = (v.y - mean) * rstd * gg.y + bb.y;
    o.z = (v.z - mean) * rstd * gg.z + bb.z;
    o.w = (v.w - mean) * rstd * gg.w + bb.w;
    *(float4*)(out + row * CC + col) = o;
    if (DUALH) {
        *(__half2*)(outh + row * CC + col)     = __floats2half2_rn(o.x, o.y);
        *(__half2*)(outh + row * CC + col + 2) = __floats2half2_rn(o.z, o.w);
    }
}

// ------------------------------- launcher ---------------------------------------
extern "C" void kernel_launch(void* const* d_in, const int* in_sizes, int n_in,
                              void* d_out, int out_size)
{
    const float* x    = (const float*)d_in[0];
    const float* enc  = (const float*)d_in[1];
    const unsigned char* tmask = (const unsigned char*)d_in[2];
    const unsigned char* smask = (const unsigned char*)d_in[3];
    const float* Wq1 = (const float*)d_in[4];
    const float* Wk1 = (const float*)d_in[5];
    const float* Wv1 = (const float*)d_in[6];
    const float* Wo1 = (const float*)d_in[7];
    const float* ln1g = (const float*)d_in[8];
    const float* ln1b = (const float*)d_in[9];
    const float* Wq2 = (const float*)d_in[10];
    const float* Wk2 = (const float*)d_in[11];
    const float* Wv2 = (const float*)d_in[12];
    const float* Wo2 = (const float*)d_in[13];
    const float* ln2g = (const float*)d_in[14];
    const float* ln2b = (const float*)d_in[15];
    const float* Wf1 = (const float*)d_in[16];
    const float* bf1 = (const float*)d_in[17];
    const float* Wf2 = (const float*)d_in[18];
    const float* bf2 = (const float*)d_in[19];
    const float* ln3g = (const float*)d_in[20];
    const float* ln3b = (const float*)d_in[21];
    float* out = (float*)d_out;

    float *go, *gx1, *gx2;
    __half *gxh, *geh, *gqh, *gvth, *gctxh, *gx1h, *gx2h, *gffh, *gwth;
    cudaGetSymbolAddress((void**)&go,  g_o);
    cudaGetSymbolAddress((void**)&gx1, g_x1);
    cudaGetSymbolAddress((void**)&gx2, g_x2);
    cudaGetSymbolAddress((void**)&gxh, g_xh);
    cudaGetSymbolAddress((void**)&geh, g_eh);
    cudaGetSymbolAddress((void**)&gqh, g_qh);
    cudaGetSymbolAddress((void**)&gvth, g_vth);
    cudaGetSymbolAddress((void**)&gctxh, g_ctxh);
    cudaGetSymbolAddress((void**)&gx1h, g_x1h);
    cudaGetSymbolAddress((void**)&gx2h, g_x2h);
    cudaGetSymbolAddress((void**)&gffh, g_ffh);
    cudaGetSymbolAddress((void**)&gwth, g_wth);

    __half* tq1 = gwth + 0u * 1048576u;   // tq1,tk1,tv1 contiguous -> [3072,1024]
    __half* tk1 = gwth + 1u * 1048576u;
    __half* tv1 = gwth + 2u * 1048576u;
    __half* to1 = gwth + 3u * 1048576u;
    __half* tq2 = gwth + 4u * 1048576u;
    __half* tk2 = gwth + 5u * 1048576u;   // tk2,tv2 contiguous -> [2048,1024]
    __half* tv2 = gwth + 6u * 1048576u;
    __half* to2 = gwth + 7u * 1048576u;
    __half* tf1 = gwth + 8u * 1048576u;              // [F, C]
    __half* tf2 = gwth + 8u * 1048576u + 4194304u;   // [C, F]

    auto* kProj  = gemm_mma<false, false, false>;   // fp32 out (-> add_ln)
    auto* kProjH = gemm_mma<false, false, true >;   // half out (-> flash / GEMM-A)
    auto* kFfn1  = gemm_mma<true,  true,  true >;   // bias+relu, half out
    auto* kFfn2  = gemm_mma<true,  false, false>;
    cudaFuncSetAttribute(kProj,  cudaFuncAttributeMaxDynamicSharedMemorySize, GSMEM);
    cudaFuncSetAttribute(kProjH, cudaFuncAttributeMaxDynamicSharedMemorySize, GSMEM);
    cudaFuncSetAttribute(kFfn1,  cudaFuncAttributeMaxDynamicSharedMemorySize, GSMEM);
    cudaFuncSetAttribute(kFfn2,  cudaFuncAttributeMaxDynamicSharedMemorySize, GSMEM);
    cudaFuncSetAttribute(flash_k<true>,  cudaFuncAttributeMaxDynamicSharedMemorySize, FSMEM);
    cudaFuncSetAttribute(flash_k<false>, cudaFuncAttributeMaxDynamicSharedMemorySize, FSMEM);

    const dim3 blk(256);
    const dim3 tblk(32, 8);

    // ---- fp16 conversion of external GEMM-A inputs (1 launch) ----
    Ptr2h p2;
    p2.s[0] = x;   p2.d[0] = gxh;
    p2.s[1] = enc; p2.d[1] = geh;
    round2h<<<dim3(MM * CC / 1024, 2), blk>>>(p2);

    // ---- weight transposes (K-major, fp16 B operands) ----
    Ptr8h p8;
    p8.s[0] = Wq1; p8.d[0] = tq1;  p8.s[1] = Wk1; p8.d[1] = tk1;
    p8.s[2] = Wv1; p8.d[2] = tv1;  p8.s[3] = Wo1; p8.d[3] = to1;
    p8.s[4] = Wq2; p8.d[4] = tq2;  p8.s[5] = Wk2; p8.d[5] = tk2;
    p8.s[6] = Wv2; p8.d[6] = tv2;  p8.s[7] = Wo2; p8.d[7] = to2;
    transpose8h<<<dim3(CC/32, CC/32, 8), tblk>>>(p8);
    transpose_kh<<<dim3(FF/32, CC/32), tblk>>>(Wf1, tf1, CC, FF);
    transpose_kh<<<dim3(CC/32, FF/32), tblk>>>(Wf2, tf2, FF, CC);

    const dim3 gQKV(3072/128, MM/128);   // (24, 32) fused self QKV
    const dim3 gKV (2048/128, MM/128);   // (16, 32) fused cross KV
    const dim3 gP  (CC/128,   MM/128);   // (8, 32)
    const dim3 gF1 (FF/128,   MM/128);   // (32, 32)
    const dim3 gFl (TT/128, BB*HH);      // (8, 64)
    const dim3 gVt (CC/32, TT/32, BB);
    const int nLn = MM;

    // ---- self-attention (causal) ----
    kProjH<<<gQKV, blk, GSMEM>>>(gxh, tq1, nullptr, gffh, CC, CC, CC, 3072);
    transpose_vh<<<gVt, tblk>>>(gffh + 2048, gvth, 3072);
    flash_k<true><<<gFl, blk, FSMEM>>>(gffh, gffh + 1024, gvth, tmask, gctxh, 3072, 3072);
    kProj<<<gP, blk, GSMEM>>>(gctxh, to1, nullptr, go, CC, CC, CC, CC);
    add_ln<true><<<nLn, blk>>>(x, go, ln1g, ln1b, gx1, gx1h);

    // ---- cross-attention ----
    kProjH<<<gP,  blk, GSMEM>>>(gx1h, tq2, nullptr, gqh, CC, CC, CC, CC);
    kProjH<<<gKV, blk, GSMEM>>>(geh, tk2, nullptr, gffh, CC, CC, CC, 2048);
    transpose_vh<<<gVt, tblk>>>(gffh + 1024, gvth, 2048);
    flash_k<false><<<gFl, blk, FSMEM>>>(gqh, gffh, gvth, smask, gctxh, CC, 2048);
    kProj<<<gP, blk, GSMEM>>>(gctxh, to2, nullptr, go, CC, CC, CC, CC);
    add_ln<true><<<nLn, blk>>>(gx1, go, ln2g, ln2b, gx2, gx2h);

    // ---- FFN ----
    kFfn1<<<gF1, blk, GSMEM>>>(gx2h, tf1, bf1, gffh, CC, CC, CC, FF);
    kFfn2<<<gP,  blk, GSMEM>>>(gffh, tf2, bf2, go, FF, FF, FF, CC);
    add_ln<false><<<nLn, blk>>>(gx2, go, ln3g, ln3b, out, nullptr);
}

// round 11
// speedup vs baseline: 2.2066x; 1.0942x over previous
#include <cuda_runtime.h>
#include <cuda_fp16.h>
#include <cstdint>
#include <cstddef>

// Problem constants
#define BB 4
#define TT 1024
#define CC 1024
#define HH 16
#define DH 64
#define FF 4096
#define MM (BB*TT)          // 4096 rows

// ---------------- scratch (device globals; no allocation allowed) ----------------
__device__ float  g_o  [(size_t)MM*CC];        // GEMM fp32 outputs (pre-LN)
__device__ float  g_x1 [(size_t)MM*CC];
__device__ float  g_x2 [(size_t)MM*CC];
__device__ __half g_xh [(size_t)MM*CC];        // half GEMM-A operands
__device__ __half g_eh [(size_t)MM*CC];
__device__ __half g_qh [(size_t)MM*CC];        // cross-attn Q (half, flash input)
__device__ __half g_vth[(size_t)MM*CC];        // V^T per batch: [B][C][T] half
__device__ __half g_ctxh[(size_t)MM*CC];
__device__ __half g_x1h[(size_t)MM*CC];
__device__ __half g_x2h[(size_t)MM*CC];
__device__ __half g_ffh[(size_t)MM*FF];        // QKV / KV / FFN1 half outputs
__device__ __half g_wth[8u*1024u*1024u + 2u*4096u*1024u];   // half weights (K-major)

// ============================ small helpers ======================================
__device__ __forceinline__ void mma_f16(float* d, const uint32_t* a, const uint32_t* b) {
    asm volatile(
        "mma.sync.aligned.m16n8k16.row.col.f32.f16.f16.f32 "
        "{%0,%1,%2,%3},{%4,%5,%6,%7},{%8,%9},{%0,%1,%2,%3};"
        : "+f"(d[0]), "+f"(d[1]), "+f"(d[2]), "+f"(d[3])
        : "r"(a[0]), "r"(a[1]), "r"(a[2]), "r"(a[3]),
          "r"(b[0]), "r"(b[1]));
}
__device__ __forceinline__ void ldsm4(uint32_t* r, uint32_t addr) {
    asm volatile("ldmatrix.sync.aligned.m8n8.x4.shared.b16 {%0,%1,%2,%3}, [%4];"
                 : "=r"(r[0]), "=r"(r[1]), "=r"(r[2]), "=r"(r[3]) : "r"(addr));
}
__device__ __forceinline__ uint32_t smem_u32(const void* p) {
    uint32_t a;
    asm("{ .reg .u64 t; cvta.to.shared.u64 t, %1; cvt.u32.u64 %0, t; }" : "=r"(a) : "l"(p));
    return a;
}
__device__ __forceinline__ void cp16(uint32_t dst, const void* src) {
    asm volatile("cp.async.cg.shared.global [%0], [%1], 16;" :: "r"(dst), "l"(src));
}
__device__ __forceinline__ uint32_t packh2(float a, float b) {
    __half2 h = __floats2half2_rn(a, b);
    return *(uint32_t*)&h;
}

// =================== fp16 conversion copy (2 tensors, z-batched) =================
struct Ptr2h { const float* s[2]; __half* d[2]; };
__global__ void __launch_bounds__(256)
round2h(Ptr2h p)
{
    const float* in = p.s[blockIdx.y];
    __half* out = p.d[blockIdx.y];
    const size_t i = ((size_t)blockIdx.x * 256 + threadIdx.x) * 4;
    float4 v = *(const float4*)(in + i);
    *(__half2*)(out + i)     = __floats2half2_rn(v.x, v.y);
    *(__half2*)(out + i + 2) = __floats2half2_rn(v.z, v.w);
}

// ====================== 32x32 tiled transposes (fp16 out) ========================
struct Ptr8h { const float* s[8]; __half* d[8]; };

__global__ void __launch_bounds__(256)
transpose8h(Ptr8h ps)   // 8 square [CC x CC] weights, z selects matrix
{
    const float* in = ps.s[blockIdx.z];
    __half* out = ps.d[blockIdx.z];
    __shared__ float t[32][33];
    const int bx = blockIdx.x * 32, by = blockIdx.y * 32;
    int x = bx + threadIdx.x;
#pragma unroll
    for (int i = 0; i < 32; i += 8)
        t[threadIdx.y + i][threadIdx.x] = in[(size_t)(by + threadIdx.y + i) * CC + x];
    __syncthreads();
    x = by + threadIdx.x;
#pragma unroll
    for (int i = 0; i < 32; i += 8)
        out[(size_t)(bx + threadIdx.y + i) * CC + x] = __float2half_rn(t[threadIdx.x][threadIdx.y + i]);
}

__global__ void __launch_bounds__(256)
transpose_kh(const float* __restrict__ in, __half* __restrict__ out, int R, int C)
{
    __shared__ float t[32][33];
    const int bx = blockIdx.x * 32, by = blockIdx.y * 32;
    int x = bx + threadIdx.x;
#pragma unroll
    for (int i = 0; i < 32; i += 8)
        t[threadIdx.y + i][threadIdx.x] = in[(size_t)(by + threadIdx.y + i) * C + x];
    __syncthreads();
    x = by + threadIdx.x;
#pragma unroll
    for (int i = 0; i < 32; i += 8)
        out[(size_t)(bx + threadIdx.y + i) * R + x] = __float2half_rn(t[threadIdx.x][threadIdx.y + i]);
}

// extract + transpose V block out of a packed [B*T, ldin] half buffer -> [B][C][T]
__global__ void __launch_bounds__(256)
transpose_vh(const __half* __restrict__ in, __half* __restrict__ out, int ldin)
{
    in  += (size_t)blockIdx.z * TT * ldin;
    out += (size_t)blockIdx.z * CC * TT;
    __shared__ __half t[32][40];
    const int bx = blockIdx.x * 32, by = blockIdx.y * 32;   // bx: C dim, by: T dim
#pragma unroll
    for (int i = 0; i < 32; i += 8)
        t[threadIdx.y + i][threadIdx.x] =
            in[(size_t)(by + threadIdx.y + i) * ldin + bx + threadIdx.x];
    __syncthreads();
#pragma unroll
    for (int i = 0; i < 32; i += 8)
        out[(size_t)(bx + threadIdx.y + i) * TT + by + threadIdx.x] =
            t[threadIdx.x][threadIdx.y + i];
}

// ================= fp16 mma.sync GEMM: C[M,N] = A[M,K] @ Bt[N,K]^T ===============
// R10 structure; fragment loads via ldmatrix.x4 (LDSM).
#define G_LDPH 72                            // halfs per row (64 data + 8 pad)
#define G_STGH (256 * G_LDPH)                // halfs per stage (A128 + B128 rows)
#define GSMEM  (3 * G_STGH * 2)              // 110592 bytes

template<bool BIAS, bool RELU, bool HOUT>
__global__ void __launch_bounds__(256, 2)
gemm_mma(const __half* __restrict__ A, const __half* __restrict__ Bt,
         const float* __restrict__ bias, void* __restrict__ Cv,
         int K, int lda, int ldb, int ldc)
{
    extern __shared__ __half smh[];
    const int bxn = blockIdx.x * 128, bym = blockIdx.y * 128;
    const int tid = threadIdx.x, wid = tid >> 5, lane = tid & 31;
    const int wr = wid >> 2, wc = wid & 3;      // 2 x 4 warps, 64x32 each
    const int g = lane >> 2, qc = lane & 3;

    const int row = tid >> 1, colb = (tid & 1) * 32;   // halfs
    const __half* Ag = A  + (size_t)(bym + row) * lda + colb;
    const __half* Bg = Bt + (size_t)(bxn + row) * ldb + colb;
    const uint32_t smb = smem_u32(smh);
    const uint32_t adst = smb + (uint32_t)(row * G_LDPH + colb) * 2;
    const uint32_t bdst = adst + 128 * G_LDPH * 2;

    // ldmatrix lane addresses (bytes)
    const int l15 = lane & 15, l7 = lane & 7;
    const uint32_t aL = smb
        + (uint32_t)(((wr * 64 + l15) * G_LDPH + (lane >> 4) * 8) * 2);
    const uint32_t bL = smb + 128 * G_LDPH * 2
        + (uint32_t)(((wc * 32 + l7 + (lane >> 4) * 8) * G_LDPH + ((lane >> 3) & 1) * 8) * 2);

    float acc[4][4][4];
#pragma unroll
    for (int i = 0; i < 4; i++)
#pragma unroll
        for (int j = 0; j < 4; j++)
#pragma unroll
            for (int r = 0; r < 4; r++) acc[i][j][r] = 0.f;

    const int nst = K >> 6;                    // K-stage = 64 halfs

#pragma unroll
    for (int s = 0; s < 2; s++) {
        const __half* as = Ag + s * 64;
        const __half* bs = Bg + s * 64;
        const uint32_t ad = adst + s * G_STGH * 2;
        const uint32_t bd = bdst + s * G_STGH * 2;
#pragma unroll
        for (int j = 0; j < 4; j++) {
            cp16(ad + j * 16, as + j * 8);
            cp16(bd + j * 16, bs + j * 8);
        }
        asm volatile("cp.async.commit_group;" ::: "memory");
    }

    int buf = 0, nxt = 2;      // nxt = (it+2) % 3
    for (int it = 0; it < nst; ++it) {
        asm volatile("cp.async.wait_group 1;" ::: "memory");
        __syncthreads();
        const uint32_t aB = aL + (uint32_t)buf * G_STGH * 2;
        const uint32_t bB = bL + (uint32_t)buf * G_STGH * 2;
#pragma unroll
        for (int ks = 0; ks < 4; ks++) {       // 4 x k16
            uint32_t av_[4][4], bv_[2][4];
#pragma unroll
            for (int mi = 0; mi < 4; mi++)
                ldsm4(av_[mi], aB + mi * (16 * G_LDPH * 2) + ks * 32);
#pragma unroll
            for (int np = 0; np < 2; np++)
                ldsm4(bv_[np], bB + np * (16 * G_LDPH * 2) + ks * 32);
#pragma unroll
            for (int mi = 0; mi < 4; mi++)
#pragma unroll
                for (int ni = 0; ni < 4; ni++)
                    mma_f16(acc[mi][ni], av_[mi], &bv_[ni >> 1][(ni & 1) * 2]);
        }
        if (it + 2 < nst) {
            const int kt = it + 2;
            const __half* as = Ag + kt * 64;
            const __half* bs = Bg + kt * 64;
            const uint32_t ad = adst + nxt * G_STGH * 2;
            const uint32_t bd = bdst + nxt * G_STGH * 2;
#pragma unroll
            for (int j = 0; j < 4; j++) {
                cp16(ad + j * 16, as + j * 8);
                cp16(bd + j * 16, bs + j * 8);
            }
            asm volatile("cp.async.commit_group;" ::: "memory");
        }
        buf = (buf == 2) ? 0 : buf + 1;
        nxt = (nxt == 2) ? 0 : nxt + 1;
    }

#pragma unroll
    for (int mi = 0; mi < 4; mi++) {
        const int r = bym + wr * 64 + mi * 16 + g;
#pragma unroll
        for (int ni = 0; ni < 4; ni++) {
            const int col = bxn + wc * 32 + ni * 8 + qc * 2;
            float2 bv = make_float2(0.f, 0.f);
            if (BIAS) bv = *(const float2*)(bias + col);
            float2 v0, v1;
            v0.x = acc[mi][ni][0] + bv.x;
            v0.y = acc[mi][ni][1] + bv.y;
            v1.x = acc[mi][ni][2] + bv.x;
            v1.y = acc[mi][ni][3] + bv.y;
            if (RELU) {
                v0.x = fmaxf(v0.x, 0.f); v0.y = fmaxf(v0.y, 0.f);
                v1.x = fmaxf(v1.x, 0.f); v1.y = fmaxf(v1.y, 0.f);
            }
            if (HOUT) {
                __half* C = (__half*)Cv;
                *(__half2*)(C + (size_t)r * ldc + col)       = __floats2half2_rn(v0.x, v0.y);
                *(__half2*)(C + (size_t)(r + 8) * ldc + col) = __floats2half2_rn(v1.x, v1.y);
            } else {
                float* C = (float*)Cv;
                *(float2*)(C + (size_t)r * ldc + col)       = v0;
                *(float2*)(C + (size_t)(r + 8) * ldc + col) = v1;
            }
        }
    }
}

// ====================== flash attention (fp16 mma, ldmatrix) =====================
// smem (bytes): Q 18432 | K 2x18432 | V 2x17408 | masks 264
#define FLB_K  18432
#define FLB_V  55296
#define FLB_M  90112
#define FSMEM  (90112 + 264)

template<bool CAUSAL>
__global__ void __launch_bounds__(256, 1)
flash_k(const __half* __restrict__ Qg, const __half* __restrict__ Kg,
        const __half* __restrict__ Vg, const unsigned char* __restrict__ padg,
        __half* __restrict__ Og, int ldq, int ldk)
{
    extern __shared__ __half smh[];
    const int tid = threadIdx.x, lane = tid & 31, w = tid >> 5;
    const int g = lane >> 2, qc = lane & 3;
    const int qt = blockIdx.x;
    const int z = blockIdx.y, b = z >> 4, h = z & 15;

    const __half* Qp = Qg + (size_t)b * TT * ldq + h * 64;
    const __half* Kp = Kg + (size_t)b * TT * ldk + h * 64;
    const __half* Vp = Vg + ((size_t)b * CC + h * 64) * TT;
    const unsigned char* padp = padg + (size_t)b * TT;
    __half* Op = Og + (size_t)b * TT * CC + h * 64;

    const uint32_t sQa = smem_u32(smh);
    const uint32_t sKa = sQa + FLB_K;
    const uint32_t sVa = sQa + FLB_V;
    uint32_t* sMskp = (uint32_t*)((char*)smh + FLB_M);

    // ldmatrix lane addresses (bytes)
    const int l15 = lane & 15, l7 = lane & 7;
    const uint32_t qL = sQa + (uint32_t)(((w * 16 + l15) * 72 + (lane >> 4) * 8) * 2);
    const uint32_t kL = sKa + (uint32_t)(((l7 + (lane >> 4) * 8) * 72 + ((lane >> 3) & 1) * 8) * 2);
    const uint32_t vL = sVa + (uint32_t)(((l7 + (lane >> 4) * 8) * 136 + ((lane >> 3) & 1) * 8) * 2);

    const int nkt = CAUSAL ? qt + 1 : (TT / 128);

    {   // Q tile: 128 rows x 64 halfs, rows padded to 72 halfs (144 B)
        const __half* qs = Qp + (size_t)(qt * 128 + (tid >> 1)) * ldq + (tid & 1) * 32;
        uint32_t qd = sQa + (tid >> 1) * 144 + (tid & 1) * 64;
#pragma unroll
        for (int j = 0; j < 4; j++) cp16(qd + j * 16, qs + j * 8);
    }
    auto issue_kv = [&](int kt, int buf) {
        const __half* ks = Kp + (size_t)(kt * 128 + (tid >> 1)) * ldk + (tid & 1) * 32;
        uint32_t kd = sKa + buf * 18432u + (tid >> 1) * 144 + (tid & 1) * 64;
#pragma unroll
        for (int j = 0; j < 4; j++) cp16(kd + j * 16, ks + j * 8);
        const __half* vs = Vp + (size_t)(tid >> 2) * TT + kt * 128 + (tid & 3) * 32;
        uint32_t vd = sVa + buf * 17408u + (tid >> 2) * 272 + (tid & 3) * 64;
#pragma unroll
        for (int j = 0; j < 4; j++) cp16(vd + j * 16, vs + j * 8);
        if (tid < 32) {
            uint32_t mv = *(const uint32_t*)(padp + (size_t)kt * 128 + tid * 4);
            sMskp[buf * 32 + tid] = mv;
            uint32_t f = __reduce_or_sync(0xffffffffu, mv);
            if (tid == 0) sMskp[64 + buf] = f;
        }
    };
    issue_kv(0, 0);
    asm volatile("cp.async.commit_group;" ::: "memory");

    float m0 = -INFINITY, m1 = -INFINITY, l0 = 0.f, l1 = 0.f;
    float oacc[8][4];
#pragma unroll
    for (int j = 0; j < 8; j++)
#pragma unroll
        for (int r = 0; r < 4; r++) oacc[j][r] = 0.f;

    const int r0 = w * 16 + g, r1 = r0 + 8;

    for (int kt = 0; kt < nkt; ++kt) {
        const int buf = kt & 1;
        if (kt + 1 < nkt) {
            issue_kv(kt + 1, buf ^ 1);
            asm volatile("cp.async.commit_group;" ::: "memory");
            asm volatile("cp.async.wait_group 1;" ::: "memory");
        } else {
            asm volatile("cp.async.wait_group 0;" ::: "memory");
        }
        __syncthreads();

        // ---- S = Q @ K^T (warp: 16 x 128), fp16 k16, ldmatrix ----
        float sacc[16][4];
#pragma unroll
        for (int ni = 0; ni < 16; ni++)
#pragma unroll
            for (int r = 0; r < 4; r++) sacc[ni][r] = 0.f;
        {
            const uint32_t kB = kL + buf * 18432u;
#pragma unroll
            for (int ks = 0; ks < 4; ks++) {
                uint32_t aq[4];
                ldsm4(aq, qL + ks * 32);
#pragma unroll
                for (int np = 0; np < 8; np++) {
                    uint32_t kv4[4];
                    ldsm4(kv4, kB + np * (16 * 144) + ks * 32);
                    mma_f16(sacc[2 * np],     aq, kv4);
                    mma_f16(sacc[2 * np + 1], aq, kv4 + 2);
                }
            }
        }

        // ---- scale + masks + row stats ----
        const uint32_t pf = sMskp[64 + buf];
        const unsigned char* mb = (const unsigned char*)(sMskp + buf * 32);
        float tm0 = -INFINITY, tm1 = -INFINITY;
#pragma unroll
        for (int ni = 0; ni < 16; ni++) {
            float s0 = sacc[ni][0] * 0.125f, s1 = sacc[ni][1] * 0.125f;
            float s2 = sacc[ni][2] * 0.125f, s3 = sacc[ni][3] * 0.125f;
            const int c0 = ni * 8 + qc * 2;
            if (CAUSAL && kt == qt) {
                if (c0     > r0) s0 = -INFINITY;
                if (c0 + 1 > r0) s1 = -INFINITY;
                if (c0     > r1) s2 = -INFINITY;
                if (c0 + 1 > r1) s3 = -INFINITY;
            }
            if (pf) {
                if (mb[c0])     { s0 = -INFINITY; s2 = -INFINITY; }
                if (mb[c0 + 1]) { s1 = -INFINITY; s3 = -INFINITY; }
            }
            sacc[ni][0] = s0; sacc[ni][1] = s1; sacc[ni][2] = s2; sacc[ni][3] = s3;
            tm0 = fmaxf(tm0, fmaxf(s0, s1));
            tm1 = fmaxf(tm1, fmaxf(s2, s3));
        }
        tm0 = fmaxf(tm0, __shfl_xor_sync(0xffffffffu, tm0, 1));
        tm0 = fmaxf(tm0, __shfl_xor_sync(0xffffffffu, tm0, 2));
        tm1 = fmaxf(tm1, __shfl_xor_sync(0xffffffffu, tm1, 1));
        tm1 = fmaxf(tm1, __shfl_xor_sync(0xffffffffu, tm1, 2));
        const float mn0 = fmaxf(m0, tm0), mn1 = fmaxf(m1, tm1);

        float sum0 = 0.f, sum1 = 0.f;
#pragma unroll
        for (int ni = 0; ni < 16; ni++) {
            float p0 = __expf(sacc[ni][0] - mn0);
            float p1 = __expf(sacc[ni][1] - mn0);
            float p2 = __expf(sacc[ni][2] - mn1);
            float p3 = __expf(sacc[ni][3] - mn1);
            sacc[ni][0] = p0; sacc[ni][1] = p1; sacc[ni][2] = p2; sacc[ni][3] = p3;
            sum0 += p0 + p1; sum1 += p2 + p3;
        }
        sum0 += __shfl_xor_sync(0xffffffffu, sum0, 1);
        sum0 += __shfl_xor_sync(0xffffffffu, sum0, 2);
        sum1 += __shfl_xor_sync(0xffffffffu, sum1, 1);
        sum1 += __shfl_xor_sync(0xffffffffu, sum1, 2);

        const float sc0 = __expf(m0 - mn0), sc1 = __expf(m1 - mn1);
        l0 = l0 * sc0 + sum0;  l1 = l1 * sc1 + sum1;
        m0 = mn0;  m1 = mn1;
#pragma unroll
        for (int nj = 0; nj < 8; nj++) {
            oacc[nj][0] *= sc0; oacc[nj][1] *= sc0;
            oacc[nj][2] *= sc1; oacc[nj][3] *= sc1;
        }

        // ---- O += P @ V: S-fragment repack + ldmatrix V ----
        {
            const uint32_t vB = vL + buf * 17408u;
#pragma unroll
            for (int k2 = 0; k2 < 8; k2++) {
                uint32_t pa[4];
                pa[0] = packh2(sacc[2 * k2][0],     sacc[2 * k2][1]);
                pa[1] = packh2(sacc[2 * k2][2],     sacc[2 * k2][3]);
                pa[2] = packh2(sacc[2 * k2 + 1][0], sacc[2 * k2 + 1][1]);
                pa[3] = packh2(sacc[2 * k2 + 1][2], sacc[2 * k2 + 1][3]);
#pragma unroll
                for (int np = 0; np < 4; np++) {
                    uint32_t vv[4];
                    ldsm4(vv, vB + np * (16 * 272) + k2 * 32);
                    mma_f16(oacc[2 * np],     pa, vv);
                    mma_f16(oacc[2 * np + 1], pa, vv + 2);
                }
            }
        }
        __syncthreads();
    }

    const float inv0 = 1.f / l0, inv1 = 1.f / l1;
    __half* orow0 = Op + (size_t)(qt * 128 + r0) * CC;
    __half* orow1 = orow0 + 8 * CC;
#pragma unroll
    for (int nj = 0; nj < 8; nj++) {
        *(__half2*)(orow0 + nj * 8 + qc * 2) =
            __floats2half2_rn(oacc[nj][0] * inv0, oacc[nj][1] * inv0);
        *(__half2*)(orow1 + nj * 8 + qc * 2) =
            __floats2half2_rn(oacc[nj][2] * inv1, oacc[nj][3] * inv1);
    }
}

// ============================ layernorm ==========================================
__device__ __forceinline__ float warpSum(float v) {
#pragma unroll
    for (int o = 16; o; o >>= 1) v += __shfl_xor_sync(0xffffffffu, v, o);
    return v;
}

template<bool DUALH>
__global__ void __launch_bounds__(256)
add_ln(const float* __restrict__ X, const float* __restrict__ R,
       const float* __restrict__ g, const float* __restrict__ be,
       float* __restrict__ out, __half* __restrict__ outh)
{
    const size_t row = blockIdx.x;
    const int tid = threadIdx.x;
    const int col = tid * 4;
    float4 xv = *(const float4*)(X + row * CC + col);
    float4 rv = *(const float4*)(R + row * CC + col);
    float4 v;
    v.x = xv.x + rv.x; v.y = xv.y + rv.y; v.z = xv.z + rv.z; v.w = xv.w + rv.w;

    __shared__ float sh1[8], sh2[8];
    float s = (v.x + v.y) + (v.z + v.w);
    float sq = v.x * v.x + v.y * v.y + v.z * v.z + v.w * v.w;
    s = warpSum(s); sq = warpSum(sq);
    if ((tid & 31) == 0) { sh1[tid >> 5] = s; sh2[tid >> 5] = sq; }
    __syncthreads();
    s  = (sh1[0] + sh1[1]) + (sh1[2] + sh1[3]) + (sh1[4] + sh1[5]) + (sh1[6] + sh1[7]);
    sq = (sh2[0] + sh2[1]) + (sh2[2] + sh2[3]) + (sh2[4] + sh2[5]) + (sh2[6] + sh2[7]);
    const float mean = s * (1.0f / CC);
    const float var = sq * (1.0f / CC) - mean * mean;
    const float rstd = rsqrtf(var + 1e-5f);

    float4 gg = *(const float4*)(g + col);
    float4 bb = *(const float4*)(be + col);
    float4 o;
    o.x = (v.x - mean) * rstd * gg.x + bb.x;
    o.y = (v.y - mean) * rstd * gg.y + bb.y;
    o.z = (v.z - mean) * rstd * gg.z + bb.z;
    o.w = (v.w - mean) * rstd * gg.w + bb.w;
    *(float4*)(out + row * CC + col) = o;
    if (DUALH) {
        *(__half2*)(outh + row * CC + col)     = __floats2half2_rn(o.x, o.y);
        *(__half2*)(outh + row * CC + col + 2) = __floats2half2_rn(o.z, o.w);
    }
}

// ------------------------------- launcher ---------------------------------------
extern "C" void kernel_launch(void* const* d_in, const int* in_sizes, int n_in,
                              void* d_out, int out_size)
{
    const float* x    = (const float*)d_in[0];
    const float* enc  = (const float*)d_in[1];
    const unsigned char* tmask = (const unsigned char*)d_in[2];
    const unsigned char* smask = (const unsigned char*)d_in[3];
    const float* Wq1 = (const float*)d_in[4];
    const float* Wk1 = (const float*)d_in[5];
    const float* Wv1 = (const float*)d_in[6];
    const float* Wo1 = (const float*)d_in[7];
    const float* ln1g = (const float*)d_in[8];
    const float* ln1b = (const float*)d_in[9];
    const float* Wq2 = (const float*)d_in[10];
    const float* Wk2 = (const float*)d_in[11];
    const float* Wv2 = (const float*)d_in[12];
    const float* Wo2 = (const float*)d_in[13];
    const float* ln2g = (const float*)d_in[14];
    const float* ln2b = (const float*)d_in[15];
    const float* Wf1 = (const float*)d_in[16];
    const float* bf1 = (const float*)d_in[17];
    const float* Wf2 = (const float*)d_in[18];
    const float* bf2 = (const float*)d_in[19];
    const float* ln3g = (const float*)d_in[20];
    const float* ln3b = (const float*)d_in[21];
    float* out = (float*)d_out;

    float *go, *gx1, *gx2;
    __half *gxh, *geh, *gqh, *gvth, *gctxh, *gx1h, *gx2h, *gffh, *gwth;
    cudaGetSymbolAddress((void**)&go,  g_o);
    cudaGetSymbolAddress((void**)&gx1, g_x1);
    cudaGetSymbolAddress((void**)&gx2, g_x2);
    cudaGetSymbolAddress((void**)&gxh, g_xh);
    cudaGetSymbolAddress((void**)&geh, g_eh);
    cudaGetSymbolAddress((void**)&gqh, g_qh);
    cudaGetSymbolAddress((void**)&gvth, g_vth);
    cudaGetSymbolAddress((void**)&gctxh, g_ctxh);
    cudaGetSymbolAddress((void**)&gx1h, g_x1h);
    cudaGetSymbolAddress((void**)&gx2h, g_x2h);
    cudaGetSymbolAddress((void**)&gffh, g_ffh);
    cudaGetSymbolAddress((void**)&gwth, g_wth);

    __half* tq1 = gwth + 0u * 1048576u;   // tq1,tk1,tv1 contiguous -> [3072,1024]
    __half* tk1 = gwth + 1u * 1048576u;
    __half* tv1 = gwth + 2u * 1048576u;
    __half* to1 = gwth + 3u * 1048576u;
    __half* tq2 = gwth + 4u * 1048576u;
    __half* tk2 = gwth + 5u * 1048576u;   // tk2,tv2 contiguous -> [2048,1024]
    __half* tv2 = gwth + 6u * 1048576u;
    __half* to2 = gwth + 7u * 1048576u;
    __half* tf1 = gwth + 8u * 1048576u;              // [F, C]
    __half* tf2 = gwth + 8u * 1048576u + 4194304u;   // [C, F]

    auto* kProj  = gemm_mma<false, false, false>;   // fp32 out (-> add_ln)
    auto* kProjH = gemm_mma<false, false, true >;   // half out (-> flash / GEMM-A)
    auto* kFfn1  = gemm_mma<true,  true,  true >;   // bias+relu, half out
    auto* kFfn2  = gemm_mma<true,  false, false>;
    cudaFuncSetAttribute(kProj,  cudaFuncAttributeMaxDynamicSharedMemorySize, GSMEM);
    cudaFuncSetAttribute(kProjH, cudaFuncAttributeMaxDynamicSharedMemorySize, GSMEM);
    cudaFuncSetAttribute(kFfn1,  cudaFuncAttributeMaxDynamicSharedMemorySize, GSMEM);
    cudaFuncSetAttribute(kFfn2,  cudaFuncAttributeMaxDynamicSharedMemorySize, GSMEM);
    cudaFuncSetAttribute(flash_k<true>,  cudaFuncAttributeMaxDynamicSharedMemorySize, FSMEM);
    cudaFuncSetAttribute(flash_k<false>, cudaFuncAttributeMaxDynamicSharedMemorySize, FSMEM);

    const dim3 blk(256);
    const dim3 tblk(32, 8);

    // ---- fp16 conversion of external GEMM-A inputs (1 launch) ----
    Ptr2h p2;
    p2.s[0] = x;   p2.d[0] = gxh;
    p2.s[1] = enc; p2.d[1] = geh;
    round2h<<<dim3(MM * CC / 1024, 2), blk>>>(p2);

    // ---- weight transposes (K-major, fp16 B operands) ----
    Ptr8h p8;
    p8.s[0] = Wq1; p8.d[0] = tq1;  p8.s[1] = Wk1; p8.d[1] = tk1;
    p8.s[2] = Wv1; p8.d[2] = tv1;  p8.s[3] = Wo1; p8.d[3] = to1;
    p8.s[4] = Wq2; p8.d[4] = tq2;  p8.s[5] = Wk2; p8.d[5] = tk2;
    p8.s[6] = Wv2; p8.d[6] = tv2;  p8.s[7] = Wo2; p8.d[7] = to2;
    transpose8h<<<dim3(CC/32, CC/32, 8), tblk>>>(p8);
    transpose_kh<<<dim3(FF/32, CC/32), tblk>>>(Wf1, tf1, CC, FF);
    transpose_kh<<<dim3(CC/32, FF/32), tblk>>>(Wf2, tf2, FF, CC);

    const dim3 gQKV(3072/128, MM/128);   // (24, 32) fused self QKV
    const dim3 gKV (2048/128, MM/128);   // (16, 32) fused cross KV
    const dim3 gP  (CC/128,   MM/128);   // (8, 32)
    const dim3 gF1 (FF/128,   MM/128);   // (32, 32)
    const dim3 gFl (TT/128, BB*HH);      // (8, 64)
    const dim3 gVt (CC/32, TT/32, BB);
    const int nLn = MM;

    // ---- self-attention (causal) ----
    kProjH<<<gQKV, blk, GSMEM>>>(gxh, tq1, nullptr, gffh, CC, CC, CC, 3072);
    transpose_vh<<<gVt, tblk>>>(gffh + 2048, gvth, 3072);
    flash_k<true><<<gFl, blk, FSMEM>>>(gffh, gffh + 1024, gvth, tmask, gctxh, 3072, 3072);
    kProj<<<gP, blk, GSMEM>>>(gctxh, to1, nullptr, go, CC, CC, CC, CC);
    add_ln<true><<<nLn, blk>>>(x, go, ln1g, ln1b, gx1, gx1h);

    // ---- cross-attention ----
    kProjH<<<gP,  blk, GSMEM>>>(gx1h, tq2, nullptr, gqh, CC, CC, CC, CC);
    kProjH<<<gKV, blk, GSMEM>>>(geh, tk2, nullptr, gffh, CC, CC, CC, 2048);
    transpose_vh<<<gVt, tblk>>>(gffh + 1024, gvth, 2048);
    flash_k<false><<<gFl, blk, FSMEM>>>(gqh, gffh, gvth, smask, gctxh, CC, 2048);
    kProj<<<gP, blk, GSMEM>>>(gctxh, to2, nullptr, go, CC, CC, CC, CC);
    add_ln<true><<<nLn, blk>>>(gx1, go, ln2g, ln2b, gx2, gx2h);

    // ---- FFN ----
    kFfn1<<<gF1, blk, GSMEM>>>(gx2h, tf1, bf1, gffh, CC, CC, CC, FF);
    kFfn2<<<gP,  blk, GSMEM>>>(gffh, tf2, bf2, go, FF, FF, FF, CC);
    add_ln<false><<<nLn, blk>>>(gx2, go, ln3g, ln3b, out, nullptr);
}

// round 12
// speedup vs baseline: 2.2289x; 1.0101x over previous
#include <cuda_runtime.h>
#include <cuda_fp16.h>
#include <cstdint>
#include <cstddef>

// Problem constants
#define BB 4
#define TT 1024
#define CC 1024
#define HH 16
#define DH 64
#define FF 4096
#define MM (BB*TT)          // 4096 rows

// ---------------- scratch (device globals; no allocation allowed) ----------------
__device__ float  g_o  [(size_t)MM*CC];        // GEMM fp32 outputs (pre-LN)
__device__ float  g_x1 [(size_t)MM*CC];
__device__ float  g_x2 [(size_t)MM*CC];
__device__ __half g_xh [(size_t)MM*CC];        // half GEMM-A operands
__device__ __half g_eh [(size_t)MM*CC];
__device__ __half g_qh [(size_t)MM*CC];        // cross-attn Q (half, flash input)
__device__ __half g_ctxh[(size_t)MM*CC];
__device__ __half g_x1h[(size_t)MM*CC];
__device__ __half g_x2h[(size_t)MM*CC];
__device__ __half g_ffh[(size_t)MM*FF];        // QKV / KV / FFN1 half outputs
__device__ __half g_wth[8u*1024u*1024u + 2u*4096u*1024u];   // half weights (K-major)

// ============================ small helpers ======================================
__device__ __forceinline__ void mma_f16(float* d, const uint32_t* a, const uint32_t* b) {
    asm volatile(
        "mma.sync.aligned.m16n8k16.row.col.f32.f16.f16.f32 "
        "{%0,%1,%2,%3},{%4,%5,%6,%7},{%8,%9},{%0,%1,%2,%3};"
        : "+f"(d[0]), "+f"(d[1]), "+f"(d[2]), "+f"(d[3])
        : "r"(a[0]), "r"(a[1]), "r"(a[2]), "r"(a[3]),
          "r"(b[0]), "r"(b[1]));
}
__device__ __forceinline__ void ldsm4(uint32_t* r, uint32_t addr) {
    asm volatile("ldmatrix.sync.aligned.m8n8.x4.shared.b16 {%0,%1,%2,%3}, [%4];"
                 : "=r"(r[0]), "=r"(r[1]), "=r"(r[2]), "=r"(r[3]) : "r"(addr));
}
__device__ __forceinline__ void ldsm4t(uint32_t* r, uint32_t addr) {
    asm volatile("ldmatrix.sync.aligned.m8n8.x4.trans.shared.b16 {%0,%1,%2,%3}, [%4];"
                 : "=r"(r[0]), "=r"(r[1]), "=r"(r[2]), "=r"(r[3]) : "r"(addr));
}
__device__ __forceinline__ uint32_t smem_u32(const void* p) {
    uint32_t a;
    asm("{ .reg .u64 t; cvta.to.shared.u64 t, %1; cvt.u32.u64 %0, t; }" : "=r"(a) : "l"(p));
    return a;
}
__device__ __forceinline__ void cp16(uint32_t dst, const void* src) {
    asm volatile("cp.async.cg.shared.global [%0], [%1], 16;" :: "r"(dst), "l"(src));
}
__device__ __forceinline__ uint32_t packh2(float a, float b) {
    __half2 h = __floats2half2_rn(a, b);
    return *(uint32_t*)&h;
}

// =================== fp16 conversion copy (2 tensors, z-batched) =================
struct Ptr2h { const float* s[2]; __half* d[2]; };
__global__ void __launch_bounds__(256)
round2h(Ptr2h p)
{
    const float* in = p.s[blockIdx.y];
    __half* out = p.d[blockIdx.y];
    const size_t i = ((size_t)blockIdx.x * 256 + threadIdx.x) * 4;
    float4 v = *(const float4*)(in + i);
    *(__half2*)(out + i)     = __floats2half2_rn(v.x, v.y);
    *(__half2*)(out + i + 2) = __floats2half2_rn(v.z, v.w);
}

// ====================== 32x32 tiled transposes (fp16 out) ========================
struct Ptr8h { const float* s[8]; __half* d[8]; };

__global__ void __launch_bounds__(256)
transpose8h(Ptr8h ps)   // 8 square [CC x CC] weights, z selects matrix
{
    const float* in = ps.s[blockIdx.z];
    __half* out = ps.d[blockIdx.z];
    __shared__ float t[32][33];
    const int bx = blockIdx.x * 32, by = blockIdx.y * 32;
    int x = bx + threadIdx.x;
#pragma unroll
    for (int i = 0; i < 32; i += 8)
        t[threadIdx.y + i][threadIdx.x] = in[(size_t)(by + threadIdx.y + i) * CC + x];
    __syncthreads();
    x = by + threadIdx.x;
#pragma unroll
    for (int i = 0; i < 32; i += 8)
        out[(size_t)(bx + threadIdx.y + i) * CC + x] = __float2half_rn(t[threadIdx.x][threadIdx.y + i]);
}

// both FFN weight transposes in one launch (1D grid, 8192 tiles)
__global__ void __launch_bounds__(256)
transpose_w2(const float* __restrict__ Wf1, __half* __restrict__ tf1,
             const float* __restrict__ Wf2, __half* __restrict__ tf2)
{
    const int bid = blockIdx.x;
    const bool second = bid >= 4096;
    const int tile = second ? bid - 4096 : bid;
    const float* in;  __half* outp;  int R, C, bx, by;
    if (!second) { in = Wf1; outp = tf1; R = CC; C = FF; bx = (tile & 127) * 32; by = (tile >> 7) * 32; }
    else         { in = Wf2; outp = tf2; R = FF; C = CC; bx = (tile & 31)  * 32; by = (tile >> 5) * 32; }
    const int tx = threadIdx.x, ty = threadIdx.y;
    __shared__ float t[32][33];
    int x = bx + tx;
#pragma unroll
    for (int i = 0; i < 32; i += 8)
        t[ty + i][tx] = in[(size_t)(by + ty + i) * C + x];
    __syncthreads();
    x = by + tx;
#pragma unroll
    for (int i = 0; i < 32; i += 8)
        outp[(size_t)(bx + ty + i) * R + x] = __float2half_rn(t[tx][ty + i]);
}

// ================= fp16 mma.sync GEMM: C[M,N] = A[M,K] @ Bt[N,K]^T ===============
// (byte-identical to R11 — passing 873us config)
#define G_LDPH 72                            // halfs per row (64 data + 8 pad)
#define G_STGH (256 * G_LDPH)                // halfs per stage (A128 + B128 rows)
#define GSMEM  (3 * G_STGH * 2)              // 110592 bytes

template<bool BIAS, bool RELU, bool HOUT>
__global__ void __launch_bounds__(256, 2)
gemm_mma(const __half* __restrict__ A, const __half* __restrict__ Bt,
         const float* __restrict__ bias, void* __restrict__ Cv,
         int K, int lda, int ldb, int ldc)
{
    extern __shared__ __half smh[];
    const int bxn = blockIdx.x * 128, bym = blockIdx.y * 128;
    const int tid = threadIdx.x, wid = tid >> 5, lane = tid & 31;
    const int wr = wid >> 2, wc = wid & 3;      // 2 x 4 warps, 64x32 each
    const int g = lane >> 2, qc = lane & 3;

    const int row = tid >> 1, colb = (tid & 1) * 32;   // halfs
    const __half* Ag = A  + (size_t)(bym + row) * lda + colb;
    const __half* Bg = Bt + (size_t)(bxn + row) * ldb + colb;
    const uint32_t smb = smem_u32(smh);
    const uint32_t adst = smb + (uint32_t)(row * G_LDPH + colb) * 2;
    const uint32_t bdst = adst + 128 * G_LDPH * 2;

    const int l15 = lane & 15, l7 = lane & 7;
    const uint32_t aL = smb
        + (uint32_t)(((wr * 64 + l15) * G_LDPH + (lane >> 4) * 8) * 2);
    const uint32_t bL = smb + 128 * G_LDPH * 2
        + (uint32_t)(((wc * 32 + l7 + (lane >> 4) * 8) * G_LDPH + ((lane >> 3) & 1) * 8) * 2);

    float acc[4][4][4];
#pragma unroll
    for (int i = 0; i < 4; i++)
#pragma unroll
        for (int j = 0; j < 4; j++)
#pragma unroll
            for (int r = 0; r < 4; r++) acc[i][j][r] = 0.f;

    const int nst = K >> 6;                    // K-stage = 64 halfs

#pragma unroll
    for (int s = 0; s < 2; s++) {
        const __half* as = Ag + s * 64;
        const __half* bs = Bg + s * 64;
        const uint32_t ad = adst + s * G_STGH * 2;
        const uint32_t bd = bdst + s * G_STGH * 2;
#pragma unroll
        for (int j = 0; j < 4; j++) {
            cp16(ad + j * 16, as + j * 8);
            cp16(bd + j * 16, bs + j * 8);
        }
        asm volatile("cp.async.commit_group;" ::: "memory");
    }

    int buf = 0, nxt = 2;      // nxt = (it+2) % 3
    for (int it = 0; it < nst; ++it) {
        asm volatile("cp.async.wait_group 1;" ::: "memory");
        __syncthreads();
        const uint32_t aB = aL + (uint32_t)buf * G_STGH * 2;
        const uint32_t bB = bL + (uint32_t)buf * G_STGH * 2;
#pragma unroll
        for (int ks = 0; ks < 4; ks++) {       // 4 x k16
            uint32_t av_[4][4], bv_[2][4];
#pragma unroll
            for (int mi = 0; mi < 4; mi++)
                ldsm4(av_[mi], aB + mi * (16 * G_LDPH * 2) + ks * 32);
#pragma unroll
            for (int np = 0; np < 2; np++)
                ldsm4(bv_[np], bB + np * (16 * G_LDPH * 2) + ks * 32);
#pragma unroll
            for (int mi = 0; mi < 4; mi++)
#pragma unroll
                for (int ni = 0; ni < 4; ni++)
                    mma_f16(acc[mi][ni], av_[mi], &bv_[ni >> 1][(ni & 1) * 2]);
        }
        if (it + 2 < nst) {
            const int kt = it + 2;
            const __half* as = Ag + kt * 64;
            const __half* bs = Bg + kt * 64;
            const uint32_t ad = adst + nxt * G_STGH * 2;
            const uint32_t bd = bdst + nxt * G_STGH * 2;
#pragma unroll
            for (int j = 0; j < 4; j++) {
                cp16(ad + j * 16, as + j * 8);
                cp16(bd + j * 16, bs + j * 8);
            }
            asm volatile("cp.async.commit_group;" ::: "memory");
        }
        buf = (buf == 2) ? 0 : buf + 1;
        nxt = (nxt == 2) ? 0 : nxt + 1;
    }

#pragma unroll
    for (int mi = 0; mi < 4; mi++) {
        const int r = bym + wr * 64 + mi * 16 + g;
#pragma unroll
        for (int ni = 0; ni < 4; ni++) {
            const int col = bxn + wc * 32 + ni * 8 + qc * 2;
            float2 bv = make_float2(0.f, 0.f);
            if (BIAS) bv = *(const float2*)(bias + col);
            float2 v0, v1;
            v0.x = acc[mi][ni][0] + bv.x;
            v0.y = acc[mi][ni][1] + bv.y;
            v1.x = acc[mi][ni][2] + bv.x;
            v1.y = acc[mi][ni][3] + bv.y;
            if (RELU) {
                v0.x = fmaxf(v0.x, 0.f); v0.y = fmaxf(v0.y, 0.f);
                v1.x = fmaxf(v1.x, 0.f); v1.y = fmaxf(v1.y, 0.f);
            }
            if (HOUT) {
                __half* C = (__half*)Cv;
                *(__half2*)(C + (size_t)r * ldc + col)       = __floats2half2_rn(v0.x, v0.y);
                *(__half2*)(C + (size_t)(r + 8) * ldc + col) = __floats2half2_rn(v1.x, v1.y);
            } else {
                float* C = (float*)Cv;
                *(float2*)(C + (size_t)r * ldc + col)       = v0;
                *(float2*)(C + (size_t)(r + 8) * ldc + col) = v1;
            }
        }
    }
}

// ====================== flash attention (fp16 mma, ldmatrix) =====================
// V read DIRECTLY from [token, headcol] layout (same as K) via ldmatrix.trans —
// no pre-transposed V^T buffer needed.
// smem (bytes): Q 18432 | K 2x18432 | V 2x18432 | masks 264
#define FLB_K  18432
#define FLB_V  55296
#define FLB_M  92160
#define FSMEM  (92160 + 264)

template<bool CAUSAL>
__global__ void __launch_bounds__(256, 1)
flash_k(const __half* __restrict__ Qg, const __half* __restrict__ Kg,
        const __half* __restrict__ Vg, const unsigned char* __restrict__ padg,
        __half* __restrict__ Og, int ldq, int ldk)
{
    extern __shared__ __half smh[];
    const int tid = threadIdx.x, lane = tid & 31, w = tid >> 5;
    const int g = lane >> 2, qc = lane & 3;
    const int qt = blockIdx.x;
    const int z = blockIdx.y, b = z >> 4, h = z & 15;

    const __half* Qp = Qg + (size_t)b * TT * ldq + h * 64;
    const __half* Kp = Kg + (size_t)b * TT * ldk + h * 64;
    const __half* Vp = Vg + (size_t)b * TT * ldk + h * 64;   // same layout as K
    const unsigned char* padp = padg + (size_t)b * TT;
    __half* Op = Og + (size_t)b * TT * CC + h * 64;

    const uint32_t sQa = smem_u32(smh);
    const uint32_t sKa = sQa + FLB_K;
    const uint32_t sVa = sQa + FLB_V;
    uint32_t* sMskp = (uint32_t*)((char*)smh + FLB_M);

    // ldmatrix lane addresses (bytes)
    const int l15 = lane & 15, l7 = lane & 7;
    const uint32_t qL = sQa + (uint32_t)(((w * 16 + l15) * 72 + (lane >> 4) * 8) * 2);
    const uint32_t kL = sKa + (uint32_t)(((l7 + (lane >> 4) * 8) * 72 + ((lane >> 3) & 1) * 8) * 2);
    // V (trans): row = token k within chunk, col = head col
    const uint32_t vL = sVa + (uint32_t)(((l7 + ((lane >> 3) & 1) * 8) * 72 + (lane >> 4) * 8) * 2);

    const int nkt = CAUSAL ? qt + 1 : (TT / 128);

    {   // Q tile: 128 rows x 64 halfs, rows padded to 72 halfs (144 B)
        const __half* qs = Qp + (size_t)(qt * 128 + (tid >> 1)) * ldq + (tid & 1) * 32;
        uint32_t qd = sQa + (tid >> 1) * 144 + (tid & 1) * 64;
#pragma unroll
        for (int j = 0; j < 4; j++) cp16(qd + j * 16, qs + j * 8);
    }
    auto issue_kv = [&](int kt, int buf) {
        const __half* ks = Kp + (size_t)(kt * 128 + (tid >> 1)) * ldk + (tid & 1) * 32;
        uint32_t kd = sKa + buf * 18432u + (tid >> 1) * 144 + (tid & 1) * 64;
#pragma unroll
        for (int j = 0; j < 4; j++) cp16(kd + j * 16, ks + j * 8);
        const __half* vs = Vp + (size_t)(kt * 128 + (tid >> 1)) * ldk + (tid & 1) * 32;
        uint32_t vd = sVa + buf * 18432u + (tid >> 1) * 144 + (tid & 1) * 64;
#pragma unroll
        for (int j = 0; j < 4; j++) cp16(vd + j * 16, vs + j * 8);
        if (tid < 32) {
            uint32_t mv = *(const uint32_t*)(padp + (size_t)kt * 128 + tid * 4);
            sMskp[buf * 32 + tid] = mv;
            uint32_t f = __reduce_or_sync(0xffffffffu, mv);
            if (tid == 0) sMskp[64 + buf] = f;
        }
    };
    issue_kv(0, 0);
    asm volatile("cp.async.commit_group;" ::: "memory");

    float m0 = -INFINITY, m1 = -INFINITY, l0 = 0.f, l1 = 0.f;
    float oacc[8][4];
#pragma unroll
    for (int j = 0; j < 8; j++)
#pragma unroll
        for (int r = 0; r < 4; r++) oacc[j][r] = 0.f;

    const int r0 = w * 16 + g, r1 = r0 + 8;

    for (int kt = 0; kt < nkt; ++kt) {
        const int buf = kt & 1;
        if (kt + 1 < nkt) {
            issue_kv(kt + 1, buf ^ 1);
            asm volatile("cp.async.commit_group;" ::: "memory");
            asm volatile("cp.async.wait_group 1;" ::: "memory");
        } else {
            asm volatile("cp.async.wait_group 0;" ::: "memory");
        }
        __syncthreads();

        // ---- S = Q @ K^T (warp: 16 x 128), fp16 k16, ldmatrix ----
        float sacc[16][4];
#pragma unroll
        for (int ni = 0; ni < 16; ni++)
#pragma unroll
            for (int r = 0; r < 4; r++) sacc[ni][r] = 0.f;
        {
            const uint32_t kB = kL + buf * 18432u;
#pragma unroll
            for (int ks = 0; ks < 4; ks++) {
                uint32_t aq[4];
                ldsm4(aq, qL + ks * 32);
#pragma unroll
                for (int np = 0; np < 8; np++) {
                    uint32_t kv4[4];
                    ldsm4(kv4, kB + np * (16 * 144) + ks * 32);
                    mma_f16(sacc[2 * np],     aq, kv4);
                    mma_f16(sacc[2 * np + 1], aq, kv4 + 2);
                }
            }
        }

        // ---- scale + masks + row stats ----
        const uint32_t pf = sMskp[64 + buf];
        const unsigned char* mb = (const unsigned char*)(sMskp + buf * 32);
        float tm0 = -INFINITY, tm1 = -INFINITY;
#pragma unroll
        for (int ni = 0; ni < 16; ni++) {
            float s0 = sacc[ni][0] * 0.125f, s1 = sacc[ni][1] * 0.125f;
            float s2 = sacc[ni][2] * 0.125f, s3 = sacc[ni][3] * 0.125f;
            const int c0 = ni * 8 + qc * 2;
            if (CAUSAL && kt == qt) {
                if (c0     > r0) s0 = -INFINITY;
                if (c0 + 1 > r0) s1 = -INFINITY;
                if (c0     > r1) s2 = -INFINITY;
                if (c0 + 1 > r1) s3 = -INFINITY;
            }
            if (pf) {
                if (mb[c0])     { s0 = -INFINITY; s2 = -INFINITY; }
                if (mb[c0 + 1]) { s1 = -INFINITY; s3 = -INFINITY; }
            }
            sacc[ni][0] = s0; sacc[ni][1] = s1; sacc[ni][2] = s2; sacc[ni][3] = s3;
            tm0 = fmaxf(tm0, fmaxf(s0, s1));
            tm1 = fmaxf(tm1, fmaxf(s2, s3));
        }
        tm0 = fmaxf(tm0, __shfl_xor_sync(0xffffffffu, tm0, 1));
        tm0 = fmaxf(tm0, __shfl_xor_sync(0xffffffffu, tm0, 2));
        tm1 = fmaxf(tm1, __shfl_xor_sync(0xffffffffu, tm1, 1));
        tm1 = fmaxf(tm1, __shfl_xor_sync(0xffffffffu, tm1, 2));
        const float mn0 = fmaxf(m0, tm0), mn1 = fmaxf(m1, tm1);

        float sum0 = 0.f, sum1 = 0.f;
#pragma unroll
        for (int ni = 0; ni < 16; ni++) {
            float p0 = __expf(sacc[ni][0] - mn0);
            float p1 = __expf(sacc[ni][1] - mn0);
            float p2 = __expf(sacc[ni][2] - mn1);
            float p3 = __expf(sacc[ni][3] - mn1);
            sacc[ni][0] = p0; sacc[ni][1] = p1; sacc[ni][2] = p2; sacc[ni][3] = p3;
            sum0 += p0 + p1; sum1 += p2 + p3;
        }
        sum0 += __shfl_xor_sync(0xffffffffu, sum0, 1);
        sum0 += __shfl_xor_sync(0xffffffffu, sum0, 2);
        sum1 += __shfl_xor_sync(0xffffffffu, sum1, 1);
        sum1 += __shfl_xor_sync(0xffffffffu, sum1, 2);

        const float sc0 = __expf(m0 - mn0), sc1 = __expf(m1 - mn1);
        l0 = l0 * sc0 + sum0;  l1 = l1 * sc1 + sum1;
        m0 = mn0;  m1 = mn1;
#pragma unroll
        for (int nj = 0; nj < 8; nj++) {
            oacc[nj][0] *= sc0; oacc[nj][1] *= sc0;
            oacc[nj][2] *= sc1; oacc[nj][3] *= sc1;
        }

        // ---- O += P @ V: S-fragment repack + ldmatrix.trans V ----
        {
            const uint32_t vB = vL + buf * 18432u;
#pragma unroll
            for (int k2 = 0; k2 < 8; k2++) {
                uint32_t pa[4];
                pa[0] = packh2(sacc[2 * k2][0],     sacc[2 * k2][1]);
                pa[1] = packh2(sacc[2 * k2][2],     sacc[2 * k2][3]);
                pa[2] = packh2(sacc[2 * k2 + 1][0], sacc[2 * k2 + 1][1]);
                pa[3] = packh2(sacc[2 * k2 + 1][2], sacc[2 * k2 + 1][3]);
#pragma unroll
                for (int np = 0; np < 4; np++) {
                    uint32_t vv[4];
                    ldsm4t(vv, vB + k2 * (16 * 144) + np * 32);
                    mma_f16(oacc[2 * np],     pa, vv);
                    mma_f16(oacc[2 * np + 1], pa, vv + 2);
                }
            }
        }
        __syncthreads();
    }

    const float inv0 = 1.f / l0, inv1 = 1.f / l1;
    __half* orow0 = Op + (size_t)(qt * 128 + r0) * CC;
    __half* orow1 = orow0 + 8 * CC;
#pragma unroll
    for (int nj = 0; nj < 8; nj++) {
        *(__half2*)(orow0 + nj * 8 + qc * 2) =
            __floats2half2_rn(oacc[nj][0] * inv0, oacc[nj][1] * inv0);
        *(__half2*)(orow1 + nj * 8 + qc * 2) =
            __floats2half2_rn(oacc[nj][2] * inv1, oacc[nj][3] * inv1);
    }
}

// ============================ layernorm ==========================================
__device__ __forceinline__ float warpSum(float v) {
#pragma unroll
    for (int o = 16; o; o >>= 1) v += __shfl_xor_sync(0xffffffffu, v, o);
    return v;
}

template<bool DUALH>
__global__ void __launch_bounds__(256)
add_ln(const float* __restrict__ X, const float* __restrict__ R,
       const float* __restrict__ g, const float* __restrict__ be,
       float* __restrict__ out, __half* __restrict__ outh)
{
    const size_t row = blockIdx.x;
    const int tid = threadIdx.x;
    const int col = tid * 4;
    float4 xv = *(const float4*)(X + row * CC + col);
    float4 rv = *(const float4*)(R + row * CC + col);
    float4 v;
    v.x = xv.x + rv.x; v.y = xv.y + rv.y; v.z = xv.z + rv.z; v.w = xv.w + rv.w;

    __shared__ float sh1[8], sh2[8];
    float s = (v.x + v.y) + (v.z + v.w);
    float sq = v.x * v.x + v.y * v.y + v.z * v.z + v.w * v.w;
    s = warpSum(s); sq = warpSum(sq);
    if ((tid & 31) == 0) { sh1[tid >> 5] = s; sh2[tid >> 5] = sq; }
    __syncthreads();
    s  = (sh1[0] + sh1[1]) + (sh1[2] + sh1[3]) + (sh1[4] + sh1[5]) + (sh1[6] + sh1[7]);
    sq = (sh2[0] + sh2[1]) + (sh2[2] + sh2[3]) + (sh2[4] + sh2[5]) + (sh2[6] + sh2[7]);
    const float mean = s * (1.0f / CC);
    const float var = sq * (1.0f / CC) - mean * mean;
    const float rstd = rsqrtf(var + 1e-5f);

    float4 gg = *(const float4*)(g + col);
    float4 bb = *(const float4*)(be + col);
    float4 o;
    o.x = (v.x - mean) * rstd * gg.x + bb.x;
    o.y = (v.y - mean) * rstd * gg.y + bb.y;
    o.z = (v.z - mean) * rstd * gg.z + bb.z;
    o.w = (v.w - mean) * rstd * gg.w + bb.w;
    *(float4*)(out + row * CC + col) = o;
    if (DUALH) {
        *(__half2*)(outh + row * CC + col)     = __floats2half2_rn(o.x, o.y);
        *(__half2*)(outh + row * CC + col + 2) = __floats2half2_rn(o.z, o.w);
    }
}

// ------------------------------- launcher ---------------------------------------
extern "C" void kernel_launch(void* const* d_in, const int* in_sizes, int n_in,
                              void* d_out, int out_size)
{
    const float* x    = (const float*)d_in[0];
    const float* enc  = (const float*)d_in[1];
    const unsigned char* tmask = (const unsigned char*)d_in[2];
    const unsigned char* smask = (const unsigned char*)d_in[3];
    const float* Wq1 = (const float*)d_in[4];
    const float* Wk1 = (const float*)d_in[5];
    const float* Wv1 = (const float*)d_in[6];
    const float* Wo1 = (const float*)d_in[7];
    const float* ln1g = (const float*)d_in[8];
    const float* ln1b = (const float*)d_in[9];
    const float* Wq2 = (const float*)d_in[10];
    const float* Wk2 = (const float*)d_in[11];
    const float* Wv2 = (const float*)d_in[12];
    const float* Wo2 = (const float*)d_in[13];
    const float* ln2g = (const float*)d_in[14];
    const float* ln2b = (const float*)d_in[15];
    const float* Wf1 = (const float*)d_in[16];
    const float* bf1 = (const float*)d_in[17];
    const float* Wf2 = (const float*)d_in[18];
    const float* bf2 = (const float*)d_in[19];
    const float* ln3g = (const float*)d_in[20];
    const float* ln3b = (const float*)d_in[21];
    float* out = (float*)d_out;

    float *go, *gx1, *gx2;
    __half *gxh, *geh, *gqh, *gctxh, *gx1h, *gx2h, *gffh, *gwth;
    cudaGetSymbolAddress((void**)&go,  g_o);
    cudaGetSymbolAddress((void**)&gx1, g_x1);
    cudaGetSymbolAddress((void**)&gx2, g_x2);
    cudaGetSymbolAddress((void**)&gxh, g_xh);
    cudaGetSymbolAddress((void**)&geh, g_eh);
    cudaGetSymbolAddress((void**)&gqh, g_qh);
    cudaGetSymbolAddress((void**)&gctxh, g_ctxh);
    cudaGetSymbolAddress((void**)&gx1h, g_x1h);
    cudaGetSymbolAddress((void**)&gx2h, g_x2h);
    cudaGetSymbolAddress((void**)&gffh, g_ffh);
    cudaGetSymbolAddress((void**)&gwth, g_wth);

    __half* tq1 = gwth + 0u * 1048576u;   // tq1,tk1,tv1 contiguous -> [3072,1024]
    __half* tk1 = gwth + 1u * 1048576u;
    __half* tv1 = gwth + 2u * 1048576u;
    __half* to1 = gwth + 3u * 1048576u;
    __half* tq2 = gwth + 4u * 1048576u;
    __half* tk2 = gwth + 5u * 1048576u;   // tk2,tv2 contiguous -> [2048,1024]
    __half* tv2 = gwth + 6u * 1048576u;
    __half* to2 = gwth + 7u * 1048576u;
    __half* tf1 = gwth + 8u * 1048576u;              // [F, C]
    __half* tf2 = gwth + 8u * 1048576u + 4194304u;   // [C, F]

    auto* kProj  = gemm_mma<false, false, false>;   // fp32 out (-> add_ln)
    auto* kProjH = gemm_mma<false, false, true >;   // half out (-> flash / GEMM-A)
    auto* kFfn1  = gemm_mma<true,  true,  true >;   // bias+relu, half out
    auto* kFfn2  = gemm_mma<true,  false, false>;
    cudaFuncSetAttribute(kProj,  cudaFuncAttributeMaxDynamicSharedMemorySize, GSMEM);
    cudaFuncSetAttribute(kProjH, cudaFuncAttributeMaxDynamicSharedMemorySize, GSMEM);
    cudaFuncSetAttribute(kFfn1,  cudaFuncAttributeMaxDynamicSharedMemorySize, GSMEM);
    cudaFuncSetAttribute(kFfn2,  cudaFuncAttributeMaxDynamicSharedMemorySize, GSMEM);
    cudaFuncSetAttribute(flash_k<true>,  cudaFuncAttributeMaxDynamicSharedMemorySize, FSMEM);
    cudaFuncSetAttribute(flash_k<false>, cudaFuncAttributeMaxDynamicSharedMemorySize, FSMEM);

    const dim3 blk(256);
    const dim3 tblk(32, 8);

    // ---- fp16 conversion of external GEMM-A inputs (1 launch) ----
    Ptr2h p2;
    p2.s[0] = x;   p2.d[0] = gxh;
    p2.s[1] = enc; p2.d[1] = geh;
    round2h<<<dim3(MM * CC / 1024, 2), blk>>>(p2);

    // ---- weight transposes (K-major, fp16 B operands) ----
    Ptr8h p8;
    p8.s[0] = Wq1; p8.d[0] = tq1;  p8.s[1] = Wk1; p8.d[1] = tk1;
    p8.s[2] = Wv1; p8.d[2] = tv1;  p8.s[3] = Wo1; p8.d[3] = to1;
    p8.s[4] = Wq2; p8.d[4] = tq2;  p8.s[5] = Wk2; p8.d[5] = tk2;
    p8.s[6] = Wv2; p8.d[6] = tv2;  p8.s[7] = Wo2; p8.d[7] = to2;
    transpose8h<<<dim3(CC/32, CC/32, 8), tblk>>>(p8);
    transpose_w2<<<8192, tblk>>>(Wf1, tf1, Wf2, tf2);

    const dim3 gQKV(3072/128, MM/128);   // (24, 32) fused self QKV
    const dim3 gKV (2048/128, MM/128);   // (16, 32) fused cross KV
    const dim3 gP  (CC/128,   MM/128);   // (8, 32)
    const dim3 gF1 (FF/128,   MM/128);   // (32, 32)
    const dim3 gFl (TT/128, BB*HH);      // (8, 64)
    const int nLn = MM;

    // ---- self-attention (causal) ----
    kProjH<<<gQKV, blk, GSMEM>>>(gxh, tq1, nullptr, gffh, CC, CC, CC, 3072);
    flash_k<true><<<gFl, blk, FSMEM>>>(gffh, gffh + 1024, gffh + 2048, tmask, gctxh, 3072, 3072);
    kProj<<<gP, blk, GSMEM>>>(gctxh, to1, nullptr, go, CC, CC, CC, CC);
    add_ln<true><<<nLn, blk>>>(x, go, ln1g, ln1b, gx1, gx1h);

    // ---- cross-attention ----
    kProjH<<<gP,  blk, GSMEM>>>(gx1h, tq2, nullptr, gqh, CC, CC, CC, CC);
    kProjH<<<gKV, blk, GSMEM>>>(geh, tk2, nullptr, gffh, CC, CC, CC, 2048);
    flash_k<false><<<gFl, blk, FSMEM>>>(gqh, gffh, gffh + 1024, smask, gctxh, CC, 2048);
    kProj<<<gP, blk, GSMEM>>>(gctxh, to2, nullptr, go, CC, CC, CC, CC);
    add_ln<true><<<nLn, blk>>>(gx1, go, ln2g, ln2b, gx2, gx2h);

    // ---- FFN ----
    kFfn1<<<gF1, blk, GSMEM>>>(gx2h, tf1, bf1, gffh, CC, CC, CC, FF);
    kFfn2<<<gP,  blk, GSMEM>>>(gffh, tf2, bf2, go, FF, FF, FF, CC);
    add_ln<false><<<nLn, blk>>>(gx2, go, ln3g, ln3b, out, nullptr);
}

// round 13
// speedup vs baseline: 2.2854x; 1.0253x over previous
#include <cuda_runtime.h>
#include <cuda_fp16.h>
#include <cstdint>
#include <cstddef>

// Problem constants
#define BB 4
#define TT 1024
#define CC 1024
#define HH 16
#define DH 64
#define FF 4096
#define MM (BB*TT)          // 4096 rows

// ---------------- scratch (device globals; no allocation allowed) ----------------
__device__ float  g_o  [(size_t)MM*CC];        // GEMM fp32 outputs (pre-LN)
__device__ float  g_x1 [(size_t)MM*CC];
__device__ float  g_x2 [(size_t)MM*CC];
__device__ __half g_xh [(size_t)MM*CC];        // half GEMM-A operands
__device__ __half g_eh [(size_t)MM*CC];
__device__ __half g_qh [(size_t)MM*CC];        // cross-attn Q (half, flash input)
__device__ __half g_ctxh[(size_t)MM*CC];
__device__ __half g_x1h[(size_t)MM*CC];
__device__ __half g_x2h[(size_t)MM*CC];
__device__ __half g_ffh[(size_t)MM*FF];        // QKV / KV / FFN1 half outputs
__device__ __half g_wth[8u*1024u*1024u + 2u*4096u*1024u];   // half weights (K-major)

// ============================ small helpers ======================================
__device__ __forceinline__ void mma_f16(float* d, const uint32_t* a, const uint32_t* b) {
    asm volatile(
        "mma.sync.aligned.m16n8k16.row.col.f32.f16.f16.f32 "
        "{%0,%1,%2,%3},{%4,%5,%6,%7},{%8,%9},{%0,%1,%2,%3};"
        : "+f"(d[0]), "+f"(d[1]), "+f"(d[2]), "+f"(d[3])
        : "r"(a[0]), "r"(a[1]), "r"(a[2]), "r"(a[3]),
          "r"(b[0]), "r"(b[1]));
}
__device__ __forceinline__ void ldsm4(uint32_t* r, uint32_t addr) {
    asm volatile("ldmatrix.sync.aligned.m8n8.x4.shared.b16 {%0,%1,%2,%3}, [%4];"
                 : "=r"(r[0]), "=r"(r[1]), "=r"(r[2]), "=r"(r[3]) : "r"(addr));
}
__device__ __forceinline__ void ldsm4t(uint32_t* r, uint32_t addr) {
    asm volatile("ldmatrix.sync.aligned.m8n8.x4.trans.shared.b16 {%0,%1,%2,%3}, [%4];"
                 : "=r"(r[0]), "=r"(r[1]), "=r"(r[2]), "=r"(r[3]) : "r"(addr));
}
__device__ __forceinline__ uint32_t smem_u32(const void* p) {
    uint32_t a;
    asm("{ .reg .u64 t; cvta.to.shared.u64 t, %1; cvt.u32.u64 %0, t; }" : "=r"(a) : "l"(p));
    return a;
}
__device__ __forceinline__ void cp16(uint32_t dst, const void* src) {
    asm volatile("cp.async.cg.shared.global [%0], [%1], 16;" :: "r"(dst), "l"(src));
}
__device__ __forceinline__ uint32_t packh2(float a, float b) {
    __half2 h = __floats2half2_rn(a, b);
    return *(uint32_t*)&h;
}

// =================== fp16 conversion copy (2 tensors, z-batched) =================
struct Ptr2h { const float* s[2]; __half* d[2]; };
__global__ void __launch_bounds__(256)
round2h(Ptr2h p)
{
    const float* in = p.s[blockIdx.y];
    __half* out = p.d[blockIdx.y];
    const size_t i = ((size_t)blockIdx.x * 256 + threadIdx.x) * 4;
    float4 v = *(const float4*)(in + i);
    *(__half2*)(out + i)     = __floats2half2_rn(v.x, v.y);
    *(__half2*)(out + i + 2) = __floats2half2_rn(v.z, v.w);
}

// ====================== 32x32 tiled transposes (fp16 out) ========================
struct Ptr8h { const float* s[8]; __half* d[8]; };

__global__ void __launch_bounds__(256)
transpose8h(Ptr8h ps)   // 8 square [CC x CC] weights, z selects matrix
{
    const float* in = ps.s[blockIdx.z];
    __half* out = ps.d[blockIdx.z];
    __shared__ float t[32][33];
    const int bx = blockIdx.x * 32, by = blockIdx.y * 32;
    int x = bx + threadIdx.x;
#pragma unroll
    for (int i = 0; i < 32; i += 8)
        t[threadIdx.y + i][threadIdx.x] = in[(size_t)(by + threadIdx.y + i) * CC + x];
    __syncthreads();
    x = by + threadIdx.x;
#pragma unroll
    for (int i = 0; i < 32; i += 8)
        out[(size_t)(bx + threadIdx.y + i) * CC + x] = __float2half_rn(t[threadIdx.x][threadIdx.y + i]);
}

// both FFN weight transposes in one launch (1D grid, 8192 tiles)
__global__ void __launch_bounds__(256)
transpose_w2(const float* __restrict__ Wf1, __half* __restrict__ tf1,
             const float* __restrict__ Wf2, __half* __restrict__ tf2)
{
    const int bid = blockIdx.x;
    const bool second = bid >= 4096;
    const int tile = second ? bid - 4096 : bid;
    const float* in;  __half* outp;  int R, C, bx, by;
    if (!second) { in = Wf1; outp = tf1; R = CC; C = FF; bx = (tile & 127) * 32; by = (tile >> 7) * 32; }
    else         { in = Wf2; outp = tf2; R = FF; C = CC; bx = (tile & 31)  * 32; by = (tile >> 5) * 32; }
    const int tx = threadIdx.x, ty = threadIdx.y;
    __shared__ float t[32][33];
    int x = bx + tx;
#pragma unroll
    for (int i = 0; i < 32; i += 8)
        t[ty + i][tx] = in[(size_t)(by + ty + i) * C + x];
    __syncthreads();
    x = by + tx;
#pragma unroll
    for (int i = 0; i < 32; i += 8)
        outp[(size_t)(bx + ty + i) * R + x] = __float2half_rn(t[tx][ty + i]);
}

// ================= fp16 mma.sync GEMM: C[M,N] = A[M,K] @ Bt[N,K]^T ===============
// R12 structure + register double-buffered fragments (LDSM ks+1 under HMMA ks).
#define G_LDPH 72                            // halfs per row (64 data + 8 pad)
#define G_STGH (256 * G_LDPH)                // halfs per stage (A128 + B128 rows)
#define GSMEM  (3 * G_STGH * 2)              // 110592 bytes

template<bool BIAS, bool RELU, bool HOUT>
__global__ void __launch_bounds__(256, 2)
gemm_mma(const __half* __restrict__ A, const __half* __restrict__ Bt,
         const float* __restrict__ bias, void* __restrict__ Cv,
         int K, int lda, int ldb, int ldc)
{
    extern __shared__ __half smh[];
    const int bxn = blockIdx.x * 128, bym = blockIdx.y * 128;
    const int tid = threadIdx.x, wid = tid >> 5, lane = tid & 31;
    const int wr = wid >> 2, wc = wid & 3;      // 2 x 4 warps, 64x32 each
    const int g = lane >> 2, qc = lane & 3;

    const int row = tid >> 1, colb = (tid & 1) * 32;   // halfs
    const __half* Ag = A  + (size_t)(bym + row) * lda + colb;
    const __half* Bg = Bt + (size_t)(bxn + row) * ldb + colb;
    const uint32_t smb = smem_u32(smh);
    const uint32_t adst = smb + (uint32_t)(row * G_LDPH + colb) * 2;
    const uint32_t bdst = adst + 128 * G_LDPH * 2;

    const int l15 = lane & 15, l7 = lane & 7;
    const uint32_t aL = smb
        + (uint32_t)(((wr * 64 + l15) * G_LDPH + (lane >> 4) * 8) * 2);
    const uint32_t bL = smb + 128 * G_LDPH * 2
        + (uint32_t)(((wc * 32 + l7 + (lane >> 4) * 8) * G_LDPH + ((lane >> 3) & 1) * 8) * 2);

    float acc[4][4][4];
#pragma unroll
    for (int i = 0; i < 4; i++)
#pragma unroll
        for (int j = 0; j < 4; j++)
#pragma unroll
            for (int r = 0; r < 4; r++) acc[i][j][r] = 0.f;

    const int nst = K >> 6;                    // K-stage = 64 halfs

#pragma unroll
    for (int s = 0; s < 2; s++) {
        const __half* as = Ag + s * 64;
        const __half* bs = Bg + s * 64;
        const uint32_t ad = adst + s * G_STGH * 2;
        const uint32_t bd = bdst + s * G_STGH * 2;
#pragma unroll
        for (int j = 0; j < 4; j++) {
            cp16(ad + j * 16, as + j * 8);
            cp16(bd + j * 16, bs + j * 8);
        }
        asm volatile("cp.async.commit_group;" ::: "memory");
    }

    int buf = 0, nxt = 2;      // nxt = (it+2) % 3
    for (int it = 0; it < nst; ++it) {
        asm volatile("cp.async.wait_group 1;" ::: "memory");
        __syncthreads();
        const uint32_t aB = aL + (uint32_t)buf * G_STGH * 2;
        const uint32_t bB = bL + (uint32_t)buf * G_STGH * 2;

        uint32_t av_[2][4][4], bv_[2][2][4];
#pragma unroll
        for (int mi = 0; mi < 4; mi++)
            ldsm4(av_[0][mi], aB + mi * (16 * G_LDPH * 2));
#pragma unroll
        for (int np = 0; np < 2; np++)
            ldsm4(bv_[0][np], bB + np * (16 * G_LDPH * 2));
#pragma unroll
        for (int ks = 0; ks < 4; ks++) {       // 4 x k16, frag double-buffered
            const int c = ks & 1;
            if (ks < 3) {
#pragma unroll
                for (int mi = 0; mi < 4; mi++)
                    ldsm4(av_[c ^ 1][mi], aB + mi * (16 * G_LDPH * 2) + (ks + 1) * 32);
#pragma unroll
                for (int np = 0; np < 2; np++)
                    ldsm4(bv_[c ^ 1][np], bB + np * (16 * G_LDPH * 2) + (ks + 1) * 32);
            }
#pragma unroll
            for (int mi = 0; mi < 4; mi++)
#pragma unroll
                for (int ni = 0; ni < 4; ni++)
                    mma_f16(acc[mi][ni], av_[c][mi], &bv_[c][ni >> 1][(ni & 1) * 2]);
        }
        if (it + 2 < nst) {
            const int kt = it + 2;
            const __half* as = Ag + kt * 64;
            const __half* bs = Bg + kt * 64;
            const uint32_t ad = adst + nxt * G_STGH * 2;
            const uint32_t bd = bdst + nxt * G_STGH * 2;
#pragma unroll
            for (int j = 0; j < 4; j++) {
                cp16(ad + j * 16, as + j * 8);
                cp16(bd + j * 16, bs + j * 8);
            }
            asm volatile("cp.async.commit_group;" ::: "memory");
        }
        buf = (buf == 2) ? 0 : buf + 1;
        nxt = (nxt == 2) ? 0 : nxt + 1;
    }

#pragma unroll
    for (int mi = 0; mi < 4; mi++) {
        const int r = bym + wr * 64 + mi * 16 + g;
#pragma unroll
        for (int ni = 0; ni < 4; ni++) {
            const int col = bxn + wc * 32 + ni * 8 + qc * 2;
            float2 bv = make_float2(0.f, 0.f);
            if (BIAS) bv = *(const float2*)(bias + col);
            float2 v0, v1;
            v0.x = acc[mi][ni][0] + bv.x;
            v0.y = acc[mi][ni][1] + bv.y;
            v1.x = acc[mi][ni][2] + bv.x;
            v1.y = acc[mi][ni][3] + bv.y;
            if (RELU) {
                v0.x = fmaxf(v0.x, 0.f); v0.y = fmaxf(v0.y, 0.f);
                v1.x = fmaxf(v1.x, 0.f); v1.y = fmaxf(v1.y, 0.f);
            }
            if (HOUT) {
                __half* C = (__half*)Cv;
                *(__half2*)(C + (size_t)r * ldc + col)       = __floats2half2_rn(v0.x, v0.y);
                *(__half2*)(C + (size_t)(r + 8) * ldc + col) = __floats2half2_rn(v1.x, v1.y);
            } else {
                float* C = (float*)Cv;
                *(float2*)(C + (size_t)r * ldc + col)       = v0;
                *(float2*)(C + (size_t)(r + 8) * ldc + col) = v1;
            }
        }
    }
}

// ====================== flash attention (fp16 mma, ldmatrix) =====================
// V read DIRECTLY from [token, headcol] layout via ldmatrix.trans.
// smem (bytes): Q 18432 | K 2x18432 | V 2x18432 | masks 264 — fits 2 CTAs/SM.
#define FLB_K  18432
#define FLB_V  55296
#define FLB_M  92160
#define FSMEM  (92160 + 264)

template<bool CAUSAL>
__global__ void __launch_bounds__(256, 2)
flash_k(const __half* __restrict__ Qg, const __half* __restrict__ Kg,
        const __half* __restrict__ Vg, const unsigned char* __restrict__ padg,
        __half* __restrict__ Og, int ldq, int ldk)
{
    extern __shared__ __half smh[];
    const int tid = threadIdx.x, lane = tid & 31, w = tid >> 5;
    const int g = lane >> 2, qc = lane & 3;
    const int qt = blockIdx.x;
    const int z = blockIdx.y, b = z >> 4, h = z & 15;

    const __half* Qp = Qg + (size_t)b * TT * ldq + h * 64;
    const __half* Kp = Kg + (size_t)b * TT * ldk + h * 64;
    const __half* Vp = Vg + (size_t)b * TT * ldk + h * 64;   // same layout as K
    const unsigned char* padp = padg + (size_t)b * TT;
    __half* Op = Og + (size_t)b * TT * CC + h * 64;

    const uint32_t sQa = smem_u32(smh);
    const uint32_t sKa = sQa + FLB_K;
    const uint32_t sVa = sQa + FLB_V;
    uint32_t* sMskp = (uint32_t*)((char*)smh + FLB_M);

    // ldmatrix lane addresses (bytes)
    const int l15 = lane & 15, l7 = lane & 7;
    const uint32_t qL = sQa + (uint32_t)(((w * 16 + l15) * 72 + (lane >> 4) * 8) * 2);
    const uint32_t kL = sKa + (uint32_t)(((l7 + (lane >> 4) * 8) * 72 + ((lane >> 3) & 1) * 8) * 2);
    const uint32_t vL = sVa + (uint32_t)(((l7 + ((lane >> 3) & 1) * 8) * 72 + (lane >> 4) * 8) * 2);

    const int nkt = CAUSAL ? qt + 1 : (TT / 128);

    {   // Q tile: 128 rows x 64 halfs, rows padded to 72 halfs (144 B)
        const __half* qs = Qp + (size_t)(qt * 128 + (tid >> 1)) * ldq + (tid & 1) * 32;
        uint32_t qd = sQa + (tid >> 1) * 144 + (tid & 1) * 64;
#pragma unroll
        for (int j = 0; j < 4; j++) cp16(qd + j * 16, qs + j * 8);
    }
    auto issue_kv = [&](int kt, int buf) {
        const __half* ks = Kp + (size_t)(kt * 128 + (tid >> 1)) * ldk + (tid & 1) * 32;
        uint32_t kd = sKa + buf * 18432u + (tid >> 1) * 144 + (tid & 1) * 64;
#pragma unroll
        for (int j = 0; j < 4; j++) cp16(kd + j * 16, ks + j * 8);
        const __half* vs = Vp + (size_t)(kt * 128 + (tid >> 1)) * ldk + (tid & 1) * 32;
        uint32_t vd = sVa + buf * 18432u + (tid >> 1) * 144 + (tid & 1) * 64;
#pragma unroll
        for (int j = 0; j < 4; j++) cp16(vd + j * 16, vs + j * 8);
        if (tid < 32) {
            uint32_t mv = *(const uint32_t*)(padp + (size_t)kt * 128 + tid * 4);
            sMskp[buf * 32 + tid] = mv;
            uint32_t f = __reduce_or_sync(0xffffffffu, mv);
            if (tid == 0) sMskp[64 + buf] = f;
        }
    };
    issue_kv(0, 0);
    asm volatile("cp.async.commit_group;" ::: "memory");

    float m0 = -INFINITY, m1 = -INFINITY, l0 = 0.f, l1 = 0.f;
    float oacc[8][4];
#pragma unroll
    for (int j = 0; j < 8; j++)
#pragma unroll
        for (int r = 0; r < 4; r++) oacc[j][r] = 0.f;

    const int r0 = w * 16 + g, r1 = r0 + 8;

    for (int kt = 0; kt < nkt; ++kt) {
        const int buf = kt & 1;
        if (kt + 1 < nkt) {
            issue_kv(kt + 1, buf ^ 1);
            asm volatile("cp.async.commit_group;" ::: "memory");
            asm volatile("cp.async.wait_group 1;" ::: "memory");
        } else {
            asm volatile("cp.async.wait_group 0;" ::: "memory");
        }
        __syncthreads();

        // ---- S = Q @ K^T (warp: 16 x 128), fp16 k16, ldmatrix ----
        float sacc[16][4];
#pragma unroll
        for (int ni = 0; ni < 16; ni++)
#pragma unroll
            for (int r = 0; r < 4; r++) sacc[ni][r] = 0.f;
        {
            const uint32_t kB = kL + buf * 18432u;
#pragma unroll
            for (int ks = 0; ks < 4; ks++) {
                uint32_t aq[4];
                ldsm4(aq, qL + ks * 32);
#pragma unroll
                for (int np = 0; np < 8; np++) {
                    uint32_t kv4[4];
                    ldsm4(kv4, kB + np * (16 * 144) + ks * 32);
                    mma_f16(sacc[2 * np],     aq, kv4);
                    mma_f16(sacc[2 * np + 1], aq, kv4 + 2);
                }
            }
        }

        // ---- scale + masks + row stats ----
        const uint32_t pf = sMskp[64 + buf];
        const unsigned char* mb = (const unsigned char*)(sMskp + buf * 32);
        float tm0 = -INFINITY, tm1 = -INFINITY;
#pragma unroll
        for (int ni = 0; ni < 16; ni++) {
            float s0 = sacc[ni][0] * 0.125f, s1 = sacc[ni][1] * 0.125f;
            float s2 = sacc[ni][2] * 0.125f, s3 = sacc[ni][3] * 0.125f;
            const int c0 = ni * 8 + qc * 2;
            if (CAUSAL && kt == qt) {
                if (c0     > r0) s0 = -INFINITY;
                if (c0 + 1 > r0) s1 = -INFINITY;
                if (c0     > r1) s2 = -INFINITY;
                if (c0 + 1 > r1) s3 = -INFINITY;
            }
            if (pf) {
                if (mb[c0])     { s0 = -INFINITY; s2 = -INFINITY; }
                if (mb[c0 + 1]) { s1 = -INFINITY; s3 = -INFINITY; }
            }
            sacc[ni][0] = s0; sacc[ni][1] = s1; sacc[ni][2] = s2; sacc[ni][3] = s3;
            tm0 = fmaxf(tm0, fmaxf(s0, s1));
            tm1 = fmaxf(tm1, fmaxf(s2, s3));
        }
        tm0 = fmaxf(tm0, __shfl_xor_sync(0xffffffffu, tm0, 1));
        tm0 = fmaxf(tm0, __shfl_xor_sync(0xffffffffu, tm0, 2));
        tm1 = fmaxf(tm1, __shfl_xor_sync(0xffffffffu, tm1, 1));
        tm1 = fmaxf(tm1, __shfl_xor_sync(0xffffffffu, tm1, 2));
        const float mn0 = fmaxf(m0, tm0), mn1 = fmaxf(m1, tm1);

        float sum0 = 0.f, sum1 = 0.f;
#pragma unroll
        for (int ni = 0; ni < 16; ni++) {
            float p0 = __expf(sacc[ni][0] - mn0);
            float p1 = __expf(sacc[ni][1] - mn0);
            float p2 = __expf(sacc[ni][2] - mn1);
            float p3 = __expf(sacc[ni][3] - mn1);
            sacc[ni][0] = p0; sacc[ni][1] = p1; sacc[ni][2] = p2; sacc[ni][3] = p3;
            sum0 += p0 + p1; sum1 += p2 + p3;
        }
        sum0 += __shfl_xor_sync(0xffffffffu, sum0, 1);
        sum0 += __shfl_xor_sync(0xffffffffu, sum0, 2);
        sum1 += __shfl_xor_sync(0xffffffffu, sum1, 1);
        sum1 += __shfl_xor_sync(0xffffffffu, sum1, 2);

        const float sc0 = __expf(m0 - mn0), sc1 = __expf(m1 - mn1);
        l0 = l0 * sc0 + sum0;  l1 = l1 * sc1 + sum1;
        m0 = mn0;  m1 = mn1;
#pragma unroll
        for (int nj = 0; nj < 8; nj++) {
            oacc[nj][0] *= sc0; oacc[nj][1] *= sc0;
            oacc[nj][2] *= sc1; oacc[nj][3] *= sc1;
        }

        // ---- O += P @ V: S-fragment repack + ldmatrix.trans V ----
        {
            const uint32_t vB = vL + buf * 18432u;
#pragma unroll
            for (int k2 = 0; k2 < 8; k2++) {
                uint32_t pa[4];
                pa[0] = packh2(sacc[2 * k2][0],     sacc[2 * k2][1]);
                pa[1] = packh2(sacc[2 * k2][2],     sacc[2 * k2][3]);
                pa[2] = packh2(sacc[2 * k2 + 1][0], sacc[2 * k2 + 1][1]);
                pa[3] = packh2(sacc[2 * k2 + 1][2], sacc[2 * k2 + 1][3]);
#pragma unroll
                for (int np = 0; np < 4; np++) {
                    uint32_t vv[4];
                    ldsm4t(vv, vB + k2 * (16 * 144) + np * 32);
                    mma_f16(oacc[2 * np],     pa, vv);
                    mma_f16(oacc[2 * np + 1], pa, vv + 2);
                }
            }
        }
        __syncthreads();
    }

    const float inv0 = 1.f / l0, inv1 = 1.f / l1;
    __half* orow0 = Op + (size_t)(qt * 128 + r0) * CC;
    __half* orow1 = orow0 + 8 * CC;
#pragma unroll
    for (int nj = 0; nj < 8; nj++) {
        *(__half2*)(orow0 + nj * 8 + qc * 2) =
            __floats2half2_rn(oacc[nj][0] * inv0, oacc[nj][1] * inv0);
        *(__half2*)(orow1 + nj * 8 + qc * 2) =
            __floats2half2_rn(oacc[nj][2] * inv1, oacc[nj][3] * inv1);
    }
}

// ============================ layernorm ==========================================
__device__ __forceinline__ float warpSum(float v) {
#pragma unroll
    for (int o = 16; o; o >>= 1) v += __shfl_xor_sync(0xffffffffu, v, o);
    return v;
}

template<bool DUALH>
__global__ void __launch_bounds__(256)
add_ln(const float* __restrict__ X, const float* __restrict__ R,
       const float* __restrict__ g, const float* __restrict__ be,
       float* __restrict__ out, __half* __restrict__ outh)
{
    const size_t row = blockIdx.x;
    const int tid = threadIdx.x;
    const int col = tid * 4;
    float4 xv = *(const float4*)(X + row * CC + col);
    float4 rv = *(const float4*)(R + row * CC + col);
    float4 v;
    v.x = xv.x + rv.x; v.y = xv.y + rv.y; v.z = xv.z + rv.z; v.w = xv.w + rv.w;

    __shared__ float sh1[8], sh2[8];
    float s = (v.x + v.y) + (v.z + v.w);
    float sq = v.x * v.x + v.y * v.y + v.z * v.z + v.w * v.w;
    s = warpSum(s); sq = warpSum(sq);
    if ((tid & 31) == 0) { sh1[tid >> 5] = s; sh2[tid >> 5] = sq; }
    __syncthreads();
    s  = (sh1[0] + sh1[1]) + (sh1[2] + sh1[3]) + (sh1[4] + sh1[5]) + (sh1[6] + sh1[7]);
    sq = (sh2[0] + sh2[1]) + (sh2[2] + sh2[3]) + (sh2[4] + sh2[5]) + (sh2[6] + sh2[7]);
    const float mean = s * (1.0f / CC);
    const float var = sq * (1.0f / CC) - mean * mean;
    const float rstd = rsqrtf(var + 1e-5f);

    float4 gg = *(const float4*)(g + col);
    float4 bb = *(const float4*)(be + col);
    float4 o;
    o.x = (v.x - mean) * rstd * gg.x + bb.x;
    o.y = (v.y - mean) * rstd * gg.y + bb.y;
    o.z = (v.z - mean) * rstd * gg.z + bb.z;
    o.w = (v.w - mean) * rstd * gg.w + bb.w;
    *(float4*)(out + row * CC + col) = o;
    if (DUALH) {
        *(__half2*)(outh + row * CC + col)     = __floats2half2_rn(o.x, o.y);
        *(__half2*)(outh + row * CC + col + 2) = __floats2half2_rn(o.z, o.w);
    }
}

// ------------------------------- launcher ---------------------------------------
extern "C" void kernel_launch(void* const* d_in, const int* in_sizes, int n_in,
                              void* d_out, int out_size)
{
    const float* x    = (const float*)d_in[0];
    const float* enc  = (const float*)d_in[1];
    const unsigned char* tmask = (const unsigned char*)d_in[2];
    const unsigned char* smask = (const unsigned char*)d_in[3];
    const float* Wq1 = (const float*)d_in[4];
    const float* Wk1 = (const float*)d_in[5];
    const float* Wv1 = (const float*)d_in[6];
    const float* Wo1 = (const float*)d_in[7];
    const float* ln1g = (const float*)d_in[8];
    const float* ln1b = (const float*)d_in[9];
    const float* Wq2 = (const float*)d_in[10];
    const float* Wk2 = (const float*)d_in[11];
    const float* Wv2 = (const float*)d_in[12];
    const float* Wo2 = (const float*)d_in[13];
    const float* ln2g = (const float*)d_in[14];
    const float* ln2b = (const float*)d_in[15];
    const float* Wf1 = (const float*)d_in[16];
    const float* bf1 = (const float*)d_in[17];
    const float* Wf2 = (const float*)d_in[18];
    const float* bf2 = (const float*)d_in[19];
    const float* ln3g = (const float*)d_in[20];
    const float* ln3b = (const float*)d_in[21];
    float* out = (float*)d_out;

    float *go, *gx1, *gx2;
    __half *gxh, *geh, *gqh, *gctxh, *gx1h, *gx2h, *gffh, *gwth;
    cudaGetSymbolAddress((void**)&go,  g_o);
    cudaGetSymbolAddress((void**)&gx1, g_x1);
    cudaGetSymbolAddress((void**)&gx2, g_x2);
    cudaGetSymbolAddress((void**)&gxh, g_xh);
    cudaGetSymbolAddress((void**)&geh, g_eh);
    cudaGetSymbolAddress((void**)&gqh, g_qh);
    cudaGetSymbolAddress((void**)&gctxh, g_ctxh);
    cudaGetSymbolAddress((void**)&gx1h, g_x1h);
    cudaGetSymbolAddress((void**)&gx2h, g_x2h);
    cudaGetSymbolAddress((void**)&gffh, g_ffh);
    cudaGetSymbolAddress((void**)&gwth, g_wth);

    __half* tq1 = gwth + 0u * 1048576u;   // tq1,tk1,tv1 contiguous -> [3072,1024]
    __half* tk1 = gwth + 1u * 1048576u;
    __half* tv1 = gwth + 2u * 1048576u;
    __half* to1 = gwth + 3u * 1048576u;
    __half* tq2 = gwth + 4u * 1048576u;
    __half* tk2 = gwth + 5u * 1048576u;   // tk2,tv2 contiguous -> [2048,1024]
    __half* tv2 = gwth + 6u * 1048576u;
    __half* to2 = gwth + 7u * 1048576u;
    __half* tf1 = gwth + 8u * 1048576u;              // [F, C]
    __half* tf2 = gwth + 8u * 1048576u + 4194304u;   // [C, F]

    auto* kProj  = gemm_mma<false, false, false>;   // fp32 out (-> add_ln)
    auto* kProjH = gemm_mma<false, false, true >;   // half out (-> flash / GEMM-A)
    auto* kFfn1  = gemm_mma<true,  true,  true >;   // bias+relu, half out
    auto* kFfn2  = gemm_mma<true,  false, false>;
    cudaFuncSetAttribute(kProj,  cudaFuncAttributeMaxDynamicSharedMemorySize, GSMEM);
    cudaFuncSetAttribute(kProjH, cudaFuncAttributeMaxDynamicSharedMemorySize, GSMEM);
    cudaFuncSetAttribute(kFfn1,  cudaFuncAttributeMaxDynamicSharedMemorySize, GSMEM);
    cudaFuncSetAttribute(kFfn2,  cudaFuncAttributeMaxDynamicSharedMemorySize, GSMEM);
    cudaFuncSetAttribute(flash_k<true>,  cudaFuncAttributeMaxDynamicSharedMemorySize, FSMEM);
    cudaFuncSetAttribute(flash_k<false>, cudaFuncAttributeMaxDynamicSharedMemorySize, FSMEM);

    const dim3 blk(256);
    const dim3 tblk(32, 8);

    // ---- fp16 conversion of external GEMM-A inputs (1 launch) ----
    Ptr2h p2;
    p2.s[0] = x;   p2.d[0] = gxh;
    p2.s[1] = enc; p2.d[1] = geh;
    round2h<<<dim3(MM * CC / 1024, 2), blk>>>(p2);

    // ---- weight transposes (K-major, fp16 B operands) ----
    Ptr8h p8;
    p8.s[0] = Wq1; p8.d[0] = tq1;  p8.s[1] = Wk1; p8.d[1] = tk1;
    p8.s[2] = Wv1; p8.d[2] = tv1;  p8.s[3] = Wo1; p8.d[3] = to1;
    p8.s[4] = Wq2; p8.d[4] = tq2;  p8.s[5] = Wk2; p8.d[5] = tk2;
    p8.s[6] = Wv2; p8.d[6] = tv2;  p8.s[7] = Wo2; p8.d[7] = to2;
    transpose8h<<<dim3(CC/32, CC/32, 8), tblk>>>(p8);
    transpose_w2<<<8192, tblk>>>(Wf1, tf1, Wf2, tf2);

    const dim3 gQKV(3072/128, MM/128);   // (24, 32) fused self QKV
    const dim3 gKV (2048/128, MM/128);   // (16, 32) fused cross KV
    const dim3 gP  (CC/128,   MM/128);   // (8, 32)
    const dim3 gF1 (FF/128,   MM/128);   // (32, 32)
    const dim3 gFl (TT/128, BB*HH);      // (8, 64)
    const int nLn = MM;

    // ---- self-attention (causal) ----
    kProjH<<<gQKV, blk, GSMEM>>>(gxh, tq1, nullptr, gffh, CC, CC, CC, 3072);
    flash_k<true><<<gFl, blk, FSMEM>>>(gffh, gffh + 1024, gffh + 2048, tmask, gctxh, 3072, 3072);
    kProj<<<gP, blk, GSMEM>>>(gctxh, to1, nullptr, go, CC, CC, CC, CC);
    add_ln<true><<<nLn, blk>>>(x, go, ln1g, ln1b, gx1, gx1h);

    // ---- cross-attention ----
    kProjH<<<gP,  blk, GSMEM>>>(gx1h, tq2, nullptr, gqh, CC, CC, CC, CC);
    kProjH<<<gKV, blk, GSMEM>>>(geh, tk2, nullptr, gffh, CC, CC, CC, 2048);
    flash_k<false><<<gFl, blk, FSMEM>>>(gqh, gffh, gffh + 1024, smask, gctxh, CC, 2048);
    kProj<<<gP, blk, GSMEM>>>(gctxh, to2, nullptr, go, CC, CC, CC, CC);
    add_ln<true><<<nLn, blk>>>(gx1, go, ln2g, ln2b, gx2, gx2h);

    // ---- FFN ----
    kFfn1<<<gF1, blk, GSMEM>>>(gx2h, tf1, bf1, gffh, CC, CC, CC, FF);
    kFfn2<<<gP,  blk, GSMEM>>>(gffh, tf2, bf2, go, FF, FF, FF, CC);
    add_ln<false><<<nLn, blk>>>(gx2, go, ln3g, ln3b, out, nullptr);
}

// round 14
// speedup vs baseline: 2.3291x; 1.0191x over previous
#include <cuda_runtime.h>
#include <cuda_fp16.h>
#include <cstdint>
#include <cstddef>

// Problem constants
#define BB 4
#define TT 1024
#define CC 1024
#define HH 16
#define DH 64
#define FF 4096
#define MM (BB*TT)          // 4096 rows

// ---------------- scratch (device globals; no allocation allowed) ----------------
__device__ float  g_o  [(size_t)MM*CC];        // GEMM fp32 outputs (pre-LN)
__device__ float  g_x1 [(size_t)MM*CC];
__device__ float  g_x2 [(size_t)MM*CC];
__device__ __half g_xh [(size_t)MM*CC];        // half GEMM-A operands
__device__ __half g_eh [(size_t)MM*CC];
__device__ __half g_qh [(size_t)MM*CC];        // cross-attn Q (half, flash input)
__device__ __half g_ctxh[(size_t)MM*CC];
__device__ __half g_x1h[(size_t)MM*CC];
__device__ __half g_x2h[(size_t)MM*CC];
__device__ __half g_ffh[(size_t)MM*FF];        // QKV / KV / FFN1 half outputs
__device__ __half g_wth[8u*1024u*1024u + 2u*4096u*1024u];   // half weights (K-major)

// ============================ small helpers ======================================
__device__ __forceinline__ void mma_f16(float* d, const uint32_t* a, const uint32_t* b) {
    asm volatile(
        "mma.sync.aligned.m16n8k16.row.col.f32.f16.f16.f32 "
        "{%0,%1,%2,%3},{%4,%5,%6,%7},{%8,%9},{%0,%1,%2,%3};"
        : "+f"(d[0]), "+f"(d[1]), "+f"(d[2]), "+f"(d[3])
        : "r"(a[0]), "r"(a[1]), "r"(a[2]), "r"(a[3]),
          "r"(b[0]), "r"(b[1]));
}
__device__ __forceinline__ void ldsm4(uint32_t* r, uint32_t addr) {
    asm volatile("ldmatrix.sync.aligned.m8n8.x4.shared.b16 {%0,%1,%2,%3}, [%4];"
                 : "=r"(r[0]), "=r"(r[1]), "=r"(r[2]), "=r"(r[3]) : "r"(addr));
}
__device__ __forceinline__ void ldsm4t(uint32_t* r, uint32_t addr) {
    asm volatile("ldmatrix.sync.aligned.m8n8.x4.trans.shared.b16 {%0,%1,%2,%3}, [%4];"
                 : "=r"(r[0]), "=r"(r[1]), "=r"(r[2]), "=r"(r[3]) : "r"(addr));
}
__device__ __forceinline__ uint32_t smem_u32(const void* p) {
    uint32_t a;
    asm("{ .reg .u64 t; cvta.to.shared.u64 t, %1; cvt.u32.u64 %0, t; }" : "=r"(a) : "l"(p));
    return a;
}
__device__ __forceinline__ void cp16(uint32_t dst, const void* src) {
    asm volatile("cp.async.cg.shared.global [%0], [%1], 16;" :: "r"(dst), "l"(src));
}
__device__ __forceinline__ void bulk128(uint32_t dst, const void* src, uint32_t mbar) {
    asm volatile("cp.async.bulk.shared::cta.global.mbarrier::complete_tx::bytes "
                 "[%0], [%1], 128, [%2];"
                 :: "r"(dst), "l"(src), "r"(mbar) : "memory");
}
__device__ __forceinline__ void mbar_init1(uint32_t a) {
    asm volatile("mbarrier.init.shared.b64 [%0], 1;" :: "r"(a) : "memory");
}
__device__ __forceinline__ void mbar_expect(uint32_t a, uint32_t bytes) {
    asm volatile("mbarrier.arrive.expect_tx.shared.b64 _, [%0], %1;"
                 :: "r"(a), "r"(bytes) : "memory");
}
__device__ __forceinline__ void mbar_wait(uint32_t a, uint32_t ph) {
    uint32_t done;
    asm volatile("{\n\t.reg .pred p;\n\t"
                 "mbarrier.try_wait.parity.acquire.cta.shared::cta.b64 p, [%1], %2;\n\t"
                 "selp.b32 %0,1,0,p;\n\t}"
                 : "=r"(done) : "r"(a), "r"(ph) : "memory");
    if (!done) {
        asm volatile("{\n\t.reg .pred P1;\n\t"
                     "WL%=:\n\t"
                     "mbarrier.try_wait.parity.acquire.cta.shared::cta.b64 P1, [%0], %1, 0x989680;\n\t"
                     "@P1 bra.uni WD%=;\n\t"
                     "bra.uni WL%=;\n\t"
                     "WD%=:\n\t}"
                     :: "r"(a), "r"(ph) : "memory");
    }
}
__device__ __forceinline__ uint32_t packh2(float a, float b) {
    __half2 h = __floats2half2_rn(a, b);
    return *(uint32_t*)&h;
}

// =================== fp16 conversion copy (2 tensors, z-batched) =================
struct Ptr2h { const float* s[2]; __half* d[2]; };
__global__ void __launch_bounds__(256)
round2h(Ptr2h p)
{
    const float* in = p.s[blockIdx.y];
    __half* out = p.d[blockIdx.y];
    const size_t i = ((size_t)blockIdx.x * 256 + threadIdx.x) * 4;
    float4 v = *(const float4*)(in + i);
    *(__half2*)(out + i)     = __floats2half2_rn(v.x, v.y);
    *(__half2*)(out + i + 2) = __floats2half2_rn(v.z, v.w);
}

// ====================== 32x32 tiled transposes (fp16 out) ========================
struct Ptr8h { const float* s[8]; __half* d[8]; };

__global__ void __launch_bounds__(256)
transpose8h(Ptr8h ps)   // 8 square [CC x CC] weights, z selects matrix
{
    const float* in = ps.s[blockIdx.z];
    __half* out = ps.d[blockIdx.z];
    __shared__ float t[32][33];
    const int bx = blockIdx.x * 32, by = blockIdx.y * 32;
    int x = bx + threadIdx.x;
#pragma unroll
    for (int i = 0; i < 32; i += 8)
        t[threadIdx.y + i][threadIdx.x] = in[(size_t)(by + threadIdx.y + i) * CC + x];
    __syncthreads();
    x = by + threadIdx.x;
#pragma unroll
    for (int i = 0; i < 32; i += 8)
        out[(size_t)(bx + threadIdx.y + i) * CC + x] = __float2half_rn(t[threadIdx.x][threadIdx.y + i]);
}

// both FFN weight transposes in one launch (1D grid, 8192 tiles)
__global__ void __launch_bounds__(256)
transpose_w2(const float* __restrict__ Wf1, __half* __restrict__ tf1,
             const float* __restrict__ Wf2, __half* __restrict__ tf2)
{
    const int bid = blockIdx.x;
    const bool second = bid >= 4096;
    const int tile = second ? bid - 4096 : bid;
    const float* in;  __half* outp;  int R, C, bx, by;
    if (!second) { in = Wf1; outp = tf1; R = CC; C = FF; bx = (tile & 127) * 32; by = (tile >> 7) * 32; }
    else         { in = Wf2; outp = tf2; R = FF; C = CC; bx = (tile & 31)  * 32; by = (tile >> 5) * 32; }
    const int tx = threadIdx.x, ty = threadIdx.y;
    __shared__ float t[32][33];
    int x = bx + tx;
#pragma unroll
    for (int i = 0; i < 32; i += 8)
        t[ty + i][tx] = in[(size_t)(by + ty + i) * C + x];
    __syncthreads();
    x = by + tx;
#pragma unroll
    for (int i = 0; i < 32; i += 8)
        outp[(size_t)(bx + ty + i) * R + x] = __float2half_rn(t[tx][ty + i]);
}

// ================= fp16 mma.sync GEMM: C[M,N] = A[M,K] @ Bt[N,K]^T ===============
// Stage loads via cp.async.bulk (1x128B per thread per stage) + mbarrier,
// replacing 2048 cp.async issues per stage. Fragment path unchanged (R13).
#define G_LDPH 72                            // halfs per row (64 data + 8 pad)
#define G_STGH (256 * G_LDPH)                // halfs per stage (A128 + B128 rows)
#define GSMEM  (3 * G_STGH * 2 + 64)         // + 3 mbarriers (aligned)

template<bool BIAS, bool RELU, bool HOUT>
__global__ void __launch_bounds__(256, 2)
gemm_mma(const __half* __restrict__ A, const __half* __restrict__ Bt,
         const float* __restrict__ bias, void* __restrict__ Cv,
         int K, int lda, int ldb, int ldc)
{
    extern __shared__ __half smh[];
    const int bxn = blockIdx.x * 128, bym = blockIdx.y * 128;
    const int tid = threadIdx.x, wid = tid >> 5, lane = tid & 31;
    const int wr = wid >> 2, wc = wid & 3;      // 2 x 4 warps, 64x32 each
    const int g = lane >> 2, qc = lane & 3;

    const uint32_t smb = smem_u32(smh);
    const uint32_t mbar0 = smb + 3 * G_STGH * 2;

    // one 128-byte row per thread per stage: tid<128 -> A row, else B row
    const __half* gsrc = (tid < 128)
        ? (A  + (size_t)(bym + tid) * lda)
        : (Bt + (size_t)(bxn + tid - 128) * ldb);
    const uint32_t sdst = smb + (uint32_t)tid * (G_LDPH * 2);

    const int l15 = lane & 15, l7 = lane & 7;
    const uint32_t aL = smb
        + (uint32_t)(((wr * 64 + l15) * G_LDPH + (lane >> 4) * 8) * 2);
    const uint32_t bL = smb + 128 * G_LDPH * 2
        + (uint32_t)(((wc * 32 + l7 + (lane >> 4) * 8) * G_LDPH + ((lane >> 3) & 1) * 8) * 2);

    float acc[4][4][4];
#pragma unroll
    for (int i = 0; i < 4; i++)
#pragma unroll
        for (int j = 0; j < 4; j++)
#pragma unroll
            for (int r = 0; r < 4; r++) acc[i][j][r] = 0.f;

    const int nst = K >> 6;                    // K-stage = 64 halfs

    if (tid == 0) {
        mbar_init1(mbar0);
        mbar_init1(mbar0 + 8);
        mbar_init1(mbar0 + 16);
        asm volatile("fence.proxy.async.shared::cta;" ::: "memory");
    }
    __syncthreads();

    // prologue: stages 0, 1
#pragma unroll
    for (int s = 0; s < 2; s++) {
        if (tid == 0) mbar_expect(mbar0 + s * 8, 32768u);
        bulk128(sdst + s * (G_STGH * 2), gsrc + s * 64, mbar0 + s * 8);
    }

    int buf = 0, nxt = 2;      // nxt = (it+2) % 3
    int pw = 0;                // parity of stage being waited (flips on buf wrap)
    for (int it = 0; it < nst; ++it) {
        mbar_wait(mbar0 + buf * 8, pw);
        __syncthreads();
        const uint32_t aB = aL + (uint32_t)buf * G_STGH * 2;
        const uint32_t bB = bL + (uint32_t)buf * G_STGH * 2;

        uint32_t av_[2][4][4], bv_[2][2][4];
#pragma unroll
        for (int mi = 0; mi < 4; mi++)
            ldsm4(av_[0][mi], aB + mi * (16 * G_LDPH * 2));
#pragma unroll
        for (int np = 0; np < 2; np++)
            ldsm4(bv_[0][np], bB + np * (16 * G_LDPH * 2));
#pragma unroll
        for (int ks = 0; ks < 4; ks++) {       // 4 x k16, frag double-buffered
            const int c = ks & 1;
            if (ks < 3) {
#pragma unroll
                for (int mi = 0; mi < 4; mi++)
                    ldsm4(av_[c ^ 1][mi], aB + mi * (16 * G_LDPH * 2) + (ks + 1) * 32);
#pragma unroll
                for (int np = 0; np < 2; np++)
                    ldsm4(bv_[c ^ 1][np], bB + np * (16 * G_LDPH * 2) + (ks + 1) * 32);
            }
#pragma unroll
            for (int mi = 0; mi < 4; mi++)
#pragma unroll
                for (int ni = 0; ni < 4; ni++)
                    mma_f16(acc[mi][ni], av_[c][mi], &bv_[c][ni >> 1][(ni & 1) * 2]);
        }
        if (it + 2 < nst) {
            const int kt = it + 2;
            if (tid == 0) mbar_expect(mbar0 + nxt * 8, 32768u);
            bulk128(sdst + nxt * (G_STGH * 2), gsrc + kt * 64, mbar0 + nxt * 8);
        }
        if (buf == 2) { buf = 0; pw ^= 1; } else buf++;
        nxt = (nxt == 2) ? 0 : nxt + 1;
    }

#pragma unroll
    for (int mi = 0; mi < 4; mi++) {
        const int r = bym + wr * 64 + mi * 16 + g;
#pragma unroll
        for (int ni = 0; ni < 4; ni++) {
            const int col = bxn + wc * 32 + ni * 8 + qc * 2;
            float2 bv = make_float2(0.f, 0.f);
            if (BIAS) bv = *(const float2*)(bias + col);
            float2 v0, v1;
            v0.x = acc[mi][ni][0] + bv.x;
            v0.y = acc[mi][ni][1] + bv.y;
            v1.x = acc[mi][ni][2] + bv.x;
            v1.y = acc[mi][ni][3] + bv.y;
            if (RELU) {
                v0.x = fmaxf(v0.x, 0.f); v0.y = fmaxf(v0.y, 0.f);
                v1.x = fmaxf(v1.x, 0.f); v1.y = fmaxf(v1.y, 0.f);
            }
            if (HOUT) {
                __half* C = (__half*)Cv;
                *(__half2*)(C + (size_t)r * ldc + col)       = __floats2half2_rn(v0.x, v0.y);
                *(__half2*)(C + (size_t)(r + 8) * ldc + col) = __floats2half2_rn(v1.x, v1.y);
            } else {
                float* C = (float*)Cv;
                *(float2*)(C + (size_t)r * ldc + col)       = v0;
                *(float2*)(C + (size_t)(r + 8) * ldc + col) = v1;
            }
        }
    }
}

// ====================== flash attention (fp16 mma, ldmatrix) =====================
// (byte-identical to R13 — passing 843us config)
#define FLB_K  18432
#define FLB_V  55296
#define FLB_M  92160
#define FSMEM  (92160 + 264)

template<bool CAUSAL>
__global__ void __launch_bounds__(256, 2)
flash_k(const __half* __restrict__ Qg, const __half* __restrict__ Kg,
        const __half* __restrict__ Vg, const unsigned char* __restrict__ padg,
        __half* __restrict__ Og, int ldq, int ldk)
{
    extern __shared__ __half smh[];
    const int tid = threadIdx.x, lane = tid & 31, w = tid >> 5;
    const int g = lane >> 2, qc = lane & 3;
    const int qt = blockIdx.x;
    const int z = blockIdx.y, b = z >> 4, h = z & 15;

    const __half* Qp = Qg + (size_t)b * TT * ldq + h * 64;
    const __half* Kp = Kg + (size_t)b * TT * ldk + h * 64;
    const __half* Vp = Vg + (size_t)b * TT * ldk + h * 64;   // same layout as K
    const unsigned char* padp = padg + (size_t)b * TT;
    __half* Op = Og + (size_t)b * TT * CC + h * 64;

    const uint32_t sQa = smem_u32(smh);
    const uint32_t sKa = sQa + FLB_K;
    const uint32_t sVa = sQa + FLB_V;
    uint32_t* sMskp = (uint32_t*)((char*)smh + FLB_M);

    const int l15 = lane & 15, l7 = lane & 7;
    const uint32_t qL = sQa + (uint32_t)(((w * 16 + l15) * 72 + (lane >> 4) * 8) * 2);
    const uint32_t kL = sKa + (uint32_t)(((l7 + (lane >> 4) * 8) * 72 + ((lane >> 3) & 1) * 8) * 2);
    const uint32_t vL = sVa + (uint32_t)(((l7 + ((lane >> 3) & 1) * 8) * 72 + (lane >> 4) * 8) * 2);

    const int nkt = CAUSAL ? qt + 1 : (TT / 128);

    {   // Q tile: 128 rows x 64 halfs, rows padded to 72 halfs (144 B)
        const __half* qs = Qp + (size_t)(qt * 128 + (tid >> 1)) * ldq + (tid & 1) * 32;
        uint32_t qd = sQa + (tid >> 1) * 144 + (tid & 1) * 64;
#pragma unroll
        for (int j = 0; j < 4; j++) cp16(qd + j * 16, qs + j * 8);
    }
    auto issue_kv = [&](int kt, int buf) {
        const __half* ks = Kp + (size_t)(kt * 128 + (tid >> 1)) * ldk + (tid & 1) * 32;
        uint32_t kd = sKa + buf * 18432u + (tid >> 1) * 144 + (tid & 1) * 64;
#pragma unroll
        for (int j = 0; j < 4; j++) cp16(kd + j * 16, ks + j * 8);
        const __half* vs = Vp + (size_t)(kt * 128 + (tid >> 1)) * ldk + (tid & 1) * 32;
        uint32_t vd = sVa + buf * 18432u + (tid >> 1) * 144 + (tid & 1) * 64;
#pragma unroll
        for (int j = 0; j < 4; j++) cp16(vd + j * 16, vs + j * 8);
        if (tid < 32) {
            uint32_t mv = *(const uint32_t*)(padp + (size_t)kt * 128 + tid * 4);
            sMskp[buf * 32 + tid] = mv;
            uint32_t f = __reduce_or_sync(0xffffffffu, mv);
            if (tid == 0) sMskp[64 + buf] = f;
        }
    };
    issue_kv(0, 0);
    asm volatile("cp.async.commit_group;" ::: "memory");

    float m0 = -INFINITY, m1 = -INFINITY, l0 = 0.f, l1 = 0.f;
    float oacc[8][4];
#pragma unroll
    for (int j = 0; j < 8; j++)
#pragma unroll
        for (int r = 0; r < 4; r++) oacc[j][r] = 0.f;

    const int r0 = w * 16 + g, r1 = r0 + 8;

    for (int kt = 0; kt < nkt; ++kt) {
        const int buf = kt & 1;
        if (kt + 1 < nkt) {
            issue_kv(kt + 1, buf ^ 1);
            asm volatile("cp.async.commit_group;" ::: "memory");
            asm volatile("cp.async.wait_group 1;" ::: "memory");
        } else {
            asm volatile("cp.async.wait_group 0;" ::: "memory");
        }
        __syncthreads();

        float sacc[16][4];
#pragma unroll
        for (int ni = 0; ni < 16; ni++)
#pragma unroll
            for (int r = 0; r < 4; r++) sacc[ni][r] = 0.f;
        {
            const uint32_t kB = kL + buf * 18432u;
#pragma unroll
            for (int ks = 0; ks < 4; ks++) {
                uint32_t aq[4];
                ldsm4(aq, qL + ks * 32);
#pragma unroll
                for (int np = 0; np < 8; np++) {
                    uint32_t kv4[4];
                    ldsm4(kv4, kB + np * (16 * 144) + ks * 32);
                    mma_f16(sacc[2 * np],     aq, kv4);
                    mma_f16(sacc[2 * np + 1], aq, kv4 + 2);
                }
            }
        }

        const uint32_t pf = sMskp[64 + buf];
        const unsigned char* mb = (const unsigned char*)(sMskp + buf * 32);
        float tm0 = -INFINITY, tm1 = -INFINITY;
#pragma unroll
        for (int ni = 0; ni < 16; ni++) {
            float s0 = sacc[ni][0] * 0.125f, s1 = sacc[ni][1] * 0.125f;
            float s2 = sacc[ni][2] * 0.125f, s3 = sacc[ni][3] * 0.125f;
            const int c0 = ni * 8 + qc * 2;
            if (CAUSAL && kt == qt) {
                if (c0     > r0) s0 = -INFINITY;
                if (c0 + 1 > r0) s1 = -INFINITY;
                if (c0     > r1) s2 = -INFINITY;
                if (c0 + 1 > r1) s3 = -INFINITY;
            }
            if (pf) {
                if (mb[c0])     { s0 = -INFINITY; s2 = -INFINITY; }
                if (mb[c0 + 1]) { s1 = -INFINITY; s3 = -INFINITY; }
            }
            sacc[ni][0] = s0; sacc[ni][1] = s1; sacc[ni][2] = s2; sacc[ni][3] = s3;
            tm0 = fmaxf(tm0, fmaxf(s0, s1));
            tm1 = fmaxf(tm1, fmaxf(s2, s3));
        }
        tm0 = fmaxf(tm0, __shfl_xor_sync(0xffffffffu, tm0, 1));
        tm0 = fmaxf(tm0, __shfl_xor_sync(0xffffffffu, tm0, 2));
        tm1 = fmaxf(tm1, __shfl_xor_sync(0xffffffffu, tm1, 1));
        tm1 = fmaxf(tm1, __shfl_xor_sync(0xffffffffu, tm1, 2));
        const float mn0 = fmaxf(m0, tm0), mn1 = fmaxf(m1, tm1);

        float sum0 = 0.f, sum1 = 0.f;
#pragma unroll
        for (int ni = 0; ni < 16; ni++) {
            float p0 = __expf(sacc[ni][0] - mn0);
            float p1 = __expf(sacc[ni][1] - mn0);
            float p2 = __expf(sacc[ni][2] - mn1);
            float p3 = __expf(sacc[ni][3] - mn1);
            sacc[ni][0] = p0; sacc[ni][1] = p1; sacc[ni][2] = p2; sacc[ni][3] = p3;
            sum0 += p0 + p1; sum1 += p2 + p3;
        }
        sum0 += __shfl_xor_sync(0xffffffffu, sum0, 1);
        sum0 += __shfl_xor_sync(0xffffffffu, sum0, 2);
        sum1 += __shfl_xor_sync(0xffffffffu, sum1, 1);
        sum1 += __shfl_xor_sync(0xffffffffu, sum1, 2);

        const float sc0 = __expf(m0 - mn0), sc1 = __expf(m1 - mn1);
        l0 = l0 * sc0 + sum0;  l1 = l1 * sc1 + sum1;
        m0 = mn0;  m1 = mn1;
#pragma unroll
        for (int nj = 0; nj < 8; nj++) {
            oacc[nj][0] *= sc0; oacc[nj][1] *= sc0;
            oacc[nj][2] *= sc1; oacc[nj][3] *= sc1;
        }

        {
            const uint32_t vB = vL + buf * 18432u;
#pragma unroll
            for (int k2 = 0; k2 < 8; k2++) {
                uint32_t pa[4];
                pa[0] = packh2(sacc[2 * k2][0],     sacc[2 * k2][1]);
                pa[1] = packh2(sacc[2 * k2][2],     sacc[2 * k2][3]);
                pa[2] = packh2(sacc[2 * k2 + 1][0], sacc[2 * k2 + 1][1]);
                pa[3] = packh2(sacc[2 * k2 + 1][2], sacc[2 * k2 + 1][3]);
#pragma unroll
                for (int np = 0; np < 4; np++) {
                    uint32_t vv[4];
                    ldsm4t(vv, vB + k2 * (16 * 144) + np * 32);
                    mma_f16(oacc[2 * np],     pa, vv);
                    mma_f16(oacc[2 * np + 1], pa, vv + 2);
                }
            }
        }
        __syncthreads();
    }

    const float inv0 = 1.f / l0, inv1 = 1.f / l1;
    __half* orow0 = Op + (size_t)(qt * 128 + r0) * CC;
    __half* orow1 = orow0 + 8 * CC;
#pragma unroll
    for (int nj = 0; nj < 8; nj++) {
        *(__half2*)(orow0 + nj * 8 + qc * 2) =
            __floats2half2_rn(oacc[nj][0] * inv0, oacc[nj][1] * inv0);
        *(__half2*)(orow1 + nj * 8 + qc * 2) =
            __floats2half2_rn(oacc[nj][2] * inv1, oacc[nj][3] * inv1);
    }
}

// ============================ layernorm ==========================================
__device__ __forceinline__ float warpSum(float v) {
#pragma unroll
    for (int o = 16; o; o >>= 1) v += __shfl_xor_sync(0xffffffffu, v, o);
    return v;
}

template<bool DUALH>
__global__ void __launch_bounds__(256)
add_ln(const float* __restrict__ X, const float* __restrict__ R,
       const float* __restrict__ g, const float* __restrict__ be,
       float* __restrict__ out, __half* __restrict__ outh)
{
    const size_t row = blockIdx.x;
    const int tid = threadIdx.x;
    const int col = tid * 4;
    float4 xv = *(const float4*)(X + row * CC + col);
    float4 rv = *(const float4*)(R + row * CC + col);
    float4 v;
    v.x = xv.x + rv.x; v.y = xv.y + rv.y; v.z = xv.z + rv.z; v.w = xv.w + rv.w;

    __shared__ float sh1[8], sh2[8];
    float s = (v.x + v.y) + (v.z + v.w);
    float sq = v.x * v.x + v.y * v.y + v.z * v.z + v.w * v.w;
    s = warpSum(s); sq = warpSum(sq);
    if ((tid & 31) == 0) { sh1[tid >> 5] = s; sh2[tid >> 5] = sq; }
    __syncthreads();
    s  = (sh1[0] + sh1[1]) + (sh1[2] + sh1[3]) + (sh1[4] + sh1[5]) + (sh1[6] + sh1[7]);
    sq = (sh2[0] + sh2[1]) + (sh2[2] + sh2[3]) + (sh2[4] + sh2[5]) + (sh2[6] + sh2[7]);
    const float mean = s * (1.0f / CC);
    const float var = sq * (1.0f / CC) - mean * mean;
    const float rstd = rsqrtf(var + 1e-5f);

    float4 gg = *(const float4*)(g + col);
    float4 bb = *(const float4*)(be + col);
    float4 o;
    o.x = (v.x - mean) * rstd * gg.x + bb.x;
    o.y = (v.y - mean) * rstd * gg.y + bb.y;
    o.z = (v.z - mean) * rstd * gg.z + bb.z;
    o.w = (v.w - mean) * rstd * gg.w + bb.w;
    *(float4*)(out + row * CC + col) = o;
    if (DUALH) {
        *(__half2*)(outh + row * CC + col)     = __floats2half2_rn(o.x, o.y);
        *(__half2*)(outh + row * CC + col + 2) = __floats2half2_rn(o.z, o.w);
    }
}

// ------------------------------- launcher ---------------------------------------
extern "C" void kernel_launch(void* const* d_in, const int* in_sizes, int n_in,
                              void* d_out, int out_size)
{
    const float* x    = (const float*)d_in[0];
    const float* enc  = (const float*)d_in[1];
    const unsigned char* tmask = (const unsigned char*)d_in[2];
    const unsigned char* smask = (const unsigned char*)d_in[3];
    const float* Wq1 = (const float*)d_in[4];
    const float* Wk1 = (const float*)d_in[5];
    const float* Wv1 = (const float*)d_in[6];
    const float* Wo1 = (const float*)d_in[7];
    const float* ln1g = (const float*)d_in[8];
    const float* ln1b = (const float*)d_in[9];
    const float* Wq2 = (const float*)d_in[10];
    const float* Wk2 = (const float*)d_in[11];
    const float* Wv2 = (const float*)d_in[12];
    const float* Wo2 = (const float*)d_in[13];
    const float* ln2g = (const float*)d_in[14];
    const float* ln2b = (const float*)d_in[15];
    const float* Wf1 = (const float*)d_in[16];
    const float* bf1 = (const float*)d_in[17];
    const float* Wf2 = (const float*)d_in[18];
    const float* bf2 = (const float*)d_in[19];
    const float* ln3g = (const float*)d_in[20];
    const float* ln3b = (const float*)d_in[21];
    float* out = (float*)d_out;

    float *go, *gx1, *gx2;
    __half *gxh, *geh, *gqh, *gctxh, *gx1h, *gx2h, *gffh, *gwth;
    cudaGetSymbolAddress((void**)&go,  g_o);
    cudaGetSymbolAddress((void**)&gx1, g_x1);
    cudaGetSymbolAddress((void**)&gx2, g_x2);
    cudaGetSymbolAddress((void**)&gxh, g_xh);
    cudaGetSymbolAddress((void**)&geh, g_eh);
    cudaGetSymbolAddress((void**)&gqh, g_qh);
    cudaGetSymbolAddress((void**)&gctxh, g_ctxh);
    cudaGetSymbolAddress((void**)&gx1h, g_x1h);
    cudaGetSymbolAddress((void**)&gx2h, g_x2h);
    cudaGetSymbolAddress((void**)&gffh, g_ffh);
    cudaGetSymbolAddress((void**)&gwth, g_wth);

    __half* tq1 = gwth + 0u * 1048576u;   // tq1,tk1,tv1 contiguous -> [3072,1024]
    __half* tk1 = gwth + 1u * 1048576u;
    __half* tv1 = gwth + 2u * 1048576u;
    __half* to1 = gwth + 3u * 1048576u;
    __half* tq2 = gwth + 4u * 1048576u;
    __half* tk2 = gwth + 5u * 1048576u;   // tk2,tv2 contiguous -> [2048,1024]
    __half* tv2 = gwth + 6u * 1048576u;
    __half* to2 = gwth + 7u * 1048576u;
    __half* tf1 = gwth + 8u * 1048576u;              // [F, C]
    __half* tf2 = gwth + 8u * 1048576u + 4194304u;   // [C, F]

    auto* kProj  = gemm_mma<false, false, false>;   // fp32 out (-> add_ln)
    auto* kProjH = gemm_mma<false, false, true >;   // half out (-> flash / GEMM-A)
    auto* kFfn1  = gemm_mma<true,  true,  true >;   // bias+relu, half out
    auto* kFfn2  = gemm_mma<true,  false, false>;
    cudaFuncSetAttribute(kProj,  cudaFuncAttributeMaxDynamicSharedMemorySize, GSMEM);
    cudaFuncSetAttribute(kProjH, cudaFuncAttributeMaxDynamicSharedMemorySize, GSMEM);
    cudaFuncSetAttribute(kFfn1,  cudaFuncAttributeMaxDynamicSharedMemorySize, GSMEM);
    cudaFuncSetAttribute(kFfn2,  cudaFuncAttributeMaxDynamicSharedMemorySize, GSMEM);
    cudaFuncSetAttribute(flash_k<true>,  cudaFuncAttributeMaxDynamicSharedMemorySize, FSMEM);
    cudaFuncSetAttribute(flash_k<false>, cudaFuncAttributeMaxDynamicSharedMemorySize, FSMEM);

    const dim3 blk(256);
    const dim3 tblk(32, 8);

    // ---- fp16 conversion of external GEMM-A inputs (1 launch) ----
    Ptr2h p2;
    p2.s[0] = x;   p2.d[0] = gxh;
    p2.s[1] = enc; p2.d[1] = geh;
    round2h<<<dim3(MM * CC / 1024, 2), blk>>>(p2);

    // ---- weight transposes (K-major, fp16 B operands) ----
    Ptr8h p8;
    p8.s[0] = Wq1; p8.d[0] = tq1;  p8.s[1] = Wk1; p8.d[1] = tk1;
    p8.s[2] = Wv1; p8.d[2] = tv1;  p8.s[3] = Wo1; p8.d[3] = to1;
    p8.s[4] = Wq2; p8.d[4] = tq2;  p8.s[5] = Wk2; p8.d[5] = tk2;
    p8.s[6] = Wv2; p8.d[6] = tv2;  p8.s[7] = Wo2; p8.d[7] = to2;
    transpose8h<<<dim3(CC/32, CC/32, 8), tblk>>>(p8);
    transpose_w2<<<8192, tblk>>>(Wf1, tf1, Wf2, tf2);

    const dim3 gQKV(3072/128, MM/128);   // (24, 32) fused self QKV
    const dim3 gKV (2048/128, MM/128);   // (16, 32) fused cross KV
    const dim3 gP  (CC/128,   MM/128);   // (8, 32)
    const dim3 gF1 (FF/128,   MM/128);   // (32, 32)
    const dim3 gFl (TT/128, BB*HH);      // (8, 64)
    const int nLn = MM;

    // ---- self-attention (causal) ----
    kProjH<<<gQKV, blk, GSMEM>>>(gxh, tq1, nullptr, gffh, CC, CC, CC, 3072);
    flash_k<true><<<gFl, blk, FSMEM>>>(gffh, gffh + 1024, gffh + 2048, tmask, gctxh, 3072, 3072);
    kProj<<<gP, blk, GSMEM>>>(gctxh, to1, nullptr, go, CC, CC, CC, CC);
    add_ln<true><<<nLn, blk>>>(x, go, ln1g, ln1b, gx1, gx1h);

    // ---- cross-attention ----
    kProjH<<<gP,  blk, GSMEM>>>(gx1h, tq2, nullptr, gqh, CC, CC, CC, CC);
    kProjH<<<gKV, blk, GSMEM>>>(geh, tk2, nullptr, gffh, CC, CC, CC, 2048);
    flash_k<false><<<gFl, blk, FSMEM>>>(gqh, gffh, gffh + 1024, smask, gctxh, CC, 2048);
    kProj<<<gP, blk, GSMEM>>>(gctxh, to2, nullptr, go, CC, CC, CC, CC);
    add_ln<true><<<nLn, blk>>>(gx1, go, ln2g, ln2b, gx2, gx2h);

    // ---- FFN ----
    kFfn1<<<gF1, blk, GSMEM>>>(gx2h, tf1, bf1, gffh, CC, CC, CC, FF);
    kFfn2<<<gP,  blk, GSMEM>>>(gffh, tf2, bf2, go, FF, FF, FF, CC);
    add_ln<false><<<nLn, blk>>>(gx2, go, ln3g, ln3b, out, nullptr);
}